// round 5
// baseline (speedup 1.0000x reference)
#include <cuda_runtime.h>
#include <cuda_bf16.h>
#include <cstdint>

// ---------------- problem constants ----------------
#define D_MODEL   256
#define N_HEADS   8
#define HEAD_DIM  32
#define N_LEVELS  4
#define N_POINTS  4
#define D_FFN     1024
#define HW        128
#define LQ        (HW * HW)            // 16384
#define LIN       (N_LEVELS * LQ)      // 65536
#define BATCH     2
#define ROWS_Q    (BATCH * LQ)         // 32768
#define ROWS_V    (BATCH * LIN)        // 131072

// ---------------- scratch (device globals; allocation-free rule) ----------
__device__ __align__(256) __nv_bfloat16 sc_value[ROWS_V * D_MODEL]; // 67 MB
__device__ __align__(256) float sc_q    [ROWS_Q * D_MODEL];
__device__ __align__(256) float sc_off  [ROWS_Q * D_MODEL];
__device__ __align__(256) float sc_attn [ROWS_Q * 128];
__device__ __align__(256) float sc_samp [ROWS_Q * D_MODEL];
__device__ __align__(256) float sc_src2 [ROWS_Q * D_MODEL];
__device__ __align__(256) float sc_src  [ROWS_Q * D_MODEL];
__device__ __align__(256) float sc_srct [ROWS_Q * D_MODEL];   // tf32-rounded src
__device__ __align__(256) float sc_ffn  [ROWS_Q * D_FFN];
__device__ __align__(256) float sc_ffn2 [ROWS_Q * D_MODEL];
// tf32-rounded weights
__device__ __align__(256) float sc_wval [D_MODEL * D_MODEL];
__device__ __align__(256) float sc_woff [D_MODEL * 256];
__device__ __align__(256) float sc_wattn[D_MODEL * 128];
__device__ __align__(256) float sc_wout [D_MODEL * D_MODEL];
__device__ __align__(256) float sc_w1   [D_MODEL * D_FFN];
__device__ __align__(256) float sc_w2   [D_FFN * D_MODEL];

// ---------------- helpers --------------------------------------------------
__device__ __forceinline__ uint32_t f2tf32(float f) {
    uint32_t u;
    asm("cvt.rna.tf32.f32 %0, %1;" : "=r"(u) : "f"(f));
    return u;
}
__device__ __forceinline__ float f2tf32f(float f) {
    return __uint_as_float(f2tf32(f));
}

__device__ __forceinline__ void mma_tf32(float c[4], const uint32_t a[4],
                                         const uint32_t b[2]) {
    asm volatile(
        "mma.sync.aligned.m16n8k8.row.col.f32.tf32.tf32.f32 "
        "{%0,%1,%2,%3}, {%4,%5,%6,%7}, {%8,%9}, {%0,%1,%2,%3};"
        : "+f"(c[0]), "+f"(c[1]), "+f"(c[2]), "+f"(c[3])
        : "r"(a[0]), "r"(a[1]), "r"(a[2]), "r"(a[3]), "r"(b[0]), "r"(b[1]));
}

__device__ __forceinline__ void cp_async16(void* smem, const void* gmem) {
    const uint32_t s = (uint32_t)__cvta_generic_to_shared(smem);
    asm volatile("cp.async.ca.shared.global [%0], [%1], 16;\n" :: "r"(s), "l"(gmem));
}
__device__ __forceinline__ void cp_commit() {
    asm volatile("cp.async.commit_group;\n");
}
template <int N>
__device__ __forceinline__ void cp_wait() {
    asm volatile("cp.async.wait_group %0;\n" :: "n"(N));
}

// ---------------- TF32 tensor-core GEMM, BK=32, double-buffered -----------
// C = (A [+A2, rounded]) @ B + bias [, relu].  Inputs pre-rounded to tf32
// (except FUSE_ADD path which rounds inline). A: MxK rm, B: KxN rm (rounded).
// BM=BN=128, BK=32, 256 threads (8 warps 2x4), warp tile 64x32.
// M%128==0, N%128==0, K%32==0.
#define BK     32
#define A_PAD  36    // (4g+t) distinct mod 32 -> conflict-free A frag loads
#define B_PAD  136   // (8t+g) distinct mod 32 -> conflict-free B frag loads

template <bool FUSE_ADD, bool RELU, bool BF16_OUT, bool TF32_OUT>
__global__ __launch_bounds__(256)
void tgemm_kernel(const float* __restrict__ A, const float* __restrict__ A2,
                  const float* __restrict__ B, const float* __restrict__ bias,
                  float* __restrict__ C, __nv_bfloat16* __restrict__ Cb,
                  int M, int N, int K)
{
    __shared__ float As[2][128 * A_PAD];   // [m][k]
    __shared__ float Bs[2][BK * B_PAD];    // [k][n]

    const int tid  = threadIdx.x;
    const int wid  = tid >> 5;
    const int lane = tid & 31;
    const int g    = lane >> 2;
    const int t    = lane & 3;

    const int bm = blockIdx.y * 128;
    const int bn = blockIdx.x * 128;
    const int wm = (wid & 1) * 64;
    const int wn = (wid >> 1) * 32;

    // global-load mapping: A 128x32 floats, B 32x128 floats per stage
    const int la_m = tid >> 1;            // 0..127
    const int la_k = (tid & 1) * 16;      // 0 or 16 (4 float4 each)
    const int lb_k = tid >> 3;            // 0..31
    const int lb_n = (tid & 7) * 16;      // 0..112 (4 float4 each)

    const float* a_ptr  = A + (size_t)(bm + la_m) * K + la_k;
    const float* a2_ptr = FUSE_ADD ? (A2 + (size_t)(bm + la_m) * K + la_k) : nullptr;
    const float* b_ptr  = B + (size_t)lb_k * N + bn + lb_n;

    const int nk = K / BK;

    auto load_tile = [&](int s, int k0) {
        float* as = &As[s][la_m * A_PAD + la_k];
        if (FUSE_ADD) {
            #pragma unroll
            for (int j = 0; j < 4; ++j) {
                float4 v = *(const float4*)(a_ptr + k0 + j * 4);
                const float4 w = *(const float4*)(a2_ptr + k0 + j * 4);
                v.x = f2tf32f(v.x + w.x); v.y = f2tf32f(v.y + w.y);
                v.z = f2tf32f(v.z + w.z); v.w = f2tf32f(v.w + w.w);
                *(float4*)(as + j * 4) = v;
            }
        } else {
            #pragma unroll
            for (int j = 0; j < 4; ++j)
                cp_async16(as + j * 4, a_ptr + k0 + j * 4);
        }
        float* bs = &Bs[s][lb_k * B_PAD + lb_n];
        #pragma unroll
        for (int j = 0; j < 4; ++j)
            cp_async16(bs + j * 4, b_ptr + (size_t)k0 * N + j * 4);
    };

    float acc[4][4][4] = {};  // [mt][nt][reg]

    load_tile(0, 0);
    cp_commit();

    for (int i = 0; i < nk; ++i) {
        if (i + 1 < nk) load_tile((i + 1) & 1, (i + 1) * BK);
        cp_commit();
        cp_wait<1>();           // tile i resident
        __syncthreads();

        const int s = i & 1;
        #pragma unroll
        for (int ks = 0; ks < BK; ks += 8) {
            uint32_t af[4][4];
            #pragma unroll
            for (int mt = 0; mt < 4; ++mt) {
                const float* p = &As[s][(wm + mt * 16 + g) * A_PAD + ks + t];
                af[mt][0] = __float_as_uint(p[0]);
                af[mt][1] = __float_as_uint(p[8 * A_PAD]);
                af[mt][2] = __float_as_uint(p[4]);
                af[mt][3] = __float_as_uint(p[8 * A_PAD + 4]);
            }
            uint32_t bf[4][2];
            #pragma unroll
            for (int nt = 0; nt < 4; ++nt) {
                const float* p = &Bs[s][(ks + t) * B_PAD + wn + nt * 8 + g];
                bf[nt][0] = __float_as_uint(p[0]);
                bf[nt][1] = __float_as_uint(p[4 * B_PAD]);
            }
            #pragma unroll
            for (int mt = 0; mt < 4; ++mt)
                #pragma unroll
                for (int nt = 0; nt < 4; ++nt)
                    mma_tf32(acc[mt][nt], af[mt], bf[nt]);
        }
        __syncthreads();
    }

    // ---- epilogue ----
    #pragma unroll
    for (int nt = 0; nt < 4; ++nt) {
        const int n = bn + wn + nt * 8 + t * 2;
        const float bx = bias[n], by = bias[n + 1];
        #pragma unroll
        for (int mt = 0; mt < 4; ++mt) {
            const int m = bm + wm + mt * 16 + g;
            float2 v0 = { acc[mt][nt][0] + bx, acc[mt][nt][1] + by };
            float2 v1 = { acc[mt][nt][2] + bx, acc[mt][nt][3] + by };
            if (RELU) {
                v0.x = fmaxf(v0.x, 0.f); v0.y = fmaxf(v0.y, 0.f);
                v1.x = fmaxf(v1.x, 0.f); v1.y = fmaxf(v1.y, 0.f);
            }
            if (TF32_OUT) {
                v0.x = f2tf32f(v0.x); v0.y = f2tf32f(v0.y);
                v1.x = f2tf32f(v1.x); v1.y = f2tf32f(v1.y);
            }
            if (BF16_OUT) {
                *(__nv_bfloat162*)&Cb[(size_t)m * N + n] =
                    __nv_bfloat162(__float2bfloat16_rn(v0.x), __float2bfloat16_rn(v0.y));
                *(__nv_bfloat162*)&Cb[(size_t)(m + 8) * N + n] =
                    __nv_bfloat162(__float2bfloat16_rn(v1.x), __float2bfloat16_rn(v1.y));
            } else {
                *(float2*)&C[(size_t)m * N + n]       = v0;
                *(float2*)&C[(size_t)(m + 8) * N + n] = v1;
            }
        }
    }
}

// ---------------- weight pre-round to tf32 ---------------------------------
__global__ __launch_bounds__(256)
void round_kernel(const float* __restrict__ src, float* __restrict__ dst)
{
    const size_t i = (size_t)blockIdx.x * blockDim.x + threadIdx.x;
    float4 v = ((const float4*)src)[i];
    v.x = f2tf32f(v.x); v.y = f2tf32f(v.y);
    v.z = f2tf32f(v.z); v.w = f2tf32f(v.w);
    ((float4*)dst)[i] = v;
}

// ---------------- q = tf32(cur_src + pos[:, -1]) ---------------------------
__global__ __launch_bounds__(256)
void add_q_kernel(const float* __restrict__ cur, const float* __restrict__ pos,
                  float* __restrict__ q)
{
    const size_t i = (size_t)blockIdx.x * blockDim.x + threadIdx.x;
    const size_t per_batch = (size_t)LQ * D_MODEL / 4;
    const size_t n = i / per_batch;
    const size_t r = i - n * per_batch;
    float4 a = ((const float4*)cur)[i];
    const float4 b = ((const float4*)pos)[n * 4 * per_batch + 3 * per_batch + r];
    a.x = f2tf32f(a.x + b.x); a.y = f2tf32f(a.y + b.y);
    a.z = f2tf32f(a.z + b.z); a.w = f2tf32f(a.w + b.w);
    ((float4*)q)[i] = a;
}

// ---------------- fused softmax + deformable bilinear sampling ------------
__global__ __launch_bounds__(256)
void sample_kernel(const float* __restrict__ off, const float* __restrict__ attn,
                   const float* __restrict__ ref,
                   const __nv_bfloat16* __restrict__ value,
                   float* __restrict__ out)
{
    const int gw   = blockIdx.x * 8 + (threadIdx.x >> 5);
    const int lane = threadIdx.x & 31;
    const int h = gw & 7;
    const int q = (gw >> 3) & (LQ - 1);
    const int n = gw >> 17;

    const size_t row = (size_t)n * LQ + q;
    const float* ap = attn + row * 128 + h * 16;

    float logits[16];
    float mx = -1e30f;
    #pragma unroll
    for (int i = 0; i < 16; ++i) { logits[i] = ap[i]; mx = fmaxf(mx, logits[i]); }
    float ssum = 0.f;
    #pragma unroll
    for (int i = 0; i < 16; ++i) { logits[i] = __expf(logits[i] - mx); ssum += logits[i]; }
    const float inv = 1.f / ssum;

    const float* op = off + row * 256 + h * 32;
    const float* rp = ref + row * 8;
    const __nv_bfloat16* vb = value + (size_t)n * LIN * 256 + h * 32 + lane;

    float acc = 0.f;
    #pragma unroll
    for (int l = 0; l < N_LEVELS; ++l) {
        const float rx = rp[l * 2 + 0];
        const float ry = rp[l * 2 + 1];
        const int start = l * LQ;
        #pragma unroll
        for (int p = 0; p < N_POINTS; ++p) {
            const float x = fmaf(rx, 128.f, op[l * 8 + p * 2 + 0] - 0.5f);
            const float y = fmaf(ry, 128.f, op[l * 8 + p * 2 + 1] - 0.5f);
            const float x0f = floorf(x), y0f = floorf(y);
            const float wx = x - x0f, wy = y - y0f;
            const int x0 = (int)x0f, y0 = (int)y0f;
            const float aw = logits[l * 4 + p] * inv;

            const bool vx0 = (x0 >= 0) & (x0 < HW);
            const bool vx1 = (x0 + 1 >= 0) & (x0 + 1 < HW);
            const bool vy0 = (y0 >= 0) & (y0 < HW);
            const bool vy1 = (y0 + 1 >= 0) & (y0 + 1 < HW);

            if (vy0) {
                const size_t base = (size_t)(start + y0 * HW) * 256;
                if (vx0) acc = fmaf(__bfloat162float(vb[base + (size_t)x0 * 256]),
                                    (1.f - wx) * (1.f - wy) * aw, acc);
                if (vx1) acc = fmaf(__bfloat162float(vb[base + (size_t)(x0 + 1) * 256]),
                                    wx * (1.f - wy) * aw, acc);
            }
            if (vy1) {
                const size_t base = (size_t)(start + (y0 + 1) * HW) * 256;
                if (vx0) acc = fmaf(__bfloat162float(vb[base + (size_t)x0 * 256]),
                                    (1.f - wx) * wy * aw, acc);
                if (vx1) acc = fmaf(__bfloat162float(vb[base + (size_t)(x0 + 1) * 256]),
                                    wx * wy * aw, acc);
            }
        }
    }
    out[row * 256 + h * 32 + lane] = f2tf32f(acc);   // feeds out-proj GEMM only
}

// ---------------- residual add + layernorm (+ optional tf32 twin) ---------
__global__ __launch_bounds__(256)
void add_ln_kernel(const float* __restrict__ a, const float* __restrict__ b,
                   const float* __restrict__ gamma, const float* __restrict__ beta,
                   float* __restrict__ out, float* __restrict__ out_t)
{
    const int row = blockIdx.x;
    const int t = threadIdx.x;
    const size_t idx = (size_t)row * 256 + t;
    const float v = a[idx] + b[idx];

    __shared__ float red[8];
    float s = v;
    #pragma unroll
    for (int o = 16; o; o >>= 1) s += __shfl_xor_sync(0xffffffffu, s, o);
    if ((t & 31) == 0) red[t >> 5] = s;
    __syncthreads();
    float mean = 0.f;
    #pragma unroll
    for (int i = 0; i < 8; ++i) mean += red[i];
    mean *= (1.f / 256.f);
    __syncthreads();

    const float d = v - mean;
    float s2 = d * d;
    #pragma unroll
    for (int o = 16; o; o >>= 1) s2 += __shfl_xor_sync(0xffffffffu, s2, o);
    if ((t & 31) == 0) red[t >> 5] = s2;
    __syncthreads();
    float var = 0.f;
    #pragma unroll
    for (int i = 0; i < 8; ++i) var += red[i];
    var *= (1.f / 256.f);

    const float r = d * rsqrtf(var + 1e-5f) * gamma[t] + beta[t];
    out[idx] = r;
    if (out_t) out_t[idx] = f2tf32f(r);
}

// ---------------- launch ---------------------------------------------------
extern "C" void kernel_launch(void* const* d_in, const int* in_sizes, int n_in,
                              void* d_out, int out_size)
{
    (void)in_sizes; (void)n_in; (void)out_size;
    const float* cur_src = (const float*)d_in[0];
    const float* src_all = (const float*)d_in[1];
    const float* pos     = (const float*)d_in[2];
    const float* refpts  = (const float*)d_in[3];
    const float* W_off   = (const float*)d_in[6];
    const float* b_off   = (const float*)d_in[7];
    const float* W_attn  = (const float*)d_in[8];
    const float* b_attn  = (const float*)d_in[9];
    const float* W_val   = (const float*)d_in[10];
    const float* b_val   = (const float*)d_in[11];
    const float* W_out   = (const float*)d_in[12];
    const float* b_out   = (const float*)d_in[13];
    const float* gamma1  = (const float*)d_in[14];
    const float* beta1   = (const float*)d_in[15];
    const float* W1      = (const float*)d_in[16];
    const float* b1      = (const float*)d_in[17];
    const float* W2      = (const float*)d_in[18];
    const float* b2      = (const float*)d_in[19];
    const float* gamma2  = (const float*)d_in[20];
    const float* beta2   = (const float*)d_in[21];
    float* out = (float*)d_out;

    float *g_q, *g_off, *g_attn, *g_samp, *g_src2, *g_src, *g_srct, *g_ffn, *g_ffn2;
    float *g_wval, *g_woff, *g_wattn, *g_wout, *g_w1, *g_w2;
    __nv_bfloat16* g_value;
    cudaGetSymbolAddress((void**)&g_value, sc_value);
    cudaGetSymbolAddress((void**)&g_q,     sc_q);
    cudaGetSymbolAddress((void**)&g_off,   sc_off);
    cudaGetSymbolAddress((void**)&g_attn,  sc_attn);
    cudaGetSymbolAddress((void**)&g_samp,  sc_samp);
    cudaGetSymbolAddress((void**)&g_src2,  sc_src2);
    cudaGetSymbolAddress((void**)&g_src,   sc_src);
    cudaGetSymbolAddress((void**)&g_srct,  sc_srct);
    cudaGetSymbolAddress((void**)&g_ffn,   sc_ffn);
    cudaGetSymbolAddress((void**)&g_ffn2,  sc_ffn2);
    cudaGetSymbolAddress((void**)&g_wval,  sc_wval);
    cudaGetSymbolAddress((void**)&g_woff,  sc_woff);
    cudaGetSymbolAddress((void**)&g_wattn, sc_wattn);
    cudaGetSymbolAddress((void**)&g_wout,  sc_wout);
    cudaGetSymbolAddress((void**)&g_w1,    sc_w1);
    cudaGetSymbolAddress((void**)&g_w2,    sc_w2);

    // 0. pre-round weights to tf32 (tiny)
    round_kernel<<<D_MODEL * D_MODEL / 1024, 256>>>(W_val,  g_wval);
    round_kernel<<<D_MODEL * 256     / 1024, 256>>>(W_off,  g_woff);
    round_kernel<<<D_MODEL * 128     / 1024, 256>>>(W_attn, g_wattn);
    round_kernel<<<D_MODEL * D_MODEL / 1024, 256>>>(W_out,  g_wout);
    round_kernel<<<D_MODEL * D_FFN   / 1024, 256>>>(W1,     g_w1);
    round_kernel<<<D_FFN * D_MODEL   / 1024, 256>>>(W2,     g_w2);

    // 1. q = tf32(cur_src + pos[:, -1])
    add_q_kernel<<<(ROWS_Q * D_MODEL / 4) / 256, 256>>>(cur_src, pos, g_q);

    // 2. value = (src_all + pos) @ W_val + b_val -> bf16 (M=131072,N=256,K=256)
    tgemm_kernel<true, false, true, false><<<dim3(2, ROWS_V / 128), 256>>>(
        src_all, pos, g_wval, b_val, nullptr, g_value, ROWS_V, D_MODEL, D_MODEL);

    // 3. off = q @ W_off + b_off                         (M=32768,N=256,K=256)
    tgemm_kernel<false, false, false, false><<<dim3(2, ROWS_Q / 128), 256>>>(
        g_q, nullptr, g_woff, b_off, g_off, nullptr, ROWS_Q, 256, D_MODEL);

    // 4. attn_logits = q @ W_attn + b_attn               (M=32768,N=128,K=256)
    tgemm_kernel<false, false, false, false><<<dim3(1, ROWS_Q / 128), 256>>>(
        g_q, nullptr, g_wattn, b_attn, g_attn, nullptr, ROWS_Q, 128, D_MODEL);

    // 5. fused softmax + deformable bilinear sampling (tf32-rounded out)
    sample_kernel<<<(BATCH * LQ * N_HEADS) / 8, 256>>>(
        g_off, g_attn, refpts, g_value, g_samp);

    // 6. src2 = samp @ W_out + b_out                     (M=32768,N=256,K=256)
    tgemm_kernel<false, false, false, false><<<dim3(2, ROWS_Q / 128), 256>>>(
        g_samp, nullptr, g_wout, b_out, g_src2, nullptr, ROWS_Q, D_MODEL, D_MODEL);

    // 7. src = LN(cur_src + src2); also tf32 twin for FFN1
    add_ln_kernel<<<ROWS_Q, 256>>>(cur_src, g_src2, gamma1, beta1, g_src, g_srct);

    // 8. ffn_h = tf32(relu(src @ W1 + b1))               (M=32768,N=1024,K=256)
    tgemm_kernel<false, true, false, true><<<dim3(D_FFN / 128, ROWS_Q / 128), 256>>>(
        g_srct, nullptr, g_w1, b1, g_ffn, nullptr, ROWS_Q, D_FFN, D_MODEL);

    // 9. ffn2 = ffn_h @ W2 + b2                          (M=32768,N=256,K=1024)
    tgemm_kernel<false, false, false, false><<<dim3(2, ROWS_Q / 128), 256>>>(
        g_ffn, nullptr, g_w2, b2, g_ffn2, nullptr, ROWS_Q, D_MODEL, D_FFN);

    // 10. out = LN(src + ffn2)
    add_ln_kernel<<<ROWS_Q, 256>>>(g_src, g_ffn2, gamma2, beta2, out, nullptr);
}

// round 7
// speedup vs baseline: 1.2975x; 1.2975x over previous
#include <cuda_runtime.h>
#include <cuda_bf16.h>
#include <cstdint>

// ---------------- problem constants ----------------
#define D_MODEL   256
#define N_HEADS   8
#define HEAD_DIM  32
#define N_LEVELS  4
#define N_POINTS  4
#define D_FFN     1024
#define HW        128
#define LQ        (HW * HW)            // 16384
#define LIN       (N_LEVELS * LQ)      // 65536
#define BATCH     2
#define ROWS_Q    (BATCH * LQ)         // 32768
#define ROWS_V    (BATCH * LIN)        // 131072

// ---------------- scratch (device globals) ---------------------------------
__device__ __align__(256) __nv_bfloat16 sc_value[ROWS_V * D_MODEL]; // 67 MB
__device__ __align__(256) float sc_q    [ROWS_Q * D_MODEL];
__device__ __align__(256) float sc_off  [ROWS_Q * D_MODEL];
__device__ __align__(256) float sc_attn [ROWS_Q * 128];
__device__ __align__(256) float sc_samp [ROWS_Q * D_MODEL];
__device__ __align__(256) float sc_src2 [ROWS_Q * D_MODEL];
__device__ __align__(256) float sc_src  [ROWS_Q * D_MODEL];
__device__ __align__(256) float sc_ffn  [ROWS_Q * D_FFN];
__device__ __align__(256) float sc_ffn2 [ROWS_Q * D_MODEL];
// bf16 transposed weights: Wt[n][k]
__device__ __align__(256) __nv_bfloat16 sc_wvalT[D_MODEL * D_MODEL];
__device__ __align__(256) __nv_bfloat16 sc_woffT[256 * D_MODEL];
__device__ __align__(256) __nv_bfloat16 sc_woutT[D_MODEL * D_MODEL];

// ---------------- helpers --------------------------------------------------
__device__ __forceinline__ uint32_t f2tf32(float f) {
    uint32_t u;
    asm("cvt.rna.tf32.f32 %0, %1;" : "=r"(u) : "f"(f));
    return u;
}
__device__ __forceinline__ void mma_tf32(float c[4], const uint32_t a[4],
                                         const uint32_t b[2]) {
    asm volatile(
        "mma.sync.aligned.m16n8k8.row.col.f32.tf32.tf32.f32 "
        "{%0,%1,%2,%3}, {%4,%5,%6,%7}, {%8,%9}, {%0,%1,%2,%3};"
        : "+f"(c[0]), "+f"(c[1]), "+f"(c[2]), "+f"(c[3])
        : "r"(a[0]), "r"(a[1]), "r"(a[2]), "r"(a[3]), "r"(b[0]), "r"(b[1]));
}
__device__ __forceinline__ void mma_bf16(float c[4], const uint32_t a[4],
                                         const uint32_t b[2]) {
    asm volatile(
        "mma.sync.aligned.m16n8k16.row.col.f32.bf16.bf16.f32 "
        "{%0,%1,%2,%3}, {%4,%5,%6,%7}, {%8,%9}, {%0,%1,%2,%3};"
        : "+f"(c[0]), "+f"(c[1]), "+f"(c[2]), "+f"(c[3])
        : "r"(a[0]), "r"(a[1]), "r"(a[2]), "r"(a[3]), "r"(b[0]), "r"(b[1]));
}
__device__ __forceinline__ void cp_async16(void* smem, const void* gmem) {
    const uint32_t s = (uint32_t)__cvta_generic_to_shared(smem);
    asm volatile("cp.async.ca.shared.global [%0], [%1], 16;\n" :: "r"(s), "l"(gmem));
}
__device__ __forceinline__ void cp_commit() {
    asm volatile("cp.async.commit_group;\n");
}
template <int N>
__device__ __forceinline__ void cp_wait() {
    asm volatile("cp.async.wait_group %0;\n" :: "n"(N));
}
__device__ __forceinline__ uint32_t packbf(float x, float y) {
    __nv_bfloat162 p = __floats2bfloat162_rn(x, y);
    return *(uint32_t*)&p;
}

// ================= bf16 tensor-core GEMM ===================================
// C = bf16(A [+A2]) @ Bt^T + bias [, relu].  A: [M,K] fp32 rm, Bt: [N,K] bf16 rm.
// BM=BN=128, BK=32, 256 threads (8 warps 2x4), warp tile 64x32, m16n8k16.
// M%128==0, N%128==0, K%32==0, K>=64.
#define BPAD 40   // bf16 row stride: conflict-free frag loads (20g+t mod 32 distinct)

template <bool FUSE_ADD, bool RELU, bool BF16_OUT>
__global__ __launch_bounds__(256)
void bgemm_kernel(const float* __restrict__ A, const float* __restrict__ A2,
                  const __nv_bfloat16* __restrict__ Bt, const float* __restrict__ bias,
                  float* __restrict__ C, __nv_bfloat16* __restrict__ Cb,
                  int M, int N, int K)
{
    __shared__ __align__(16) __nv_bfloat16 As[2][128 * BPAD];
    __shared__ __align__(16) __nv_bfloat16 Bs[2][128 * BPAD];

    const int tid  = threadIdx.x;
    const int wid  = tid >> 5;
    const int lane = tid & 31;
    const int g    = lane >> 2;
    const int t    = lane & 3;

    const int bm = blockIdx.y * 128;
    const int bn = blockIdx.x * 128;
    const int wm = (wid & 1) * 64;
    const int wn = (wid >> 1) * 32;

    // A load mapping: row r=tid>>1 (0..127), cols c0..c0+15, c0=(tid&1)*16
    const int la_r = tid >> 1;
    const int la_c = (tid & 1) * 16;
    const float* a_ptr  = A + (size_t)(bm + la_r) * K + la_c;
    const float* a2_ptr = FUSE_ADD ? (A2 + (size_t)(bm + la_r) * K + la_c) : nullptr;

    const int nk = K / 32;

    auto ldgA = [&](int i, uint32_t v[8]) {
        const int k0 = i * 32;
        #pragma unroll
        for (int j = 0; j < 4; ++j) {
            float4 a = *(const float4*)(a_ptr + k0 + j * 4);
            if (FUSE_ADD) {
                const float4 b = *(const float4*)(a2_ptr + k0 + j * 4);
                a.x += b.x; a.y += b.y; a.z += b.z; a.w += b.w;
            }
            v[2 * j]     = packbf(a.x, a.y);
            v[2 * j + 1] = packbf(a.z, a.w);
        }
    };
    auto stsA = [&](int s, const uint32_t v[8]) {
        uint32_t* p = (uint32_t*)&As[s][la_r * BPAD + la_c];
        *(uint4*)p       = make_uint4(v[0], v[1], v[2], v[3]);
        *(uint4*)(p + 4) = make_uint4(v[4], v[5], v[6], v[7]);
    };
    auto cpB = [&](int s, int i) {
        const int k0 = i * 32;
        #pragma unroll
        for (int j = 0; j < 2; ++j) {
            const int ch = j * 256 + tid;           // 512 chunks of 16B
            const int r  = ch >> 2;
            const int cc = (ch & 3) * 8;
            cp_async16(&Bs[s][r * BPAD + cc], Bt + (size_t)(bn + r) * K + k0 + cc);
        }
    };

    float acc[4][4][4] = {};
    uint32_t rA[8];

    ldgA(0, rA);
    stsA(0, rA);
    cpB(0, 0);
    cp_commit();
    ldgA(1, rA);

    for (int i = 0; i < nk; ++i) {
        cp_wait<0>();
        __syncthreads();
        if (i + 1 < nk) {
            stsA((i + 1) & 1, rA);
            cpB((i + 1) & 1, i + 1);
            cp_commit();
        }
        if (i + 2 < nk) ldgA(i + 2, rA);

        const int s = i & 1;
        #pragma unroll
        for (int ks = 0; ks < 32; ks += 16) {
            uint32_t af[4][4];
            #pragma unroll
            for (int mt = 0; mt < 4; ++mt) {
                const __nv_bfloat16* p = &As[s][(wm + mt * 16 + g) * BPAD + ks + 2 * t];
                af[mt][0] = *(const uint32_t*)p;
                af[mt][1] = *(const uint32_t*)(p + 8 * BPAD);
                af[mt][2] = *(const uint32_t*)(p + 8);
                af[mt][3] = *(const uint32_t*)(p + 8 * BPAD + 8);
            }
            uint32_t bf[4][2];
            #pragma unroll
            for (int nt = 0; nt < 4; ++nt) {
                const __nv_bfloat16* p = &Bs[s][(wn + nt * 8 + g) * BPAD + ks + 2 * t];
                bf[nt][0] = *(const uint32_t*)p;
                bf[nt][1] = *(const uint32_t*)(p + 8);
            }
            #pragma unroll
            for (int mt = 0; mt < 4; ++mt)
                #pragma unroll
                for (int nt = 0; nt < 4; ++nt)
                    mma_bf16(acc[mt][nt], af[mt], bf[nt]);
        }
        __syncthreads();
    }

    // ---- epilogue ----
    #pragma unroll
    for (int nt = 0; nt < 4; ++nt) {
        const int n = bn + wn + nt * 8 + t * 2;
        const float bx = bias[n], by = bias[n + 1];
        #pragma unroll
        for (int mt = 0; mt < 4; ++mt) {
            const int m = bm + wm + mt * 16 + g;
            float2 v0 = { acc[mt][nt][0] + bx, acc[mt][nt][1] + by };
            float2 v1 = { acc[mt][nt][2] + bx, acc[mt][nt][3] + by };
            if (RELU) {
                v0.x = fmaxf(v0.x, 0.f); v0.y = fmaxf(v0.y, 0.f);
                v1.x = fmaxf(v1.x, 0.f); v1.y = fmaxf(v1.y, 0.f);
            }
            if (BF16_OUT) {
                *(uint32_t*)&Cb[(size_t)m * N + n]       = packbf(v0.x, v0.y);
                *(uint32_t*)&Cb[(size_t)(m + 8) * N + n] = packbf(v1.x, v1.y);
            } else {
                *(float2*)&C[(size_t)m * N + n]       = v0;
                *(float2*)&C[(size_t)(m + 8) * N + n] = v1;
            }
        }
    }
}

// ================= TF32 GEMM (R4 config: BK=16, 3-stage) ===================
#define TBK    16
#define A_PAD  20
#define B_PAD  136
#define STAGES 3

template <bool RELU>
__global__ __launch_bounds__(256)
void tgemm_kernel(const float* __restrict__ A, const float* __restrict__ B,
                  const float* __restrict__ bias, float* __restrict__ C,
                  int M, int N, int K)
{
    __shared__ float As[STAGES][128 * A_PAD];
    __shared__ float Bs[STAGES][TBK * B_PAD];

    const int tid  = threadIdx.x;
    const int wid  = tid >> 5;
    const int lane = tid & 31;
    const int g    = lane >> 2;
    const int t    = lane & 3;

    const int bm = blockIdx.y * 128;
    const int bn = blockIdx.x * 128;
    const int wm = (wid & 1) * 64;
    const int wn = (wid >> 1) * 32;

    const int la_m = tid >> 1;
    const int la_k = (tid & 1) * 8;
    const int lb_k = tid >> 4;
    const int lb_n = (tid & 15) * 8;

    const float* a_ptr = A + (size_t)(bm + la_m) * K + la_k;
    const float* b_ptr = B + (size_t)lb_k * N + bn + lb_n;

    const int nk = K / TBK;

    auto load_tile = [&](int s, int k0) {
        float* as = &As[s][la_m * A_PAD + la_k];
        cp_async16(as,     a_ptr + k0);
        cp_async16(as + 4, a_ptr + k0 + 4);
        float* bs = &Bs[s][lb_k * B_PAD + lb_n];
        cp_async16(bs,     b_ptr + (size_t)k0 * N);
        cp_async16(bs + 4, b_ptr + (size_t)k0 * N + 4);
    };

    float acc[4][4][4] = {};

    load_tile(0, 0);        cp_commit();
    load_tile(1, TBK);      cp_commit();

    for (int i = 0; i < nk; ++i) {
        cp_wait<STAGES - 2>();
        __syncthreads();

        const int nxt = i + STAGES - 1;
        if (nxt < nk) load_tile(nxt % STAGES, nxt * TBK);
        cp_commit();

        const int s = i % STAGES;
        #pragma unroll
        for (int ks = 0; ks < TBK; ks += 8) {
            uint32_t af[4][4];
            #pragma unroll
            for (int mt = 0; mt < 4; ++mt) {
                const float* p = &As[s][(wm + mt * 16 + g) * A_PAD + ks + t];
                af[mt][0] = f2tf32(p[0]);
                af[mt][1] = f2tf32(p[8 * A_PAD]);
                af[mt][2] = f2tf32(p[4]);
                af[mt][3] = f2tf32(p[8 * A_PAD + 4]);
            }
            uint32_t bf[4][2];
            #pragma unroll
            for (int nt = 0; nt < 4; ++nt) {
                const float* p = &Bs[s][(ks + t) * B_PAD + wn + nt * 8 + g];
                bf[nt][0] = f2tf32(p[0]);
                bf[nt][1] = f2tf32(p[4 * B_PAD]);
            }
            #pragma unroll
            for (int mt = 0; mt < 4; ++mt)
                #pragma unroll
                for (int nt = 0; nt < 4; ++nt)
                    mma_tf32(acc[mt][nt], af[mt], bf[nt]);
        }
        __syncthreads();
    }

    #pragma unroll
    for (int nt = 0; nt < 4; ++nt) {
        const int n = bn + wn + nt * 8 + t * 2;
        const float bx = bias[n], by = bias[n + 1];
        #pragma unroll
        for (int mt = 0; mt < 4; ++mt) {
            const int m = bm + wm + mt * 16 + g;
            float2 v0 = { acc[mt][nt][0] + bx, acc[mt][nt][1] + by };
            float2 v1 = { acc[mt][nt][2] + bx, acc[mt][nt][3] + by };
            if (RELU) {
                v0.x = fmaxf(v0.x, 0.f); v0.y = fmaxf(v0.y, 0.f);
                v1.x = fmaxf(v1.x, 0.f); v1.y = fmaxf(v1.y, 0.f);
            }
            *(float2*)&C[(size_t)m * N + n]       = v0;
            *(float2*)&C[(size_t)(m + 8) * N + n] = v1;
        }
    }
}

// ---------------- weight transpose fp32[K][N] -> bf16[N][K] -----------------
__global__ __launch_bounds__(256)
void transpose_bf16_kernel(const float* __restrict__ W, __nv_bfloat16* __restrict__ Wt,
                           int K, int N)
{
    __shared__ float t[32][33];
    const int bx = blockIdx.x * 32;   // n
    const int by = blockIdx.y * 32;   // k
    const int x = threadIdx.x, y = threadIdx.y;   // (32, 8)
    #pragma unroll
    for (int j = 0; j < 32; j += 8)
        t[y + j][x] = W[(size_t)(by + y + j) * N + bx + x];
    __syncthreads();
    #pragma unroll
    for (int j = 0; j < 32; j += 8)
        Wt[(size_t)(bx + y + j) * K + by + x] = __float2bfloat16_rn(t[x][y + j]);
}

// ---------------- q = cur_src + pos[:, -1] ----------------------------------
__global__ __launch_bounds__(256)
void add_q_kernel(const float* __restrict__ cur, const float* __restrict__ pos,
                  float* __restrict__ q)
{
    const size_t i = (size_t)blockIdx.x * blockDim.x + threadIdx.x;
    const size_t per_batch = (size_t)LQ * D_MODEL / 4;
    const size_t n = i / per_batch;
    const size_t r = i - n * per_batch;
    float4 a = ((const float4*)cur)[i];
    const float4 b = ((const float4*)pos)[n * 4 * per_batch + 3 * per_batch + r];
    a.x += b.x; a.y += b.y; a.z += b.z; a.w += b.w;
    ((float4*)q)[i] = a;
}

// ---------------- fused softmax + deformable bilinear sampling --------------
// Half-warp per (n, q, h): 16 lanes x 2 channels (bf162 gathers).
__global__ __launch_bounds__(256)
void sample_kernel(const float* __restrict__ off, const float* __restrict__ attn,
                   const float* __restrict__ ref,
                   const __nv_bfloat16* __restrict__ value,
                   float* __restrict__ out)
{
    const int tw   = blockIdx.x * 16 + (threadIdx.x >> 4);   // half-warp task id
    const int l16  = threadIdx.x & 15;
    const int h = tw & 7;
    const int q = (tw >> 3) & (LQ - 1);
    const int n = tw >> 17;

    const size_t row = (size_t)n * LQ + q;
    const float* ap = attn + row * 128 + h * 16;

    float logits[16];
    float mx = -1e30f;
    #pragma unroll
    for (int i = 0; i < 16; ++i) { logits[i] = ap[i]; mx = fmaxf(mx, logits[i]); }
    float ssum = 0.f;
    #pragma unroll
    for (int i = 0; i < 16; ++i) { logits[i] = __expf(logits[i] - mx); ssum += logits[i]; }
    const float inv = 1.f / ssum;

    const float* op = off + row * 256 + h * 32;
    const float* rp = ref + row * 8;
    const __nv_bfloat162* vb =
        (const __nv_bfloat162*)value + (size_t)n * LIN * 128 + h * 16 + l16;

    float2 acc = {0.f, 0.f};
    #pragma unroll
    for (int l = 0; l < N_LEVELS; ++l) {
        const float rx = rp[l * 2 + 0];
        const float ry = rp[l * 2 + 1];
        const int start = l * LQ;
        #pragma unroll
        for (int p = 0; p < N_POINTS; ++p) {
            const float x = fmaf(rx, 128.f, op[l * 8 + p * 2 + 0] - 0.5f);
            const float y = fmaf(ry, 128.f, op[l * 8 + p * 2 + 1] - 0.5f);
            const float x0f = floorf(x), y0f = floorf(y);
            const float wx = x - x0f, wy = y - y0f;
            const int x0 = (int)x0f, y0 = (int)y0f;
            const float aw = logits[l * 4 + p] * inv;

            const bool vx0 = (x0 >= 0) & (x0 < HW);
            const bool vx1 = (x0 + 1 >= 0) & (x0 + 1 < HW);
            const bool vy0 = (y0 >= 0) & (y0 < HW);
            const bool vy1 = (y0 + 1 >= 0) & (y0 + 1 < HW);

            if (vy0) {
                const size_t base = (size_t)(start + y0 * HW) * 128;
                if (vx0) {
                    const float2 f = __bfloat1622float2(vb[base + (size_t)x0 * 128]);
                    const float w = (1.f - wx) * (1.f - wy) * aw;
                    acc.x = fmaf(f.x, w, acc.x); acc.y = fmaf(f.y, w, acc.y);
                }
                if (vx1) {
                    const float2 f = __bfloat1622float2(vb[base + (size_t)(x0 + 1) * 128]);
                    const float w = wx * (1.f - wy) * aw;
                    acc.x = fmaf(f.x, w, acc.x); acc.y = fmaf(f.y, w, acc.y);
                }
            }
            if (vy1) {
                const size_t base = (size_t)(start + (y0 + 1) * HW) * 128;
                if (vx0) {
                    const float2 f = __bfloat1622float2(vb[base + (size_t)x0 * 128]);
                    const float w = (1.f - wx) * wy * aw;
                    acc.x = fmaf(f.x, w, acc.x); acc.y = fmaf(f.y, w, acc.y);
                }
                if (vx1) {
                    const float2 f = __bfloat1622float2(vb[base + (size_t)(x0 + 1) * 128]);
                    const float w = wx * wy * aw;
                    acc.x = fmaf(f.x, w, acc.x); acc.y = fmaf(f.y, w, acc.y);
                }
            }
        }
    }
    *(float2*)&out[row * 256 + h * 32 + l16 * 2] = acc;
}

// ---------------- residual add + layernorm ----------------------------------
__global__ __launch_bounds__(256)
void add_ln_kernel(const float* __restrict__ a, const float* __restrict__ b,
                   const float* __restrict__ gamma, const float* __restrict__ beta,
                   float* __restrict__ out)
{
    const int row = blockIdx.x;
    const int t = threadIdx.x;
    const size_t idx = (size_t)row * 256 + t;
    const float v = a[idx] + b[idx];

    __shared__ float red[8];
    float s = v;
    #pragma unroll
    for (int o = 16; o; o >>= 1) s += __shfl_xor_sync(0xffffffffu, s, o);
    if ((t & 31) == 0) red[t >> 5] = s;
    __syncthreads();
    float mean = 0.f;
    #pragma unroll
    for (int i = 0; i < 8; ++i) mean += red[i];
    mean *= (1.f / 256.f);
    __syncthreads();

    const float d = v - mean;
    float s2 = d * d;
    #pragma unroll
    for (int o = 16; o; o >>= 1) s2 += __shfl_xor_sync(0xffffffffu, s2, o);
    if ((t & 31) == 0) red[t >> 5] = s2;
    __syncthreads();
    float var = 0.f;
    #pragma unroll
    for (int i = 0; i < 8; ++i) var += red[i];
    var *= (1.f / 256.f);

    out[idx] = d * rsqrtf(var + 1e-5f) * gamma[t] + beta[t];
}

// ---------------- launch -----------------------------------------------------
extern "C" void kernel_launch(void* const* d_in, const int* in_sizes, int n_in,
                              void* d_out, int out_size)
{
    (void)in_sizes; (void)n_in; (void)out_size;
    const float* cur_src = (const float*)d_in[0];
    const float* src_all = (const float*)d_in[1];
    const float* pos     = (const float*)d_in[2];
    const float* refpts  = (const float*)d_in[3];
    const float* W_off   = (const float*)d_in[6];
    const float* b_off   = (const float*)d_in[7];
    const float* W_attn  = (const float*)d_in[8];
    const float* b_attn  = (const float*)d_in[9];
    const float* W_val   = (const float*)d_in[10];
    const float* b_val   = (const float*)d_in[11];
    const float* W_out   = (const float*)d_in[12];
    const float* b_out   = (const float*)d_in[13];
    const float* gamma1  = (const float*)d_in[14];
    const float* beta1   = (const float*)d_in[15];
    const float* W1      = (const float*)d_in[16];
    const float* b1      = (const float*)d_in[17];
    const float* W2      = (const float*)d_in[18];
    const float* b2      = (const float*)d_in[19];
    const float* gamma2  = (const float*)d_in[20];
    const float* beta2   = (const float*)d_in[21];
    float* out = (float*)d_out;

    float *g_q, *g_off, *g_attn, *g_samp, *g_src2, *g_src, *g_ffn, *g_ffn2;
    __nv_bfloat16 *g_value, *g_wvalT, *g_woffT, *g_woutT;
    cudaGetSymbolAddress((void**)&g_value, sc_value);
    cudaGetSymbolAddress((void**)&g_q,     sc_q);
    cudaGetSymbolAddress((void**)&g_off,   sc_off);
    cudaGetSymbolAddress((void**)&g_attn,  sc_attn);
    cudaGetSymbolAddress((void**)&g_samp,  sc_samp);
    cudaGetSymbolAddress((void**)&g_src2,  sc_src2);
    cudaGetSymbolAddress((void**)&g_src,   sc_src);
    cudaGetSymbolAddress((void**)&g_ffn,   sc_ffn);
    cudaGetSymbolAddress((void**)&g_ffn2,  sc_ffn2);
    cudaGetSymbolAddress((void**)&g_wvalT, sc_wvalT);
    cudaGetSymbolAddress((void**)&g_woffT, sc_woffT);
    cudaGetSymbolAddress((void**)&g_woutT, sc_woutT);

    // 0. weight transposes (fp32 [K][N] -> bf16 [N][K])
    transpose_bf16_kernel<<<dim3(256/32, 256/32), dim3(32, 8)>>>(W_val, g_wvalT, 256, 256);
    transpose_bf16_kernel<<<dim3(256/32, 256/32), dim3(32, 8)>>>(W_off, g_woffT, 256, 256);
    transpose_bf16_kernel<<<dim3(256/32, 256/32), dim3(32, 8)>>>(W_out, g_woutT, 256, 256);

    // 1. q = cur_src + pos[:, -1]
    add_q_kernel<<<(ROWS_Q * D_MODEL / 4) / 256, 256>>>(cur_src, pos, g_q);

    // 2. value = bf16(src_all + pos) @ W_val + b_val -> bf16 (M=131072,N=256,K=256)
    bgemm_kernel<true, false, true><<<dim3(2, ROWS_V / 128), 256>>>(
        src_all, pos, g_wvalT, b_val, nullptr, g_value, ROWS_V, 256, 256);

    // 3. off = q @ W_off + b_off (bf16)                      (M=32768,N=256,K=256)
    bgemm_kernel<false, false, false><<<dim3(2, ROWS_Q / 128), 256>>>(
        g_q, nullptr, g_woffT, b_off, g_off, nullptr, ROWS_Q, 256, 256);

    // 4. attn_logits = q @ W_attn + b_attn (tf32)            (M=32768,N=128,K=256)
    tgemm_kernel<false><<<dim3(1, ROWS_Q / 128), 256>>>(
        g_q, W_attn, b_attn, g_attn, ROWS_Q, 128, 256);

    // 5. fused softmax + deformable bilinear sampling
    sample_kernel<<<(BATCH * LQ * N_HEADS) / 16, 256>>>(
        g_off, g_attn, refpts, g_value, g_samp);

    // 6. src2 = samp @ W_out + b_out (bf16)                  (M=32768,N=256,K=256)
    bgemm_kernel<false, false, false><<<dim3(2, ROWS_Q / 128), 256>>>(
        g_samp, nullptr, g_woutT, b_out, g_src2, nullptr, ROWS_Q, 256, 256);

    // 7. src = LN(cur_src + src2)
    add_ln_kernel<<<ROWS_Q, 256>>>(cur_src, g_src2, gamma1, beta1, g_src);

    // 8. ffn_h = relu(src @ W1 + b1) (tf32)                  (M=32768,N=1024,K=256)
    tgemm_kernel<true><<<dim3(D_FFN / 128, ROWS_Q / 128), 256>>>(
        g_src, W1, b1, g_ffn, ROWS_Q, D_FFN, 256);

    // 9. ffn2 = ffn_h @ W2 + b2 (tf32)                       (M=32768,N=256,K=1024)
    tgemm_kernel<false><<<dim3(2, ROWS_Q / 128), 256>>>(
        g_ffn, W2, b2, g_ffn2, ROWS_Q, 256, 1024);

    // 10. out = LN(src + ffn2)
    add_ln_kernel<<<ROWS_Q, 256>>>(g_src, g_ffn2, gamma2, beta2, out);
}

// round 8
// speedup vs baseline: 1.6166x; 1.2459x over previous
#include <cuda_runtime.h>
#include <cuda_bf16.h>
#include <cstdint>

// ---------------- problem constants ----------------
#define D_MODEL   256
#define N_HEADS   8
#define HEAD_DIM  32
#define N_LEVELS  4
#define N_POINTS  4
#define D_FFN     1024
#define HW        128
#define LQ        (HW * HW)            // 16384
#define LIN       (N_LEVELS * LQ)      // 65536
#define BATCH     2
#define ROWS_Q    (BATCH * LQ)         // 32768
#define ROWS_V    (BATCH * LIN)        // 131072

// ---------------- scratch (device globals) ---------------------------------
__device__ __align__(256) __nv_bfloat16 sc_value[ROWS_V * D_MODEL]; // 67 MB
__device__ __align__(256) __nv_bfloat16 sc_q    [ROWS_Q * D_MODEL];
__device__ __align__(256) float         sc_off  [ROWS_Q * D_MODEL];
__device__ __align__(256) float         sc_attn [ROWS_Q * 128];
__device__ __align__(256) __nv_bfloat16 sc_samp [ROWS_Q * D_MODEL];
__device__ __align__(256) float         sc_src2 [ROWS_Q * D_MODEL];
__device__ __align__(256) float         sc_src  [ROWS_Q * D_MODEL];
__device__ __align__(256) __nv_bfloat16 sc_srcb [ROWS_Q * D_MODEL];
__device__ __align__(256) __nv_bfloat16 sc_ffnb [ROWS_Q * D_FFN];   // 67 MB
__device__ __align__(256) float         sc_ffn2 [ROWS_Q * D_MODEL];
// bf16 transposed weights Wt[n][k]
__device__ __align__(256) __nv_bfloat16 sc_wvalT [D_MODEL * D_MODEL];
__device__ __align__(256) __nv_bfloat16 sc_woffT [256 * D_MODEL];
__device__ __align__(256) __nv_bfloat16 sc_wattnT[128 * D_MODEL];
__device__ __align__(256) __nv_bfloat16 sc_woutT [D_MODEL * D_MODEL];
__device__ __align__(256) __nv_bfloat16 sc_w1T   [D_FFN * D_MODEL];
__device__ __align__(256) __nv_bfloat16 sc_w2T   [D_MODEL * D_FFN];

// ---------------- helpers --------------------------------------------------
__device__ __forceinline__ void mma_bf16(float c[4], const uint32_t a[4],
                                         const uint32_t b[2]) {
    asm volatile(
        "mma.sync.aligned.m16n8k16.row.col.f32.bf16.bf16.f32 "
        "{%0,%1,%2,%3}, {%4,%5,%6,%7}, {%8,%9}, {%0,%1,%2,%3};"
        : "+f"(c[0]), "+f"(c[1]), "+f"(c[2]), "+f"(c[3])
        : "r"(a[0]), "r"(a[1]), "r"(a[2]), "r"(a[3]), "r"(b[0]), "r"(b[1]));
}
__device__ __forceinline__ void cp_async16(void* smem, const void* gmem) {
    const uint32_t s = (uint32_t)__cvta_generic_to_shared(smem);
    asm volatile("cp.async.ca.shared.global [%0], [%1], 16;\n" :: "r"(s), "l"(gmem));
}
__device__ __forceinline__ void cp_commit() {
    asm volatile("cp.async.commit_group;\n");
}
template <int N>
__device__ __forceinline__ void cp_wait() {
    asm volatile("cp.async.wait_group %0;\n" :: "n"(N));
}
__device__ __forceinline__ uint32_t packbf(float x, float y) {
    __nv_bfloat162 p = __floats2bfloat162_rn(x, y);
    return *(uint32_t*)&p;
}

#define BPAD 40   // bf16 row stride: conflict-free frag loads

// ---- shared epilogue -------------------------------------------------------
template <bool RELU, bool BF16_OUT>
__device__ __forceinline__ void gemm_epilogue(
    float acc[4][4][4], const float* bias, float* C, __nv_bfloat16* Cb,
    int bm, int bn, int wm, int wn, int g, int t, int N)
{
    #pragma unroll
    for (int nt = 0; nt < 4; ++nt) {
        const int n = bn + wn + nt * 8 + t * 2;
        const float bx = bias[n], by = bias[n + 1];
        #pragma unroll
        for (int mt = 0; mt < 4; ++mt) {
            const int m = bm + wm + mt * 16 + g;
            float2 v0 = { acc[mt][nt][0] + bx, acc[mt][nt][1] + by };
            float2 v1 = { acc[mt][nt][2] + bx, acc[mt][nt][3] + by };
            if (RELU) {
                v0.x = fmaxf(v0.x, 0.f); v0.y = fmaxf(v0.y, 0.f);
                v1.x = fmaxf(v1.x, 0.f); v1.y = fmaxf(v1.y, 0.f);
            }
            if (BF16_OUT) {
                *(uint32_t*)&Cb[(size_t)m * N + n]       = packbf(v0.x, v0.y);
                *(uint32_t*)&Cb[(size_t)(m + 8) * N + n] = packbf(v1.x, v1.y);
            } else {
                *(float2*)&C[(size_t)m * N + n]       = v0;
                *(float2*)&C[(size_t)(m + 8) * N + n] = v1;
            }
        }
    }
}

// ---- warp-tile compute on one smem stage -----------------------------------
__device__ __forceinline__ void gemm_compute_stage(
    const __nv_bfloat16* As, const __nv_bfloat16* Bs,
    float acc[4][4][4], int wm, int wn, int g, int t)
{
    #pragma unroll
    for (int ks = 0; ks < 32; ks += 16) {
        uint32_t af[4][4];
        #pragma unroll
        for (int mt = 0; mt < 4; ++mt) {
            const __nv_bfloat16* p = &As[(wm + mt * 16 + g) * BPAD + ks + 2 * t];
            af[mt][0] = *(const uint32_t*)p;
            af[mt][1] = *(const uint32_t*)(p + 8 * BPAD);
            af[mt][2] = *(const uint32_t*)(p + 8);
            af[mt][3] = *(const uint32_t*)(p + 8 * BPAD + 8);
        }
        uint32_t bf[4][2];
        #pragma unroll
        for (int nt = 0; nt < 4; ++nt) {
            const __nv_bfloat16* p = &Bs[(wn + nt * 8 + g) * BPAD + ks + 2 * t];
            bf[nt][0] = *(const uint32_t*)p;
            bf[nt][1] = *(const uint32_t*)(p + 8);
        }
        #pragma unroll
        for (int mt = 0; mt < 4; ++mt)
            #pragma unroll
            for (int nt = 0; nt < 4; ++nt)
                mma_bf16(acc[mt][nt], af[mt], bf[nt]);
    }
}

// ================= GEMM A: fp32 A (+A2 fuse) -> bf16 MMA =====================
// value projection only. BM=BN=128, BK=32, 256 thr, 2-stage reg-staged A.
template <bool RELU, bool BF16_OUT>
__global__ __launch_bounds__(256)
void bgemm_f32a(const float* __restrict__ A, const float* __restrict__ A2,
                const __nv_bfloat16* __restrict__ Bt, const float* __restrict__ bias,
                float* __restrict__ C, __nv_bfloat16* __restrict__ Cb,
                int M, int N, int K)
{
    __shared__ __align__(16) __nv_bfloat16 As[2][128 * BPAD];
    __shared__ __align__(16) __nv_bfloat16 Bs[2][128 * BPAD];

    const int tid  = threadIdx.x;
    const int wid  = tid >> 5;
    const int lane = tid & 31;
    const int g    = lane >> 2;
    const int t    = lane & 3;
    const int bm = blockIdx.y * 128;
    const int bn = blockIdx.x * 128;
    const int wm = (wid & 1) * 64;
    const int wn = (wid >> 1) * 32;

    const int la_r = tid >> 1;
    const int la_c = (tid & 1) * 16;
    const float* a_ptr  = A  + (size_t)(bm + la_r) * K + la_c;
    const float* a2_ptr = A2 + (size_t)(bm + la_r) * K + la_c;

    const int nk = K / 32;

    auto ldgA = [&](int i, uint32_t v[8]) {
        const int k0 = i * 32;
        #pragma unroll
        for (int j = 0; j < 4; ++j) {
            float4 a = *(const float4*)(a_ptr + k0 + j * 4);
            const float4 b = *(const float4*)(a2_ptr + k0 + j * 4);
            a.x += b.x; a.y += b.y; a.z += b.z; a.w += b.w;
            v[2 * j]     = packbf(a.x, a.y);
            v[2 * j + 1] = packbf(a.z, a.w);
        }
    };
    auto stsA = [&](int s, const uint32_t v[8]) {
        uint32_t* p = (uint32_t*)&As[s][la_r * BPAD + la_c];
        *(uint4*)p       = make_uint4(v[0], v[1], v[2], v[3]);
        *(uint4*)(p + 4) = make_uint4(v[4], v[5], v[6], v[7]);
    };
    auto cpB = [&](int s, int i) {
        const int k0 = i * 32;
        #pragma unroll
        for (int j = 0; j < 2; ++j) {
            const int ch = j * 256 + tid;
            const int r  = ch >> 2;
            const int cc = (ch & 3) * 8;
            cp_async16(&Bs[s][r * BPAD + cc], Bt + (size_t)(bn + r) * K + k0 + cc);
        }
    };

    float acc[4][4][4] = {};
    uint32_t rA[8];

    ldgA(0, rA);
    stsA(0, rA);
    cpB(0, 0);
    cp_commit();
    ldgA(1, rA);

    for (int i = 0; i < nk; ++i) {
        cp_wait<0>();
        __syncthreads();
        if (i + 1 < nk) {
            stsA((i + 1) & 1, rA);
            cpB((i + 1) & 1, i + 1);
            cp_commit();
        }
        if (i + 2 < nk) ldgA(i + 2, rA);
        gemm_compute_stage(As[i & 1], Bs[i & 1], acc, wm, wn, g, t);
        __syncthreads();
    }
    gemm_epilogue<RELU, BF16_OUT>(acc, bias, C, Cb, bm, bn, wm, wn, g, t, N);
}

// ================= GEMM B: bf16 A -> bf16 MMA, 3-stage cp.async ==============
template <bool RELU, bool BF16_OUT>
__global__ __launch_bounds__(256)
void bgemm_b16a(const __nv_bfloat16* __restrict__ A,
                const __nv_bfloat16* __restrict__ Bt, const float* __restrict__ bias,
                float* __restrict__ C, __nv_bfloat16* __restrict__ Cb,
                int M, int N, int K)
{
    __shared__ __align__(16) __nv_bfloat16 As[3][128 * BPAD];
    __shared__ __align__(16) __nv_bfloat16 Bs[3][128 * BPAD];

    const int tid  = threadIdx.x;
    const int wid  = tid >> 5;
    const int lane = tid & 31;
    const int g    = lane >> 2;
    const int t    = lane & 3;
    const int bm = blockIdx.y * 128;
    const int bn = blockIdx.x * 128;
    const int wm = (wid & 1) * 64;
    const int wn = (wid >> 1) * 32;

    const int nk = K / 32;

    auto load_stage = [&](int s, int i) {
        const int k0 = i * 32;
        #pragma unroll
        for (int j = 0; j < 2; ++j) {
            const int ch = j * 256 + tid;
            const int r  = ch >> 2;
            const int cc = (ch & 3) * 8;
            cp_async16(&As[s][r * BPAD + cc], A  + (size_t)(bm + r) * K + k0 + cc);
            cp_async16(&Bs[s][r * BPAD + cc], Bt + (size_t)(bn + r) * K + k0 + cc);
        }
    };

    float acc[4][4][4] = {};

    load_stage(0, 0); cp_commit();
    load_stage(1, 1); cp_commit();

    for (int i = 0; i < nk; ++i) {
        cp_wait<1>();
        __syncthreads();
        const int nxt = i + 2;
        if (nxt < nk) load_stage(nxt % 3, nxt);
        cp_commit();
        gemm_compute_stage(As[i % 3], Bs[i % 3], acc, wm, wn, g, t);
        __syncthreads();
    }
    gemm_epilogue<RELU, BF16_OUT>(acc, bias, C, Cb, bm, bn, wm, wn, g, t, N);
}

// ---------------- weight transpose fp32[K][N] -> bf16[N][K] -----------------
__global__ __launch_bounds__(256)
void transpose_bf16_kernel(const float* __restrict__ W, __nv_bfloat16* __restrict__ Wt,
                           int K, int N)
{
    __shared__ float t[32][33];
    const int bx = blockIdx.x * 32;   // n
    const int by = blockIdx.y * 32;   // k
    const int x = threadIdx.x, y = threadIdx.y;   // (32, 8)
    #pragma unroll
    for (int j = 0; j < 32; j += 8)
        t[y + j][x] = W[(size_t)(by + y + j) * N + bx + x];
    __syncthreads();
    #pragma unroll
    for (int j = 0; j < 32; j += 8)
        Wt[(size_t)(bx + y + j) * K + by + x] = __float2bfloat16_rn(t[x][y + j]);
}

// ---------------- q = bf16(cur_src + pos[:, -1]) ----------------------------
__global__ __launch_bounds__(256)
void add_q_kernel(const float* __restrict__ cur, const float* __restrict__ pos,
                  __nv_bfloat16* __restrict__ q)
{
    const size_t i = (size_t)blockIdx.x * blockDim.x + threadIdx.x;
    const size_t per_batch = (size_t)LQ * D_MODEL / 4;
    const size_t n = i / per_batch;
    const size_t r = i - n * per_batch;
    const float4 a = ((const float4*)cur)[i];
    const float4 b = ((const float4*)pos)[n * 4 * per_batch + 3 * per_batch + r];
    uint2 w;
    w.x = packbf(a.x + b.x, a.y + b.y);
    w.y = packbf(a.z + b.z, a.w + b.w);
    ((uint2*)q)[i] = w;
}

// ---------------- fused softmax + deformable bilinear sampling --------------
// Half-warp per (n, q, h): 16 lanes x 2 channels (bf162 gathers), bf16 out.
__global__ __launch_bounds__(256)
void sample_kernel(const float* __restrict__ off, const float* __restrict__ attn,
                   const float* __restrict__ ref,
                   const __nv_bfloat16* __restrict__ value,
                   __nv_bfloat16* __restrict__ out)
{
    const int tw   = blockIdx.x * 16 + (threadIdx.x >> 4);
    const int l16  = threadIdx.x & 15;
    const int h = tw & 7;
    const int q = (tw >> 3) & (LQ - 1);
    const int n = tw >> 17;

    const size_t row = (size_t)n * LQ + q;
    const float* ap = attn + row * 128 + h * 16;

    float logits[16];
    float mx = -1e30f;
    #pragma unroll
    for (int i = 0; i < 16; ++i) { logits[i] = ap[i]; mx = fmaxf(mx, logits[i]); }
    float ssum = 0.f;
    #pragma unroll
    for (int i = 0; i < 16; ++i) { logits[i] = __expf(logits[i] - mx); ssum += logits[i]; }
    const float inv = 1.f / ssum;

    const float* op = off + row * 256 + h * 32;
    const float* rp = ref + row * 8;
    const __nv_bfloat162* vb =
        (const __nv_bfloat162*)value + (size_t)n * LIN * 128 + h * 16 + l16;

    float2 acc = {0.f, 0.f};
    #pragma unroll
    for (int l = 0; l < N_LEVELS; ++l) {
        const float rx = rp[l * 2 + 0];
        const float ry = rp[l * 2 + 1];
        const int start = l * LQ;
        #pragma unroll
        for (int p = 0; p < N_POINTS; ++p) {
            const float x = fmaf(rx, 128.f, op[l * 8 + p * 2 + 0] - 0.5f);
            const float y = fmaf(ry, 128.f, op[l * 8 + p * 2 + 1] - 0.5f);
            const float x0f = floorf(x), y0f = floorf(y);
            const float wx = x - x0f, wy = y - y0f;
            const int x0 = (int)x0f, y0 = (int)y0f;
            const float aw = logits[l * 4 + p] * inv;

            const bool vx0 = (x0 >= 0) & (x0 < HW);
            const bool vx1 = (x0 + 1 >= 0) & (x0 + 1 < HW);
            const bool vy0 = (y0 >= 0) & (y0 < HW);
            const bool vy1 = (y0 + 1 >= 0) & (y0 + 1 < HW);

            if (vy0) {
                const size_t base = (size_t)(start + y0 * HW) * 128;
                if (vx0) {
                    const float2 f = __bfloat1622float2(vb[base + (size_t)x0 * 128]);
                    const float w = (1.f - wx) * (1.f - wy) * aw;
                    acc.x = fmaf(f.x, w, acc.x); acc.y = fmaf(f.y, w, acc.y);
                }
                if (vx1) {
                    const float2 f = __bfloat1622float2(vb[base + (size_t)(x0 + 1) * 128]);
                    const float w = wx * (1.f - wy) * aw;
                    acc.x = fmaf(f.x, w, acc.x); acc.y = fmaf(f.y, w, acc.y);
                }
            }
            if (vy1) {
                const size_t base = (size_t)(start + (y0 + 1) * HW) * 128;
                if (vx0) {
                    const float2 f = __bfloat1622float2(vb[base + (size_t)x0 * 128]);
                    const float w = (1.f - wx) * wy * aw;
                    acc.x = fmaf(f.x, w, acc.x); acc.y = fmaf(f.y, w, acc.y);
                }
                if (vx1) {
                    const float2 f = __bfloat1622float2(vb[base + (size_t)(x0 + 1) * 128]);
                    const float w = wx * wy * aw;
                    acc.x = fmaf(f.x, w, acc.x); acc.y = fmaf(f.y, w, acc.y);
                }
            }
        }
    }
    *(uint32_t*)&out[row * 256 + h * 32 + l16 * 2] = packbf(acc.x, acc.y);
}

// ---------------- residual add + layernorm (+ optional bf16 twin) -----------
__global__ __launch_bounds__(256)
void add_ln_kernel(const float* __restrict__ a, const float* __restrict__ b,
                   const float* __restrict__ gamma, const float* __restrict__ beta,
                   float* __restrict__ out, __nv_bfloat16* __restrict__ out_b)
{
    const int row = blockIdx.x;
    const int t = threadIdx.x;
    const size_t idx = (size_t)row * 256 + t;
    const float v = a[idx] + b[idx];

    __shared__ float red[8];
    float s = v;
    #pragma unroll
    for (int o = 16; o; o >>= 1) s += __shfl_xor_sync(0xffffffffu, s, o);
    if ((t & 31) == 0) red[t >> 5] = s;
    __syncthreads();
    float mean = 0.f;
    #pragma unroll
    for (int i = 0; i < 8; ++i) mean += red[i];
    mean *= (1.f / 256.f);
    __syncthreads();

    const float d = v - mean;
    float s2 = d * d;
    #pragma unroll
    for (int o = 16; o; o >>= 1) s2 += __shfl_xor_sync(0xffffffffu, s2, o);
    if ((t & 31) == 0) red[t >> 5] = s2;
    __syncthreads();
    float var = 0.f;
    #pragma unroll
    for (int i = 0; i < 8; ++i) var += red[i];
    var *= (1.f / 256.f);

    const float r = d * rsqrtf(var + 1e-5f) * gamma[t] + beta[t];
    out[idx] = r;
    if (out_b) out_b[idx] = __float2bfloat16_rn(r);
}

// ---------------- launch -----------------------------------------------------
extern "C" void kernel_launch(void* const* d_in, const int* in_sizes, int n_in,
                              void* d_out, int out_size)
{
    (void)in_sizes; (void)n_in; (void)out_size;
    const float* cur_src = (const float*)d_in[0];
    const float* src_all = (const float*)d_in[1];
    const float* pos     = (const float*)d_in[2];
    const float* refpts  = (const float*)d_in[3];
    const float* W_off   = (const float*)d_in[6];
    const float* b_off   = (const float*)d_in[7];
    const float* W_attn  = (const float*)d_in[8];
    const float* b_attn  = (const float*)d_in[9];
    const float* W_val   = (const float*)d_in[10];
    const float* b_val   = (const float*)d_in[11];
    const float* W_out   = (const float*)d_in[12];
    const float* b_out   = (const float*)d_in[13];
    const float* gamma1  = (const float*)d_in[14];
    const float* beta1   = (const float*)d_in[15];
    const float* W1      = (const float*)d_in[16];
    const float* b1      = (const float*)d_in[17];
    const float* W2      = (const float*)d_in[18];
    const float* b2      = (const float*)d_in[19];
    const float* gamma2  = (const float*)d_in[20];
    const float* beta2   = (const float*)d_in[21];
    float* out = (float*)d_out;

    float *g_off, *g_attn, *g_src2, *g_src, *g_ffn2;
    __nv_bfloat16 *g_value, *g_q, *g_samp, *g_srcb, *g_ffnb;
    __nv_bfloat16 *g_wvalT, *g_woffT, *g_wattnT, *g_woutT, *g_w1T, *g_w2T;
    cudaGetSymbolAddress((void**)&g_value,  sc_value);
    cudaGetSymbolAddress((void**)&g_q,      sc_q);
    cudaGetSymbolAddress((void**)&g_off,    sc_off);
    cudaGetSymbolAddress((void**)&g_attn,   sc_attn);
    cudaGetSymbolAddress((void**)&g_samp,   sc_samp);
    cudaGetSymbolAddress((void**)&g_src2,   sc_src2);
    cudaGetSymbolAddress((void**)&g_src,    sc_src);
    cudaGetSymbolAddress((void**)&g_srcb,   sc_srcb);
    cudaGetSymbolAddress((void**)&g_ffnb,   sc_ffnb);
    cudaGetSymbolAddress((void**)&g_ffn2,   sc_ffn2);
    cudaGetSymbolAddress((void**)&g_wvalT,  sc_wvalT);
    cudaGetSymbolAddress((void**)&g_woffT,  sc_woffT);
    cudaGetSymbolAddress((void**)&g_wattnT, sc_wattnT);
    cudaGetSymbolAddress((void**)&g_woutT,  sc_woutT);
    cudaGetSymbolAddress((void**)&g_w1T,    sc_w1T);
    cudaGetSymbolAddress((void**)&g_w2T,    sc_w2T);

    // 0. weight transposes (fp32 [K][N] -> bf16 [N][K])
    transpose_bf16_kernel<<<dim3(8, 8),  dim3(32, 8)>>>(W_val,  g_wvalT,  256, 256);
    transpose_bf16_kernel<<<dim3(8, 8),  dim3(32, 8)>>>(W_off,  g_woffT,  256, 256);
    transpose_bf16_kernel<<<dim3(4, 8),  dim3(32, 8)>>>(W_attn, g_wattnT, 256, 128);
    transpose_bf16_kernel<<<dim3(8, 8),  dim3(32, 8)>>>(W_out,  g_woutT,  256, 256);
    transpose_bf16_kernel<<<dim3(32, 8), dim3(32, 8)>>>(W1,     g_w1T,    256, 1024);
    transpose_bf16_kernel<<<dim3(8, 32), dim3(32, 8)>>>(W2,     g_w2T,    1024, 256);

    // 1. q = bf16(cur_src + pos[:, -1])
    add_q_kernel<<<(ROWS_Q * D_MODEL / 4) / 256, 256>>>(cur_src, pos, g_q);

    // 2. value = bf16(src_all + pos) @ W_val + b_val -> bf16 (M=131072,N=256,K=256)
    bgemm_f32a<false, true><<<dim3(2, ROWS_V / 128), 256>>>(
        src_all, pos, g_wvalT, b_val, nullptr, g_value, ROWS_V, 256, 256);

    // 3. off = q @ W_off + b_off                             (M=32768,N=256,K=256)
    bgemm_b16a<false, false><<<dim3(2, ROWS_Q / 128), 256>>>(
        g_q, g_woffT, b_off, g_off, nullptr, ROWS_Q, 256, 256);

    // 4. attn_logits = q @ W_attn + b_attn                   (M=32768,N=128,K=256)
    bgemm_b16a<false, false><<<dim3(1, ROWS_Q / 128), 256>>>(
        g_q, g_wattnT, b_attn, g_attn, nullptr, ROWS_Q, 128, 256);

    // 5. fused softmax + deformable bilinear sampling -> bf16
    sample_kernel<<<(BATCH * LQ * N_HEADS) / 16, 256>>>(
        g_off, g_attn, refpts, g_value, g_samp);

    // 6. src2 = samp @ W_out + b_out                         (M=32768,N=256,K=256)
    bgemm_b16a<false, false><<<dim3(2, ROWS_Q / 128), 256>>>(
        g_samp, g_woutT, b_out, g_src2, nullptr, ROWS_Q, 256, 256);

    // 7. src = LN(cur_src + src2), bf16 twin for FFN1
    add_ln_kernel<<<ROWS_Q, 256>>>(cur_src, g_src2, gamma1, beta1, g_src, g_srcb);

    // 8. ffn_h = relu(src @ W1 + b1) -> bf16                 (M=32768,N=1024,K=256)
    bgemm_b16a<true, true><<<dim3(D_FFN / 128, ROWS_Q / 128), 256>>>(
        g_srcb, g_w1T, b1, nullptr, g_ffnb, ROWS_Q, D_FFN, 256);

    // 9. ffn2 = ffn_h @ W2 + b2                              (M=32768,N=256,K=1024)
    bgemm_b16a<false, false><<<dim3(2, ROWS_Q / 128), 256>>>(
        g_ffnb, g_w2T, b2, g_ffn2, nullptr, ROWS_Q, 256, 1024);

    // 10. out = LN(src + ffn2)
    add_ln_kernel<<<ROWS_Q, 256>>>(g_src, g_ffn2, gamma2, beta2, out, nullptr);
}

// round 10
// speedup vs baseline: 1.6651x; 1.0300x over previous
#include <cuda_runtime.h>
#include <cuda_bf16.h>
#include <cstdint>

// ---------------- problem constants ----------------
#define D_MODEL   256
#define N_HEADS   8
#define HEAD_DIM  32
#define N_LEVELS  4
#define N_POINTS  4
#define D_FFN     1024
#define HW        128
#define LQ        (HW * HW)            // 16384
#define LIN       (N_LEVELS * LQ)      // 65536
#define BATCH     2
#define ROWS_Q    (BATCH * LQ)         // 32768
#define ROWS_V    (BATCH * LIN)        // 131072

// ---------------- scratch (device globals) ---------------------------------
__device__ __align__(256) __nv_bfloat16 sc_value[ROWS_V * D_MODEL]; // head-major
__device__ __align__(256) float         sc_off  [ROWS_Q * D_MODEL];
__device__ __align__(256) float         sc_attn [ROWS_Q * 128];
__device__ __align__(256) __nv_bfloat16 sc_samp [ROWS_Q * D_MODEL];
__device__ __align__(256) float         sc_src2 [ROWS_Q * D_MODEL];
__device__ __align__(256) float         sc_src  [ROWS_Q * D_MODEL];
__device__ __align__(256) __nv_bfloat16 sc_srcb [ROWS_Q * D_MODEL];
__device__ __align__(256) __nv_bfloat16 sc_ffnb [ROWS_Q * D_FFN];
__device__ __align__(256) float         sc_ffn2 [ROWS_Q * D_MODEL];
// bf16 transposed weights Wt[n][k]
__device__ __align__(256) __nv_bfloat16 sc_wvalT[D_MODEL * D_MODEL];
__device__ __align__(256) __nv_bfloat16 sc_wqT  [384 * D_MODEL];      // off(256)+attn(128)
__device__ __align__(256) __nv_bfloat16 sc_woutT[D_MODEL * D_MODEL];
__device__ __align__(256) __nv_bfloat16 sc_w1T  [D_FFN * D_MODEL];
__device__ __align__(256) __nv_bfloat16 sc_w2T  [D_MODEL * D_FFN];
__device__ __align__(256) float         sc_bq   [384];                // b_off ++ b_attn

// ---------------- helpers --------------------------------------------------
__device__ __forceinline__ void mma_bf16(float c[4], const uint32_t a[4],
                                         const uint32_t b[2]) {
    asm volatile(
        "mma.sync.aligned.m16n8k16.row.col.f32.bf16.bf16.f32 "
        "{%0,%1,%2,%3}, {%4,%5,%6,%7}, {%8,%9}, {%0,%1,%2,%3};"
        : "+f"(c[0]), "+f"(c[1]), "+f"(c[2]), "+f"(c[3])
        : "r"(a[0]), "r"(a[1]), "r"(a[2]), "r"(a[3]), "r"(b[0]), "r"(b[1]));
}
__device__ __forceinline__ void cp_async16(void* smem, const void* gmem) {
    const uint32_t s = (uint32_t)__cvta_generic_to_shared(smem);
    asm volatile("cp.async.ca.shared.global [%0], [%1], 16;\n" :: "r"(s), "l"(gmem));
}
__device__ __forceinline__ void cp_commit() {
    asm volatile("cp.async.commit_group;\n");
}
template <int N>
__device__ __forceinline__ void cp_wait() {
    asm volatile("cp.async.wait_group %0;\n" :: "n"(N));
}
__device__ __forceinline__ uint32_t packbf(float x, float y) {
    __nv_bfloat162 p = __floats2bfloat162_rn(x, y);
    return *(uint32_t*)&p;
}

#define BPAD 40   // bf16 row stride: conflict-free frag loads

// ---- warp-tile compute on one smem stage -----------------------------------
__device__ __forceinline__ void gemm_compute_stage(
    const __nv_bfloat16* As, const __nv_bfloat16* Bs,
    float acc[4][4][4], int wm, int wn, int g, int t)
{
    #pragma unroll
    for (int ks = 0; ks < 32; ks += 16) {
        uint32_t af[4][4];
        #pragma unroll
        for (int mt = 0; mt < 4; ++mt) {
            const __nv_bfloat16* p = &As[(wm + mt * 16 + g) * BPAD + ks + 2 * t];
            af[mt][0] = *(const uint32_t*)p;
            af[mt][1] = *(const uint32_t*)(p + 8 * BPAD);
            af[mt][2] = *(const uint32_t*)(p + 8);
            af[mt][3] = *(const uint32_t*)(p + 8 * BPAD + 8);
        }
        uint32_t bf[4][2];
        #pragma unroll
        for (int nt = 0; nt < 4; ++nt) {
            const __nv_bfloat16* p = &Bs[(wn + nt * 8 + g) * BPAD + ks + 2 * t];
            bf[nt][0] = *(const uint32_t*)p;
            bf[nt][1] = *(const uint32_t*)(p + 8);
        }
        #pragma unroll
        for (int mt = 0; mt < 4; ++mt)
            #pragma unroll
            for (int nt = 0; nt < 4; ++nt)
                mma_bf16(acc[mt][nt], af[mt], bf[nt]);
    }
}

// ================= GEMM 1: value projection =================================
// A fp32 + A2 fp32 (same row), out = bf16 HEAD-MAJOR [n][h][pix][32].
__global__ __launch_bounds__(256)
void bgemm_value(const float* __restrict__ A, const float* __restrict__ A2,
                 const __nv_bfloat16* __restrict__ Bt, const float* __restrict__ bias,
                 __nv_bfloat16* __restrict__ Cb, int K)
{
    __shared__ __align__(16) __nv_bfloat16 As[2][128 * BPAD];
    __shared__ __align__(16) __nv_bfloat16 Bs[2][128 * BPAD];

    const int tid  = threadIdx.x;
    const int wid  = tid >> 5;
    const int lane = tid & 31;
    const int g    = lane >> 2;
    const int t    = lane & 3;
    const int bm = blockIdx.y * 128;
    const int bn = blockIdx.x * 128;
    const int wm = (wid & 1) * 64;
    const int wn = (wid >> 1) * 32;

    const int la_r = tid >> 1;
    const int la_c = (tid & 1) * 16;
    const float* a_ptr  = A  + (size_t)(bm + la_r) * K + la_c;
    const float* a2_ptr = A2 + (size_t)(bm + la_r) * K + la_c;

    const int nk = K / 32;

    auto ldgA = [&](int i, uint32_t v[8]) {
        const int k0 = i * 32;
        #pragma unroll
        for (int j = 0; j < 4; ++j) {
            float4 a = *(const float4*)(a_ptr + k0 + j * 4);
            const float4 b = *(const float4*)(a2_ptr + k0 + j * 4);
            a.x += b.x; a.y += b.y; a.z += b.z; a.w += b.w;
            v[2 * j]     = packbf(a.x, a.y);
            v[2 * j + 1] = packbf(a.z, a.w);
        }
    };
    auto stsA = [&](int s, const uint32_t v[8]) {
        uint32_t* p = (uint32_t*)&As[s][la_r * BPAD + la_c];
        *(uint4*)p       = make_uint4(v[0], v[1], v[2], v[3]);
        *(uint4*)(p + 4) = make_uint4(v[4], v[5], v[6], v[7]);
    };
    auto cpB = [&](int s, int i) {
        const int k0 = i * 32;
        #pragma unroll
        for (int j = 0; j < 2; ++j) {
            const int ch = j * 256 + tid;
            const int r  = ch >> 2;
            const int cc = (ch & 3) * 8;
            cp_async16(&Bs[s][r * BPAD + cc], Bt + (size_t)(bn + r) * K + k0 + cc);
        }
    };

    float acc[4][4][4] = {};
    uint32_t rA[8];

    ldgA(0, rA); stsA(0, rA); cpB(0, 0); cp_commit();
    ldgA(1, rA);

    for (int i = 0; i < nk; ++i) {
        cp_wait<0>();
        __syncthreads();
        if (i + 1 < nk) { stsA((i + 1) & 1, rA); cpB((i + 1) & 1, i + 1); cp_commit(); }
        if (i + 2 < nk) ldgA(i + 2, rA);
        gemm_compute_stage(As[i & 1], Bs[i & 1], acc, wm, wn, g, t);
        __syncthreads();
    }

    // epilogue: head-major store
    const int nb  = bm / LIN;              // batch (tile never straddles LIN)
    const int pix0 = bm & (LIN - 1);
    #pragma unroll
    for (int nt = 0; nt < 4; ++nt) {
        const int n = bn + wn + nt * 8 + t * 2;
        const int h = n >> 5, c = n & 31;
        const float bx = bias[n], by = bias[n + 1];
        __nv_bfloat16* hb = Cb + ((size_t)(nb * 8 + h) * LIN) * 32 + c;
        #pragma unroll
        for (int mt = 0; mt < 4; ++mt) {
            const int pix = pix0 + wm + mt * 16 + g;
            *(uint32_t*)&hb[(size_t)pix * 32] =
                packbf(acc[mt][nt][0] + bx, acc[mt][nt][1] + by);
            *(uint32_t*)&hb[(size_t)(pix + 8) * 32] =
                packbf(acc[mt][nt][2] + bx, acc[mt][nt][3] + by);
        }
    }
}

// ================= GEMM 2: fused q-add + off/attn split =====================
// A=cur_src fp32, A2=pos (row remap), Bt = wqT[384][256], bias = bq[384].
// bn<256 -> off (stride 256); bn==256 -> attn (stride 128).
__global__ __launch_bounds__(256)
void bgemm_qa(const float* __restrict__ A, const float* __restrict__ A2,
              const __nv_bfloat16* __restrict__ Bt, const float* __restrict__ bias,
              float* __restrict__ Coff, float* __restrict__ Cattn)
{
    const int K = 256;
    __shared__ __align__(16) __nv_bfloat16 As[2][128 * BPAD];
    __shared__ __align__(16) __nv_bfloat16 Bs[2][128 * BPAD];

    const int tid  = threadIdx.x;
    const int wid  = tid >> 5;
    const int lane = tid & 31;
    const int g    = lane >> 2;
    const int t    = lane & 3;
    const int bm = blockIdx.y * 128;
    const int bn = blockIdx.x * 128;
    const int wm = (wid & 1) * 64;
    const int wn = (wid >> 1) * 32;

    const int la_r = tid >> 1;
    const int la_c = (tid & 1) * 16;
    const int r_glob = bm + la_r;
    const int pos_row = r_glob + 49152 * ((r_glob >> 14) + 1);  // pos[:, -1] remap
    const float* a_ptr  = A  + (size_t)r_glob * K + la_c;
    const float* a2_ptr = A2 + (size_t)pos_row * K + la_c;

    const int nk = K / 32;

    auto ldgA = [&](int i, uint32_t v[8]) {
        const int k0 = i * 32;
        #pragma unroll
        for (int j = 0; j < 4; ++j) {
            float4 a = *(const float4*)(a_ptr + k0 + j * 4);
            const float4 b = *(const float4*)(a2_ptr + k0 + j * 4);
            a.x += b.x; a.y += b.y; a.z += b.z; a.w += b.w;
            v[2 * j]     = packbf(a.x, a.y);
            v[2 * j + 1] = packbf(a.z, a.w);
        }
    };
    auto stsA = [&](int s, const uint32_t v[8]) {
        uint32_t* p = (uint32_t*)&As[s][la_r * BPAD + la_c];
        *(uint4*)p       = make_uint4(v[0], v[1], v[2], v[3]);
        *(uint4*)(p + 4) = make_uint4(v[4], v[5], v[6], v[7]);
    };
    auto cpB = [&](int s, int i) {
        const int k0 = i * 32;
        #pragma unroll
        for (int j = 0; j < 2; ++j) {
            const int ch = j * 256 + tid;
            const int r  = ch >> 2;
            const int cc = (ch & 3) * 8;
            cp_async16(&Bs[s][r * BPAD + cc], Bt + (size_t)(bn + r) * K + k0 + cc);
        }
    };

    float acc[4][4][4] = {};
    uint32_t rA[8];

    ldgA(0, rA); stsA(0, rA); cpB(0, 0); cp_commit();
    ldgA(1, rA);

    for (int i = 0; i < nk; ++i) {
        cp_wait<0>();
        __syncthreads();
        if (i + 1 < nk) { stsA((i + 1) & 1, rA); cpB((i + 1) & 1, i + 1); cp_commit(); }
        if (i + 2 < nk) ldgA(i + 2, rA);
        gemm_compute_stage(As[i & 1], Bs[i & 1], acc, wm, wn, g, t);
        __syncthreads();
    }

    const bool is_attn = (bn >= 256);
    float* C = is_attn ? Cattn : Coff;
    const int stride = is_attn ? 128 : 256;
    const int cbase  = is_attn ? bn - 256 : bn;
    #pragma unroll
    for (int nt = 0; nt < 4; ++nt) {
        const int nn = wn + nt * 8 + t * 2;
        const float bx = bias[bn + nn], by = bias[bn + nn + 1];
        #pragma unroll
        for (int mt = 0; mt < 4; ++mt) {
            const int m = bm + wm + mt * 16 + g;
            *(float2*)&C[(size_t)m * stride + cbase + nn] =
                make_float2(acc[mt][nt][0] + bx, acc[mt][nt][1] + by);
            *(float2*)&C[(size_t)(m + 8) * stride + cbase + nn] =
                make_float2(acc[mt][nt][2] + bx, acc[mt][nt][3] + by);
        }
    }
}

// ================= GEMM 3: bf16 A, 3-stage (out-proj / FFN) =================
template <bool RELU, bool BF16_OUT>
__global__ __launch_bounds__(256)
void bgemm_b16a(const __nv_bfloat16* __restrict__ A,
                const __nv_bfloat16* __restrict__ Bt, const float* __restrict__ bias,
                float* __restrict__ C, __nv_bfloat16* __restrict__ Cb,
                int M, int N, int K)
{
    __shared__ __align__(16) __nv_bfloat16 As[3][128 * BPAD];
    __shared__ __align__(16) __nv_bfloat16 Bs[3][128 * BPAD];

    const int tid  = threadIdx.x;
    const int wid  = tid >> 5;
    const int lane = tid & 31;
    const int g    = lane >> 2;
    const int t    = lane & 3;
    const int bm = blockIdx.y * 128;
    const int bn = blockIdx.x * 128;
    const int wm = (wid & 1) * 64;
    const int wn = (wid >> 1) * 32;

    const int nk = K / 32;

    auto load_stage = [&](int s, int i) {
        const int k0 = i * 32;
        #pragma unroll
        for (int j = 0; j < 2; ++j) {
            const int ch = j * 256 + tid;
            const int r  = ch >> 2;
            const int cc = (ch & 3) * 8;
            cp_async16(&As[s][r * BPAD + cc], A  + (size_t)(bm + r) * K + k0 + cc);
            cp_async16(&Bs[s][r * BPAD + cc], Bt + (size_t)(bn + r) * K + k0 + cc);
        }
    };

    float acc[4][4][4] = {};

    load_stage(0, 0); cp_commit();
    load_stage(1, 1); cp_commit();

    for (int i = 0; i < nk; ++i) {
        cp_wait<1>();
        __syncthreads();
        const int nxt = i + 2;
        if (nxt < nk) load_stage(nxt % 3, nxt);
        cp_commit();
        gemm_compute_stage(As[i % 3], Bs[i % 3], acc, wm, wn, g, t);
        __syncthreads();
    }

    #pragma unroll
    for (int nt = 0; nt < 4; ++nt) {
        const int n = bn + wn + nt * 8 + t * 2;
        const float bx = bias[n], by = bias[n + 1];
        #pragma unroll
        for (int mt = 0; mt < 4; ++mt) {
            const int m = bm + wm + mt * 16 + g;
            float2 v0 = { acc[mt][nt][0] + bx, acc[mt][nt][1] + by };
            float2 v1 = { acc[mt][nt][2] + bx, acc[mt][nt][3] + by };
            if (RELU) {
                v0.x = fmaxf(v0.x, 0.f); v0.y = fmaxf(v0.y, 0.f);
                v1.x = fmaxf(v1.x, 0.f); v1.y = fmaxf(v1.y, 0.f);
            }
            if (BF16_OUT) {
                *(uint32_t*)&Cb[(size_t)m * N + n]       = packbf(v0.x, v0.y);
                *(uint32_t*)&Cb[(size_t)(m + 8) * N + n] = packbf(v1.x, v1.y);
            } else {
                *(float2*)&C[(size_t)m * N + n]       = v0;
                *(float2*)&C[(size_t)(m + 8) * N + n] = v1;
            }
        }
    }
}

// ================= single prep kernel: all transposes + bias concat =========
__device__ __forceinline__ void do_transpose_tile(
    const float* W, __nv_bfloat16* Wt, int K, int N, int tilesX, int local)
{
    __shared__ float tt[32][33];
    const int bx = (local % tilesX) * 32;   // n
    const int by = (local / tilesX) * 32;   // k
    const int x = threadIdx.x, y = threadIdx.y;
    #pragma unroll
    for (int j = 0; j < 32; j += 8)
        tt[y + j][x] = W[(size_t)(by + y + j) * N + bx + x];
    __syncthreads();
    #pragma unroll
    for (int j = 0; j < 32; j += 8)
        Wt[(size_t)(bx + y + j) * K + by + x] = __float2bfloat16_rn(tt[x][y + j]);
}

__global__ void prep_kernel(
    const float* __restrict__ W_val, const float* __restrict__ W_off,
    const float* __restrict__ W_attn, const float* __restrict__ W_out,
    const float* __restrict__ W1, const float* __restrict__ W2,
    const float* __restrict__ b_off, const float* __restrict__ b_attn,
    __nv_bfloat16* __restrict__ wvalT, __nv_bfloat16* __restrict__ wqT,
    __nv_bfloat16* __restrict__ woutT, __nv_bfloat16* __restrict__ w1T,
    __nv_bfloat16* __restrict__ w2T, float* __restrict__ bq)
{
    const int b = blockIdx.x;
    if      (b < 64)  do_transpose_tile(W_val,  wvalT,           256, 256,  8,  b);
    else if (b < 128) do_transpose_tile(W_off,  wqT,             256, 256,  8,  b - 64);
    else if (b < 160) do_transpose_tile(W_attn, wqT + 256 * 256, 256, 128,  4,  b - 128);
    else if (b < 224) do_transpose_tile(W_out,  woutT,           256, 256,  8,  b - 160);
    else if (b < 480) do_transpose_tile(W1,     w1T,             256, 1024, 32, b - 224);
    else if (b < 736) do_transpose_tile(W2,     w2T,            1024, 256,  8,  b - 480);
    else {
        const int t = threadIdx.y * 32 + threadIdx.x;   // 0..255
        bq[t] = b_off[t];
        if (t < 128) bq[256 + t] = b_attn[t];
    }
}

// ---------------- fused softmax + deformable bilinear sampling --------------
// Half-warp per (n, q, h); value is HEAD-MAJOR [n][h][pix][32] bf16.
__global__ __launch_bounds__(256)
void sample_kernel(const float* __restrict__ off, const float* __restrict__ attn,
                   const float* __restrict__ ref,
                   const __nv_bfloat16* __restrict__ value,
                   __nv_bfloat16* __restrict__ out)
{
    const int tw   = blockIdx.x * 16 + (threadIdx.x >> 4);
    const int l16  = threadIdx.x & 15;
    const int h = tw & 7;
    const int q = (tw >> 3) & (LQ - 1);
    const int n = tw >> 17;

    const size_t row = (size_t)n * LQ + q;
    const float* ap = attn + row * 128 + h * 16;

    float logits[16];
    float mx = -1e30f;
    #pragma unroll
    for (int i = 0; i < 16; ++i) { logits[i] = ap[i]; mx = fmaxf(mx, logits[i]); }
    float ssum = 0.f;
    #pragma unroll
    for (int i = 0; i < 16; ++i) { logits[i] = __expf(logits[i] - mx); ssum += logits[i]; }
    const float inv = 1.f / ssum;

    const float* op = off + row * 256 + h * 32;
    const float* rp = ref + row * 8;
    // head-major: 16 bf162 per pixel; lane offset l16
    const __nv_bfloat162* vb =
        (const __nv_bfloat162*)value + ((size_t)(n * 8 + h) * LIN) * 16 + l16;

    float2 acc = {0.f, 0.f};
    #pragma unroll
    for (int l = 0; l < N_LEVELS; ++l) {
        const float rx = rp[l * 2 + 0];
        const float ry = rp[l * 2 + 1];
        const int start = l * LQ;
        #pragma unroll
        for (int p = 0; p < N_POINTS; ++p) {
            const float x = fmaf(rx, 128.f, op[l * 8 + p * 2 + 0] - 0.5f);
            const float y = fmaf(ry, 128.f, op[l * 8 + p * 2 + 1] - 0.5f);
            const float x0f = floorf(x), y0f = floorf(y);
            const float wx = x - x0f, wy = y - y0f;
            const int x0 = (int)x0f, y0 = (int)y0f;
            const float aw = logits[l * 4 + p] * inv;

            const bool vx0 = (x0 >= 0) & (x0 < HW);
            const bool vx1 = (x0 + 1 >= 0) & (x0 + 1 < HW);
            const bool vy0 = (y0 >= 0) & (y0 < HW);
            const bool vy1 = (y0 + 1 >= 0) & (y0 + 1 < HW);

            if (vy0) {
                const size_t base = (size_t)(start + y0 * HW) * 16;
                if (vx0) {
                    const float2 f = __bfloat1622float2(vb[base + (size_t)x0 * 16]);
                    const float w = (1.f - wx) * (1.f - wy) * aw;
                    acc.x = fmaf(f.x, w, acc.x); acc.y = fmaf(f.y, w, acc.y);
                }
                if (vx1) {
                    const float2 f = __bfloat1622float2(vb[base + (size_t)(x0 + 1) * 16]);
                    const float w = wx * (1.f - wy) * aw;
                    acc.x = fmaf(f.x, w, acc.x); acc.y = fmaf(f.y, w, acc.y);
                }
            }
            if (vy1) {
                const size_t base = (size_t)(start + (y0 + 1) * HW) * 16;
                if (vx0) {
                    const float2 f = __bfloat1622float2(vb[base + (size_t)x0 * 16]);
                    const float w = (1.f - wx) * wy * aw;
                    acc.x = fmaf(f.x, w, acc.x); acc.y = fmaf(f.y, w, acc.y);
                }
                if (vx1) {
                    const float2 f = __bfloat1622float2(vb[base + (size_t)(x0 + 1) * 16]);
                    const float w = wx * wy * aw;
                    acc.x = fmaf(f.x, w, acc.x); acc.y = fmaf(f.y, w, acc.y);
                }
            }
        }
    }
    *(uint32_t*)&out[row * 256 + h * 32 + l16 * 2] = packbf(acc.x, acc.y);
}

// ---------------- residual add + layernorm (+ optional bf16 twin) -----------
__global__ __launch_bounds__(256)
void add_ln_kernel(const float* __restrict__ a, const float* __restrict__ b,
                   const float* __restrict__ gamma, const float* __restrict__ beta,
                   float* __restrict__ out, __nv_bfloat16* __restrict__ out_b)
{
    const int row = blockIdx.x;
    const int t = threadIdx.x;
    const size_t idx = (size_t)row * 256 + t;
    const float v = a[idx] + b[idx];

    __shared__ float red[8];
    float s = v;
    #pragma unroll
    for (int o = 16; o; o >>= 1) s += __shfl_xor_sync(0xffffffffu, s, o);
    if ((t & 31) == 0) red[t >> 5] = s;
    __syncthreads();
    float mean = 0.f;
    #pragma unroll
    for (int i = 0; i < 8; ++i) mean += red[i];
    mean *= (1.f / 256.f);
    __syncthreads();

    const float d = v - mean;
    float s2 = d * d;
    #pragma unroll
    for (int o = 16; o; o >>= 1) s2 += __shfl_xor_sync(0xffffffffu, s2, o);
    if ((t & 31) == 0) red[t >> 5] = s2;
    __syncthreads();
    float var = 0.f;
    #pragma unroll
    for (int i = 0; i < 8; ++i) var += red[i];
    var *= (1.f / 256.f);

    const float r = d * rsqrtf(var + 1e-5f) * gamma[t] + beta[t];
    out[idx] = r;
    if (out_b) out_b[idx] = __float2bfloat16_rn(r);
}

// ---------------- launch -----------------------------------------------------
extern "C" void kernel_launch(void* const* d_in, const int* in_sizes, int n_in,
                              void* d_out, int out_size)
{
    (void)in_sizes; (void)n_in; (void)out_size;
    const float* cur_src = (const float*)d_in[0];
    const float* src_all = (const float*)d_in[1];
    const float* pos     = (const float*)d_in[2];
    const float* refpts  = (const float*)d_in[3];
    const float* W_off   = (const float*)d_in[6];
    const float* b_off   = (const float*)d_in[7];
    const float* W_attn  = (const float*)d_in[8];
    const float* b_attn  = (const float*)d_in[9];
    const float* W_val   = (const float*)d_in[10];
    const float* b_val   = (const float*)d_in[11];
    const float* W_out   = (const float*)d_in[12];
    const float* b_out   = (const float*)d_in[13];
    const float* gamma1  = (const float*)d_in[14];
    const float* beta1   = (const float*)d_in[15];
    const float* W1      = (const float*)d_in[16];
    const float* b1      = (const float*)d_in[17];
    const float* W2      = (const float*)d_in[18];
    const float* b2      = (const float*)d_in[19];
    const float* gamma2  = (const float*)d_in[20];
    const float* beta2   = (const float*)d_in[21];
    float* out = (float*)d_out;

    float *g_off, *g_attn, *g_src2, *g_src, *g_ffn2, *g_bq;
    __nv_bfloat16 *g_value, *g_samp, *g_srcb, *g_ffnb;
    __nv_bfloat16 *g_wvalT, *g_wqT, *g_woutT, *g_w1T, *g_w2T;
    cudaGetSymbolAddress((void**)&g_value, sc_value);
    cudaGetSymbolAddress((void**)&g_off,   sc_off);
    cudaGetSymbolAddress((void**)&g_attn,  sc_attn);
    cudaGetSymbolAddress((void**)&g_samp,  sc_samp);
    cudaGetSymbolAddress((void**)&g_src2,  sc_src2);
    cudaGetSymbolAddress((void**)&g_src,   sc_src);
    cudaGetSymbolAddress((void**)&g_srcb,  sc_srcb);
    cudaGetSymbolAddress((void**)&g_ffnb,  sc_ffnb);
    cudaGetSymbolAddress((void**)&g_ffn2,  sc_ffn2);
    cudaGetSymbolAddress((void**)&g_wvalT, sc_wvalT);
    cudaGetSymbolAddress((void**)&g_wqT,   sc_wqT);
    cudaGetSymbolAddress((void**)&g_woutT, sc_woutT);
    cudaGetSymbolAddress((void**)&g_w1T,   sc_w1T);
    cudaGetSymbolAddress((void**)&g_w2T,   sc_w2T);
    cudaGetSymbolAddress((void**)&g_bq,    sc_bq);

    // 0. one prep kernel: all weight transposes + bias concat
    prep_kernel<<<737, dim3(32, 8)>>>(W_val, W_off, W_attn, W_out, W1, W2,
                                      b_off, b_attn,
                                      g_wvalT, g_wqT, g_woutT, g_w1T, g_w2T, g_bq);

    // 1. value = bf16(src_all + pos) @ W_val + b_val -> head-major bf16
    bgemm_value<<<dim3(2, ROWS_V / 128), 256>>>(
        src_all, pos, g_wvalT, b_val, g_value, 256);

    // 2. [off | attn] = (cur_src + pos[:,-1]) @ [W_off|W_attn] + [b_off|b_attn]
    bgemm_qa<<<dim3(3, ROWS_Q / 128), 256>>>(
        cur_src, pos, g_wqT, g_bq, g_off, g_attn);

    // 3. fused softmax + deformable bilinear sampling -> bf16
    sample_kernel<<<(BATCH * LQ * N_HEADS) / 16, 256>>>(
        g_off, g_attn, refpts, g_value, g_samp);

    // 4. src2 = samp @ W_out + b_out
    bgemm_b16a<false, false><<<dim3(2, ROWS_Q / 128), 256>>>(
        g_samp, g_woutT, b_out, g_src2, nullptr, ROWS_Q, 256, 256);

    // 5. src = LN(cur_src + src2), bf16 twin for FFN1
    add_ln_kernel<<<ROWS_Q, 256>>>(cur_src, g_src2, gamma1, beta1, g_src, g_srcb);

    // 6. ffn_h = relu(src @ W1 + b1) -> bf16
    bgemm_b16a<true, true><<<dim3(D_FFN / 128, ROWS_Q / 128), 256>>>(
        g_srcb, g_w1T, b1, nullptr, g_ffnb, ROWS_Q, D_FFN, 256);

    // 7. ffn2 = ffn_h @ W2 + b2
    bgemm_b16a<false, false><<<dim3(2, ROWS_Q / 128), 256>>>(
        g_ffnb, g_w2T, b2, g_ffn2, nullptr, ROWS_Q, 256, 1024);

    // 8. out = LN(src + ffn2)
    add_ln_kernel<<<ROWS_Q, 256>>>(g_src, g_ffn2, gamma2, beta2, out, nullptr);
}

// round 11
// speedup vs baseline: 2.0485x; 1.2303x over previous
#include <cuda_runtime.h>
#include <cuda_bf16.h>
#include <cstdint>

// ---------------- problem constants ----------------
#define D_MODEL   256
#define N_HEADS   8
#define HEAD_DIM  32
#define N_LEVELS  4
#define N_POINTS  4
#define D_FFN     1024
#define HW        128
#define LQ        (HW * HW)            // 16384
#define LIN       (N_LEVELS * LQ)      // 65536
#define BATCH     2
#define ROWS_Q    (BATCH * LQ)         // 32768
#define ROWS_V    (BATCH * LIN)        // 131072

// ---------------- scratch (device globals) ---------------------------------
__device__ __align__(256) __nv_bfloat16 sc_value[ROWS_V * D_MODEL]; // head-major
__device__ __align__(256) float         sc_off  [ROWS_Q * D_MODEL];
__device__ __align__(256) float         sc_attn [ROWS_Q * 128];
__device__ __align__(256) __nv_bfloat16 sc_samp [ROWS_Q * D_MODEL];
__device__ __align__(256) float         sc_src2 [ROWS_Q * D_MODEL];
__device__ __align__(256) float         sc_src  [ROWS_Q * D_MODEL];
__device__ __align__(256) __nv_bfloat16 sc_srcb [ROWS_Q * D_MODEL];
__device__ __align__(256) __nv_bfloat16 sc_ffnb [ROWS_Q * D_FFN];
__device__ __align__(256) float         sc_ffn2 [ROWS_Q * D_MODEL];
// bf16 transposed weights Wt[n][k]
__device__ __align__(256) __nv_bfloat16 sc_wvalT[D_MODEL * D_MODEL];
__device__ __align__(256) __nv_bfloat16 sc_wqT  [384 * D_MODEL];      // off(256)+attn(128)
__device__ __align__(256) __nv_bfloat16 sc_woutT[D_MODEL * D_MODEL];
__device__ __align__(256) __nv_bfloat16 sc_w1T  [D_FFN * D_MODEL];
__device__ __align__(256) __nv_bfloat16 sc_w2T  [D_MODEL * D_FFN];
__device__ __align__(256) float         sc_bq   [384];                // b_off ++ b_attn

// ---------------- helpers --------------------------------------------------
__device__ __forceinline__ void mma_bf16(float c[4], const uint32_t a[4],
                                         const uint32_t b[2]) {
    asm volatile(
        "mma.sync.aligned.m16n8k16.row.col.f32.bf16.bf16.f32 "
        "{%0,%1,%2,%3}, {%4,%5,%6,%7}, {%8,%9}, {%0,%1,%2,%3};"
        : "+f"(c[0]), "+f"(c[1]), "+f"(c[2]), "+f"(c[3])
        : "r"(a[0]), "r"(a[1]), "r"(a[2]), "r"(a[3]), "r"(b[0]), "r"(b[1]));
}
__device__ __forceinline__ void cp_async16(void* smem, const void* gmem) {
    const uint32_t s = (uint32_t)__cvta_generic_to_shared(smem);
    asm volatile("cp.async.ca.shared.global [%0], [%1], 16;\n" :: "r"(s), "l"(gmem));
}
__device__ __forceinline__ void cp_commit() {
    asm volatile("cp.async.commit_group;\n");
}
template <int N>
__device__ __forceinline__ void cp_wait() {
    asm volatile("cp.async.wait_group %0;\n" :: "n"(N));
}
__device__ __forceinline__ uint32_t packbf(float x, float y) {
    __nv_bfloat162 p = __floats2bfloat162_rn(x, y);
    return *(uint32_t*)&p;
}
__device__ __forceinline__ float bflo(uint32_t u) { return __uint_as_float(u << 16); }
__device__ __forceinline__ float bfhi(uint32_t u) { return __uint_as_float(u & 0xffff0000u); }

#define BPAD 40   // bf16 row stride: conflict-free frag loads

// ---- warp-tile compute on one smem stage -----------------------------------
__device__ __forceinline__ void gemm_compute_stage(
    const __nv_bfloat16* As, const __nv_bfloat16* Bs,
    float acc[4][4][4], int wm, int wn, int g, int t)
{
    #pragma unroll
    for (int ks = 0; ks < 32; ks += 16) {
        uint32_t af[4][4];
        #pragma unroll
        for (int mt = 0; mt < 4; ++mt) {
            const __nv_bfloat16* p = &As[(wm + mt * 16 + g) * BPAD + ks + 2 * t];
            af[mt][0] = *(const uint32_t*)p;
            af[mt][1] = *(const uint32_t*)(p + 8 * BPAD);
            af[mt][2] = *(const uint32_t*)(p + 8);
            af[mt][3] = *(const uint32_t*)(p + 8 * BPAD + 8);
        }
        uint32_t bf[4][2];
        #pragma unroll
        for (int nt = 0; nt < 4; ++nt) {
            const __nv_bfloat16* p = &Bs[(wn + nt * 8 + g) * BPAD + ks + 2 * t];
            bf[nt][0] = *(const uint32_t*)p;
            bf[nt][1] = *(const uint32_t*)(p + 8);
        }
        #pragma unroll
        for (int mt = 0; mt < 4; ++mt)
            #pragma unroll
            for (int nt = 0; nt < 4; ++nt)
                mma_bf16(acc[mt][nt], af[mt], bf[nt]);
    }
}

// ================= GEMM 1: value projection =================================
// A fp32 + A2 fp32 (same row), out = bf16 HEAD-MAJOR [n][h][pix][32].
__global__ __launch_bounds__(256)
void bgemm_value(const float* __restrict__ A, const float* __restrict__ A2,
                 const __nv_bfloat16* __restrict__ Bt, const float* __restrict__ bias,
                 __nv_bfloat16* __restrict__ Cb, int K)
{
    __shared__ __align__(16) __nv_bfloat16 As[2][128 * BPAD];
    __shared__ __align__(16) __nv_bfloat16 Bs[2][128 * BPAD];

    const int tid  = threadIdx.x;
    const int wid  = tid >> 5;
    const int lane = tid & 31;
    const int g    = lane >> 2;
    const int t    = lane & 3;
    const int bm = blockIdx.y * 128;
    const int bn = blockIdx.x * 128;
    const int wm = (wid & 1) * 64;
    const int wn = (wid >> 1) * 32;

    const int la_r = tid >> 1;
    const int la_c = (tid & 1) * 16;
    const float* a_ptr  = A  + (size_t)(bm + la_r) * K + la_c;
    const float* a2_ptr = A2 + (size_t)(bm + la_r) * K + la_c;

    const int nk = K / 32;

    auto ldgA = [&](int i, uint32_t v[8]) {
        const int k0 = i * 32;
        #pragma unroll
        for (int j = 0; j < 4; ++j) {
            float4 a = *(const float4*)(a_ptr + k0 + j * 4);
            const float4 b = *(const float4*)(a2_ptr + k0 + j * 4);
            a.x += b.x; a.y += b.y; a.z += b.z; a.w += b.w;
            v[2 * j]     = packbf(a.x, a.y);
            v[2 * j + 1] = packbf(a.z, a.w);
        }
    };
    auto stsA = [&](int s, const uint32_t v[8]) {
        uint32_t* p = (uint32_t*)&As[s][la_r * BPAD + la_c];
        *(uint4*)p       = make_uint4(v[0], v[1], v[2], v[3]);
        *(uint4*)(p + 4) = make_uint4(v[4], v[5], v[6], v[7]);
    };
    auto cpB = [&](int s, int i) {
        const int k0 = i * 32;
        #pragma unroll
        for (int j = 0; j < 2; ++j) {
            const int ch = j * 256 + tid;
            const int r  = ch >> 2;
            const int cc = (ch & 3) * 8;
            cp_async16(&Bs[s][r * BPAD + cc], Bt + (size_t)(bn + r) * K + k0 + cc);
        }
    };

    float acc[4][4][4] = {};
    uint32_t rA[8];

    ldgA(0, rA); stsA(0, rA); cpB(0, 0); cp_commit();
    ldgA(1, rA);

    for (int i = 0; i < nk; ++i) {
        cp_wait<0>();
        __syncthreads();
        if (i + 1 < nk) { stsA((i + 1) & 1, rA); cpB((i + 1) & 1, i + 1); cp_commit(); }
        if (i + 2 < nk) ldgA(i + 2, rA);
        gemm_compute_stage(As[i & 1], Bs[i & 1], acc, wm, wn, g, t);
        __syncthreads();
    }

    // epilogue: head-major store
    const int nb  = bm / LIN;              // batch (tile never straddles LIN)
    const int pix0 = bm & (LIN - 1);
    #pragma unroll
    for (int nt = 0; nt < 4; ++nt) {
        const int n = bn + wn + nt * 8 + t * 2;
        const int h = n >> 5, c = n & 31;
        const float bx = bias[n], by = bias[n + 1];
        __nv_bfloat16* hb = Cb + ((size_t)(nb * 8 + h) * LIN) * 32 + c;
        #pragma unroll
        for (int mt = 0; mt < 4; ++mt) {
            const int pix = pix0 + wm + mt * 16 + g;
            *(uint32_t*)&hb[(size_t)pix * 32] =
                packbf(acc[mt][nt][0] + bx, acc[mt][nt][1] + by);
            *(uint32_t*)&hb[(size_t)(pix + 8) * 32] =
                packbf(acc[mt][nt][2] + bx, acc[mt][nt][3] + by);
        }
    }
}

// ================= GEMM 2: fused q-add + off/attn split =====================
__global__ __launch_bounds__(256)
void bgemm_qa(const float* __restrict__ A, const float* __restrict__ A2,
              const __nv_bfloat16* __restrict__ Bt, const float* __restrict__ bias,
              float* __restrict__ Coff, float* __restrict__ Cattn)
{
    const int K = 256;
    __shared__ __align__(16) __nv_bfloat16 As[2][128 * BPAD];
    __shared__ __align__(16) __nv_bfloat16 Bs[2][128 * BPAD];

    const int tid  = threadIdx.x;
    const int wid  = tid >> 5;
    const int lane = tid & 31;
    const int g    = lane >> 2;
    const int t    = lane & 3;
    const int bm = blockIdx.y * 128;
    const int bn = blockIdx.x * 128;
    const int wm = (wid & 1) * 64;
    const int wn = (wid >> 1) * 32;

    const int la_r = tid >> 1;
    const int la_c = (tid & 1) * 16;
    const int r_glob = bm + la_r;
    const int pos_row = r_glob + 49152 * ((r_glob >> 14) + 1);  // pos[:, -1] remap
    const float* a_ptr  = A  + (size_t)r_glob * K + la_c;
    const float* a2_ptr = A2 + (size_t)pos_row * K + la_c;

    const int nk = K / 32;

    auto ldgA = [&](int i, uint32_t v[8]) {
        const int k0 = i * 32;
        #pragma unroll
        for (int j = 0; j < 4; ++j) {
            float4 a = *(const float4*)(a_ptr + k0 + j * 4);
            const float4 b = *(const float4*)(a2_ptr + k0 + j * 4);
            a.x += b.x; a.y += b.y; a.z += b.z; a.w += b.w;
            v[2 * j]     = packbf(a.x, a.y);
            v[2 * j + 1] = packbf(a.z, a.w);
        }
    };
    auto stsA = [&](int s, const uint32_t v[8]) {
        uint32_t* p = (uint32_t*)&As[s][la_r * BPAD + la_c];
        *(uint4*)p       = make_uint4(v[0], v[1], v[2], v[3]);
        *(uint4*)(p + 4) = make_uint4(v[4], v[5], v[6], v[7]);
    };
    auto cpB = [&](int s, int i) {
        const int k0 = i * 32;
        #pragma unroll
        for (int j = 0; j < 2; ++j) {
            const int ch = j * 256 + tid;
            const int r  = ch >> 2;
            const int cc = (ch & 3) * 8;
            cp_async16(&Bs[s][r * BPAD + cc], Bt + (size_t)(bn + r) * K + k0 + cc);
        }
    };

    float acc[4][4][4] = {};
    uint32_t rA[8];

    ldgA(0, rA); stsA(0, rA); cpB(0, 0); cp_commit();
    ldgA(1, rA);

    for (int i = 0; i < nk; ++i) {
        cp_wait<0>();
        __syncthreads();
        if (i + 1 < nk) { stsA((i + 1) & 1, rA); cpB((i + 1) & 1, i + 1); cp_commit(); }
        if (i + 2 < nk) ldgA(i + 2, rA);
        gemm_compute_stage(As[i & 1], Bs[i & 1], acc, wm, wn, g, t);
        __syncthreads();
    }

    const bool is_attn = (bn >= 256);
    float* C = is_attn ? Cattn : Coff;
    const int stride = is_attn ? 128 : 256;
    const int cbase  = is_attn ? bn - 256 : bn;
    #pragma unroll
    for (int nt = 0; nt < 4; ++nt) {
        const int nn = wn + nt * 8 + t * 2;
        const float bx = bias[bn + nn], by = bias[bn + nn + 1];
        #pragma unroll
        for (int mt = 0; mt < 4; ++mt) {
            const int m = bm + wm + mt * 16 + g;
            *(float2*)&C[(size_t)m * stride + cbase + nn] =
                make_float2(acc[mt][nt][0] + bx, acc[mt][nt][1] + by);
            *(float2*)&C[(size_t)(m + 8) * stride + cbase + nn] =
                make_float2(acc[mt][nt][2] + bx, acc[mt][nt][3] + by);
        }
    }
}

// ================= GEMM 3: bf16 A, 3-stage (out-proj / FFN) =================
template <bool RELU, bool BF16_OUT>
__global__ __launch_bounds__(256)
void bgemm_b16a(const __nv_bfloat16* __restrict__ A,
                const __nv_bfloat16* __restrict__ Bt, const float* __restrict__ bias,
                float* __restrict__ C, __nv_bfloat16* __restrict__ Cb,
                int M, int N, int K)
{
    __shared__ __align__(16) __nv_bfloat16 As[3][128 * BPAD];
    __shared__ __align__(16) __nv_bfloat16 Bs[3][128 * BPAD];

    const int tid  = threadIdx.x;
    const int wid  = tid >> 5;
    const int lane = tid & 31;
    const int g    = lane >> 2;
    const int t    = lane & 3;
    const int bm = blockIdx.y * 128;
    const int bn = blockIdx.x * 128;
    const int wm = (wid & 1) * 64;
    const int wn = (wid >> 1) * 32;

    const int nk = K / 32;

    auto load_stage = [&](int s, int i) {
        const int k0 = i * 32;
        #pragma unroll
        for (int j = 0; j < 2; ++j) {
            const int ch = j * 256 + tid;
            const int r  = ch >> 2;
            const int cc = (ch & 3) * 8;
            cp_async16(&As[s][r * BPAD + cc], A  + (size_t)(bm + r) * K + k0 + cc);
            cp_async16(&Bs[s][r * BPAD + cc], Bt + (size_t)(bn + r) * K + k0 + cc);
        }
    };

    float acc[4][4][4] = {};

    load_stage(0, 0); cp_commit();
    load_stage(1, 1); cp_commit();

    for (int i = 0; i < nk; ++i) {
        cp_wait<1>();
        __syncthreads();
        const int nxt = i + 2;
        if (nxt < nk) load_stage(nxt % 3, nxt);
        cp_commit();
        gemm_compute_stage(As[i % 3], Bs[i % 3], acc, wm, wn, g, t);
        __syncthreads();
    }

    #pragma unroll
    for (int nt = 0; nt < 4; ++nt) {
        const int n = bn + wn + nt * 8 + t * 2;
        const float bx = bias[n], by = bias[n + 1];
        #pragma unroll
        for (int mt = 0; mt < 4; ++mt) {
            const int m = bm + wm + mt * 16 + g;
            float2 v0 = { acc[mt][nt][0] + bx, acc[mt][nt][1] + by };
            float2 v1 = { acc[mt][nt][2] + bx, acc[mt][nt][3] + by };
            if (RELU) {
                v0.x = fmaxf(v0.x, 0.f); v0.y = fmaxf(v0.y, 0.f);
                v1.x = fmaxf(v1.x, 0.f); v1.y = fmaxf(v1.y, 0.f);
            }
            if (BF16_OUT) {
                *(uint32_t*)&Cb[(size_t)m * N + n]       = packbf(v0.x, v0.y);
                *(uint32_t*)&Cb[(size_t)(m + 8) * N + n] = packbf(v1.x, v1.y);
            } else {
                *(float2*)&C[(size_t)m * N + n]       = v0;
                *(float2*)&C[(size_t)(m + 8) * N + n] = v1;
            }
        }
    }
}

// ================= single prep kernel: all transposes + bias concat =========
__device__ __forceinline__ void do_transpose_tile(
    const float* W, __nv_bfloat16* Wt, int K, int N, int tilesX, int local)
{
    __shared__ float tt[32][33];
    const int bx = (local % tilesX) * 32;   // n
    const int by = (local / tilesX) * 32;   // k
    const int x = threadIdx.x, y = threadIdx.y;
    #pragma unroll
    for (int j = 0; j < 32; j += 8)
        tt[y + j][x] = W[(size_t)(by + y + j) * N + bx + x];
    __syncthreads();
    #pragma unroll
    for (int j = 0; j < 32; j += 8)
        Wt[(size_t)(bx + y + j) * K + by + x] = __float2bfloat16_rn(tt[x][y + j]);
}

__global__ void prep_kernel(
    const float* __restrict__ W_val, const float* __restrict__ W_off,
    const float* __restrict__ W_attn, const float* __restrict__ W_out,
    const float* __restrict__ W1, const float* __restrict__ W2,
    const float* __restrict__ b_off, const float* __restrict__ b_attn,
    __nv_bfloat16* __restrict__ wvalT, __nv_bfloat16* __restrict__ wqT,
    __nv_bfloat16* __restrict__ woutT, __nv_bfloat16* __restrict__ w1T,
    __nv_bfloat16* __restrict__ w2T, float* __restrict__ bq)
{
    const int b = blockIdx.x;
    if      (b < 64)  do_transpose_tile(W_val,  wvalT,           256, 256,  8,  b);
    else if (b < 128) do_transpose_tile(W_off,  wqT,             256, 256,  8,  b - 64);
    else if (b < 160) do_transpose_tile(W_attn, wqT + 256 * 256, 256, 128,  4,  b - 128);
    else if (b < 224) do_transpose_tile(W_out,  woutT,           256, 256,  8,  b - 160);
    else if (b < 480) do_transpose_tile(W1,     w1T,             256, 1024, 32, b - 224);
    else if (b < 736) do_transpose_tile(W2,     w2T,            1024, 256,  8,  b - 480);
    else {
        const int t = threadIdx.y * 32 + threadIdx.x;   // 0..255
        bq[t] = b_off[t];
        if (t < 128) bq[256 + t] = b_attn[t];
    }
}

// ---------------- fused softmax + deformable bilinear sampling --------------
// Half-warp per (n, q, h). Lane l owns point l's scalar work (softmax via
// width-16 butterflies); point loop broadcasts 6 values/point via shfl and
// does 4 unconditional clamped gathers (invalid corners weighted 0).
__global__ __launch_bounds__(256)
void sample_kernel(const float* __restrict__ off, const float* __restrict__ attn,
                   const float* __restrict__ ref,
                   const __nv_bfloat16* __restrict__ value,
                   __nv_bfloat16* __restrict__ out)
{
    const int tw  = blockIdx.x * 16 + (threadIdx.x >> 4);
    const int l16 = threadIdx.x & 15;
    const int h = tw & 7;
    const int q = (tw >> 3) & (LQ - 1);
    const int n = tw >> 17;
    const size_t row = (size_t)n * LQ + q;

    // ---- lane-parallel point setup: lane l16 owns point p = l16 ----
    const int p  = l16;
    const int lv = p >> 2;

    // softmax over the 16 points (width-16 butterflies)
    const float logit = attn[row * 128 + h * 16 + p];
    float mx = logit;
    #pragma unroll
    for (int o = 8; o; o >>= 1) mx = fmaxf(mx, __shfl_xor_sync(0xffffffffu, mx, o, 16));
    const float e = __expf(logit - mx);
    float ssum = e;
    #pragma unroll
    for (int o = 8; o; o >>= 1) ssum += __shfl_xor_sync(0xffffffffu, ssum, o, 16);
    const float aw = e * (1.f / ssum);

    // coordinates & bilinear weights for point p
    const float2 o2 = *(const float2*)&off[row * 256 + h * 32 + 2 * p];
    const float rx = ref[row * 8 + lv * 2];
    const float ry = ref[row * 8 + lv * 2 + 1];
    const float x = fmaf(rx, 128.f, o2.x - 0.5f);
    const float y = fmaf(ry, 128.f, o2.y - 0.5f);
    const float x0f = floorf(x), y0f = floorf(y);
    const float wx = x - x0f, wy = y - y0f;
    const int x0 = (int)x0f, y0 = (int)y0f;
    const bool vx0 = (x0 >= 0) & (x0 < HW);
    const bool vx1 = (x0 >= -1) & (x0 < HW - 1);
    const bool vy0 = (y0 >= 0) & (y0 < HW);
    const bool vy1 = (y0 >= -1) & (y0 < HW - 1);
    const int x0c = min(max(x0, 0), HW - 1);
    const int x1c = min(max(x0 + 1, 0), HW - 1);
    const int y0c = min(max(y0, 0), HW - 1);
    const int y1c = min(max(y0 + 1, 0), HW - 1);

    // base index in bf162 units within this (n,h) slab; packed corner deltas
    const int idx00 = (lv * LQ + y0c * HW + x0c) * 16;
    const int dpack = ((x1c - x0c) * 16) | (((y1c - y0c) * (HW * 16)) << 16);
    const float w00 = (vx0 & vy0) ? (1.f - wx) * (1.f - wy) * aw : 0.f;
    const float w01 = (vx1 & vy0) ? wx * (1.f - wy) * aw : 0.f;
    const float w10 = (vx0 & vy1) ? (1.f - wx) * wy * aw : 0.f;
    const float w11 = (vx1 & vy1) ? wx * wy * aw : 0.f;

    const uint32_t* vb =
        (const uint32_t*)value + ((size_t)(n * 8 + h) * LIN) * 16 + l16;

    float2 acc = {0.f, 0.f};
    #pragma unroll
    for (int pp = 0; pp < 16; ++pp) {
        const int   ib  = __shfl_sync(0xffffffffu, idx00, pp, 16);
        const int   dp  = __shfl_sync(0xffffffffu, dpack, pp, 16);
        const float a00 = __shfl_sync(0xffffffffu, w00, pp, 16);
        const float a01 = __shfl_sync(0xffffffffu, w01, pp, 16);
        const float a10 = __shfl_sync(0xffffffffu, w10, pp, 16);
        const float a11 = __shfl_sync(0xffffffffu, w11, pp, 16);
        const int dx = dp & 0xffff;
        const int dy = dp >> 16;
        const uint32_t u00 = vb[ib];
        const uint32_t u01 = vb[ib + dx];
        const uint32_t u10 = vb[ib + dy];
        const uint32_t u11 = vb[ib + dy + dx];
        acc.x = fmaf(bflo(u00), a00, acc.x); acc.y = fmaf(bfhi(u00), a00, acc.y);
        acc.x = fmaf(bflo(u01), a01, acc.x); acc.y = fmaf(bfhi(u01), a01, acc.y);
        acc.x = fmaf(bflo(u10), a10, acc.x); acc.y = fmaf(bfhi(u10), a10, acc.y);
        acc.x = fmaf(bflo(u11), a11, acc.x); acc.y = fmaf(bfhi(u11), a11, acc.y);
    }
    *(uint32_t*)&out[row * 256 + h * 32 + l16 * 2] = packbf(acc.x, acc.y);
}

// ---------------- residual add + layernorm (+ optional bf16 twin) -----------
__global__ __launch_bounds__(256)
void add_ln_kernel(const float* __restrict__ a, const float* __restrict__ b,
                   const float* __restrict__ gamma, const float* __restrict__ beta,
                   float* __restrict__ out, __nv_bfloat16* __restrict__ out_b)
{
    const int row = blockIdx.x;
    const int t = threadIdx.x;
    const size_t idx = (size_t)row * 256 + t;
    const float v = a[idx] + b[idx];

    __shared__ float red[8];
    float s = v;
    #pragma unroll
    for (int o = 16; o; o >>= 1) s += __shfl_xor_sync(0xffffffffu, s, o);
    if ((t & 31) == 0) red[t >> 5] = s;
    __syncthreads();
    float mean = 0.f;
    #pragma unroll
    for (int i = 0; i < 8; ++i) mean += red[i];
    mean *= (1.f / 256.f);
    __syncthreads();

    const float d = v - mean;
    float s2 = d * d;
    #pragma unroll
    for (int o = 16; o; o >>= 1) s2 += __shfl_xor_sync(0xffffffffu, s2, o);
    if ((t & 31) == 0) red[t >> 5] = s2;
    __syncthreads();
    float var = 0.f;
    #pragma unroll
    for (int i = 0; i < 8; ++i) var += red[i];
    var *= (1.f / 256.f);

    const float r = d * rsqrtf(var + 1e-5f) * gamma[t] + beta[t];
    out[idx] = r;
    if (out_b) out_b[idx] = __float2bfloat16_rn(r);
}

// ---------------- launch -----------------------------------------------------
extern "C" void kernel_launch(void* const* d_in, const int* in_sizes, int n_in,
                              void* d_out, int out_size)
{
    (void)in_sizes; (void)n_in; (void)out_size;
    const float* cur_src = (const float*)d_in[0];
    const float* src_all = (const float*)d_in[1];
    const float* pos     = (const float*)d_in[2];
    const float* refpts  = (const float*)d_in[3];
    const float* W_off   = (const float*)d_in[6];
    const float* b_off   = (const float*)d_in[7];
    const float* W_attn  = (const float*)d_in[8];
    const float* b_attn  = (const float*)d_in[9];
    const float* W_val   = (const float*)d_in[10];
    const float* b_val   = (const float*)d_in[11];
    const float* W_out   = (const float*)d_in[12];
    const float* b_out   = (const float*)d_in[13];
    const float* gamma1  = (const float*)d_in[14];
    const float* beta1   = (const float*)d_in[15];
    const float* W1      = (const float*)d_in[16];
    const float* b1      = (const float*)d_in[17];
    const float* W2      = (const float*)d_in[18];
    const float* b2      = (const float*)d_in[19];
    const float* gamma2  = (const float*)d_in[20];
    const float* beta2   = (const float*)d_in[21];
    float* out = (float*)d_out;

    float *g_off, *g_attn, *g_src2, *g_src, *g_ffn2, *g_bq;
    __nv_bfloat16 *g_value, *g_samp, *g_srcb, *g_ffnb;
    __nv_bfloat16 *g_wvalT, *g_wqT, *g_woutT, *g_w1T, *g_w2T;
    cudaGetSymbolAddress((void**)&g_value, sc_value);
    cudaGetSymbolAddress((void**)&g_off,   sc_off);
    cudaGetSymbolAddress((void**)&g_attn,  sc_attn);
    cudaGetSymbolAddress((void**)&g_samp,  sc_samp);
    cudaGetSymbolAddress((void**)&g_src2,  sc_src2);
    cudaGetSymbolAddress((void**)&g_src,   sc_src);
    cudaGetSymbolAddress((void**)&g_srcb,  sc_srcb);
    cudaGetSymbolAddress((void**)&g_ffnb,  sc_ffnb);
    cudaGetSymbolAddress((void**)&g_ffn2,  sc_ffn2);
    cudaGetSymbolAddress((void**)&g_wvalT, sc_wvalT);
    cudaGetSymbolAddress((void**)&g_wqT,   sc_wqT);
    cudaGetSymbolAddress((void**)&g_woutT, sc_woutT);
    cudaGetSymbolAddress((void**)&g_w1T,   sc_w1T);
    cudaGetSymbolAddress((void**)&g_w2T,   sc_w2T);
    cudaGetSymbolAddress((void**)&g_bq,    sc_bq);

    // 0. one prep kernel: all weight transposes + bias concat
    prep_kernel<<<737, dim3(32, 8)>>>(W_val, W_off, W_attn, W_out, W1, W2,
                                      b_off, b_attn,
                                      g_wvalT, g_wqT, g_woutT, g_w1T, g_w2T, g_bq);

    // 1. value = bf16(src_all + pos) @ W_val + b_val -> head-major bf16
    bgemm_value<<<dim3(2, ROWS_V / 128), 256>>>(
        src_all, pos, g_wvalT, b_val, g_value, 256);

    // 2. [off | attn] = (cur_src + pos[:,-1]) @ [W_off|W_attn] + [b_off|b_attn]
    bgemm_qa<<<dim3(3, ROWS_Q / 128), 256>>>(
        cur_src, pos, g_wqT, g_bq, g_off, g_attn);

    // 3. fused softmax + deformable bilinear sampling -> bf16
    sample_kernel<<<(BATCH * LQ * N_HEADS) / 16, 256>>>(
        g_off, g_attn, refpts, g_value, g_samp);

    // 4. src2 = samp @ W_out + b_out
    bgemm_b16a<false, false><<<dim3(2, ROWS_Q / 128), 256>>>(
        g_samp, g_woutT, b_out, g_src2, nullptr, ROWS_Q, 256, 256);

    // 5. src = LN(cur_src + src2), bf16 twin for FFN1
    add_ln_kernel<<<ROWS_Q, 256>>>(cur_src, g_src2, gamma1, beta1, g_src, g_srcb);

    // 6. ffn_h = relu(src @ W1 + b1) -> bf16
    bgemm_b16a<true, true><<<dim3(D_FFN / 128, ROWS_Q / 128), 256>>>(
        g_srcb, g_w1T, b1, nullptr, g_ffnb, ROWS_Q, D_FFN, 256);

    // 7. ffn2 = ffn_h @ W2 + b2
    bgemm_b16a<false, false><<<dim3(2, ROWS_Q / 128), 256>>>(
        g_ffnb, g_w2T, b2, g_ffn2, nullptr, ROWS_Q, 256, 1024);

    // 8. out = LN(src + ffn2)
    add_ln_kernel<<<ROWS_Q, 256>>>(g_src, g_ffn2, gamma2, beta2, out, nullptr);
}

// round 12
// speedup vs baseline: 2.0740x; 1.0125x over previous
#include <cuda_runtime.h>
#include <cuda_bf16.h>
#include <cstdint>

// ---------------- problem constants ----------------
#define D_MODEL   256
#define N_HEADS   8
#define HEAD_DIM  32
#define N_LEVELS  4
#define N_POINTS  4
#define D_FFN     1024
#define HW        128
#define LQ        (HW * HW)            // 16384
#define LIN       (N_LEVELS * LQ)      // 65536
#define BATCH     2
#define ROWS_Q    (BATCH * LQ)         // 32768
#define ROWS_V    (BATCH * LIN)        // 131072

// ---------------- scratch (device globals) ---------------------------------
__device__ __align__(256) __nv_bfloat16 sc_value[ROWS_V * D_MODEL]; // head-major
__device__ __align__(256) float         sc_off  [ROWS_Q * D_MODEL];
__device__ __align__(256) float         sc_attn [ROWS_Q * 128];
__device__ __align__(256) __nv_bfloat16 sc_samp [ROWS_Q * D_MODEL];
__device__ __align__(256) float         sc_src2 [ROWS_Q * D_MODEL];
__device__ __align__(256) float         sc_src  [ROWS_Q * D_MODEL];
__device__ __align__(256) __nv_bfloat16 sc_srcb [ROWS_Q * D_MODEL];
__device__ __align__(256) __nv_bfloat16 sc_ffnb [ROWS_Q * D_FFN];
__device__ __align__(256) float         sc_ffn2 [ROWS_Q * D_MODEL];
// bf16 transposed weights Wt[n][k]
__device__ __align__(256) __nv_bfloat16 sc_wvalT[D_MODEL * D_MODEL];
__device__ __align__(256) __nv_bfloat16 sc_wqT  [384 * D_MODEL];      // off(256)+attn(128)
__device__ __align__(256) __nv_bfloat16 sc_woutT[D_MODEL * D_MODEL];
__device__ __align__(256) __nv_bfloat16 sc_w1T  [D_FFN * D_MODEL];
__device__ __align__(256) __nv_bfloat16 sc_w2T  [D_MODEL * D_FFN];
__device__ __align__(256) float         sc_bq   [384];                // b_off ++ b_attn

// ---------------- helpers --------------------------------------------------
__device__ __forceinline__ void mma_bf16(float c[4], const uint32_t a[4],
                                         const uint32_t b[2]) {
    asm volatile(
        "mma.sync.aligned.m16n8k16.row.col.f32.bf16.bf16.f32 "
        "{%0,%1,%2,%3}, {%4,%5,%6,%7}, {%8,%9}, {%0,%1,%2,%3};"
        : "+f"(c[0]), "+f"(c[1]), "+f"(c[2]), "+f"(c[3])
        : "r"(a[0]), "r"(a[1]), "r"(a[2]), "r"(a[3]), "r"(b[0]), "r"(b[1]));
}
__device__ __forceinline__ void cp_async16(void* smem, const void* gmem) {
    const uint32_t s = (uint32_t)__cvta_generic_to_shared(smem);
    asm volatile("cp.async.ca.shared.global [%0], [%1], 16;\n" :: "r"(s), "l"(gmem));
}
__device__ __forceinline__ void cp_commit() {
    asm volatile("cp.async.commit_group;\n");
}
template <int N>
__device__ __forceinline__ void cp_wait() {
    asm volatile("cp.async.wait_group %0;\n" :: "n"(N));
}
__device__ __forceinline__ uint32_t packbf(float x, float y) {
    __nv_bfloat162 p = __floats2bfloat162_rn(x, y);
    return *(uint32_t*)&p;
}
__device__ __forceinline__ float bflo(uint32_t u) { return __uint_as_float(u << 16); }
__device__ __forceinline__ float bfhi(uint32_t u) { return __uint_as_float(u & 0xffff0000u); }

#define BPAD 40   // bf16 row stride (BK=32 tiles): conflict-free frag loads
#define BPAD64 72 // bf16 row stride (BK=64 tiles): r*36+t mod 32 all distinct

// ---- warp-tile compute on one smem stage (PITCH in bf16 elements) ----------
template <int PITCH, int BK>
__device__ __forceinline__ void gemm_compute_stage(
    const __nv_bfloat16* As, const __nv_bfloat16* Bs,
    float acc[4][4][4], int wm, int wn, int g, int t)
{
    #pragma unroll
    for (int ks = 0; ks < BK; ks += 16) {
        uint32_t af[4][4];
        #pragma unroll
        for (int mt = 0; mt < 4; ++mt) {
            const __nv_bfloat16* p = &As[(wm + mt * 16 + g) * PITCH + ks + 2 * t];
            af[mt][0] = *(const uint32_t*)p;
            af[mt][1] = *(const uint32_t*)(p + 8 * PITCH);
            af[mt][2] = *(const uint32_t*)(p + 8);
            af[mt][3] = *(const uint32_t*)(p + 8 * PITCH + 8);
        }
        uint32_t bf[4][2];
        #pragma unroll
        for (int nt = 0; nt < 4; ++nt) {
            const __nv_bfloat16* p = &Bs[(wn + nt * 8 + g) * PITCH + ks + 2 * t];
            bf[nt][0] = *(const uint32_t*)p;
            bf[nt][1] = *(const uint32_t*)(p + 8);
        }
        #pragma unroll
        for (int mt = 0; mt < 4; ++mt)
            #pragma unroll
            for (int nt = 0; nt < 4; ++nt)
                mma_bf16(acc[mt][nt], af[mt], bf[nt]);
    }
}

// ================= GEMM 1: value projection =================================
// A fp32 + A2 fp32 (same row), out = bf16 HEAD-MAJOR [n][h][pix][32].
__global__ __launch_bounds__(256)
void bgemm_value(const float* __restrict__ A, const float* __restrict__ A2,
                 const __nv_bfloat16* __restrict__ Bt, const float* __restrict__ bias,
                 __nv_bfloat16* __restrict__ Cb, int K)
{
    __shared__ __align__(16) __nv_bfloat16 As[2][128 * BPAD];
    __shared__ __align__(16) __nv_bfloat16 Bs[2][128 * BPAD];

    const int tid  = threadIdx.x;
    const int wid  = tid >> 5;
    const int lane = tid & 31;
    const int g    = lane >> 2;
    const int t    = lane & 3;
    const int bm = blockIdx.y * 128;
    const int bn = blockIdx.x * 128;
    const int wm = (wid & 1) * 64;
    const int wn = (wid >> 1) * 32;

    const int la_r = tid >> 1;
    const int la_c = (tid & 1) * 16;
    const float* a_ptr  = A  + (size_t)(bm + la_r) * K + la_c;
    const float* a2_ptr = A2 + (size_t)(bm + la_r) * K + la_c;

    const int nk = K / 32;

    auto ldgA = [&](int i, uint32_t v[8]) {
        const int k0 = i * 32;
        #pragma unroll
        for (int j = 0; j < 4; ++j) {
            float4 a = *(const float4*)(a_ptr + k0 + j * 4);
            const float4 b = *(const float4*)(a2_ptr + k0 + j * 4);
            a.x += b.x; a.y += b.y; a.z += b.z; a.w += b.w;
            v[2 * j]     = packbf(a.x, a.y);
            v[2 * j + 1] = packbf(a.z, a.w);
        }
    };
    auto stsA = [&](int s, const uint32_t v[8]) {
        uint32_t* p = (uint32_t*)&As[s][la_r * BPAD + la_c];
        *(uint4*)p       = make_uint4(v[0], v[1], v[2], v[3]);
        *(uint4*)(p + 4) = make_uint4(v[4], v[5], v[6], v[7]);
    };
    auto cpB = [&](int s, int i) {
        const int k0 = i * 32;
        #pragma unroll
        for (int j = 0; j < 2; ++j) {
            const int ch = j * 256 + tid;
            const int r  = ch >> 2;
            const int cc = (ch & 3) * 8;
            cp_async16(&Bs[s][r * BPAD + cc], Bt + (size_t)(bn + r) * K + k0 + cc);
        }
    };

    float acc[4][4][4] = {};
    uint32_t rA[8];

    ldgA(0, rA); stsA(0, rA); cpB(0, 0); cp_commit();
    ldgA(1, rA);

    for (int i = 0; i < nk; ++i) {
        cp_wait<0>();
        __syncthreads();
        if (i + 1 < nk) { stsA((i + 1) & 1, rA); cpB((i + 1) & 1, i + 1); cp_commit(); }
        if (i + 2 < nk) ldgA(i + 2, rA);
        gemm_compute_stage<BPAD, 32>(As[i & 1], Bs[i & 1], acc, wm, wn, g, t);
        __syncthreads();
    }

    // epilogue: head-major store
    const int nb  = bm / LIN;              // batch (tile never straddles LIN)
    const int pix0 = bm & (LIN - 1);
    #pragma unroll
    for (int nt = 0; nt < 4; ++nt) {
        const int n = bn + wn + nt * 8 + t * 2;
        const int h = n >> 5, c = n & 31;
        const float bx = bias[n], by = bias[n + 1];
        __nv_bfloat16* hb = Cb + ((size_t)(nb * 8 + h) * LIN) * 32 + c;
        #pragma unroll
        for (int mt = 0; mt < 4; ++mt) {
            const int pix = pix0 + wm + mt * 16 + g;
            *(uint32_t*)&hb[(size_t)pix * 32] =
                packbf(acc[mt][nt][0] + bx, acc[mt][nt][1] + by);
            *(uint32_t*)&hb[(size_t)(pix + 8) * 32] =
                packbf(acc[mt][nt][2] + bx, acc[mt][nt][3] + by);
        }
    }
}

// ================= GEMM 2: fused q-add + off/attn split =====================
__global__ __launch_bounds__(256)
void bgemm_qa(const float* __restrict__ A, const float* __restrict__ A2,
              const __nv_bfloat16* __restrict__ Bt, const float* __restrict__ bias,
              float* __restrict__ Coff, float* __restrict__ Cattn)
{
    const int K = 256;
    __shared__ __align__(16) __nv_bfloat16 As[2][128 * BPAD];
    __shared__ __align__(16) __nv_bfloat16 Bs[2][128 * BPAD];

    const int tid  = threadIdx.x;
    const int wid  = tid >> 5;
    const int lane = tid & 31;
    const int g    = lane >> 2;
    const int t    = lane & 3;
    const int bm = blockIdx.y * 128;
    const int bn = blockIdx.x * 128;
    const int wm = (wid & 1) * 64;
    const int wn = (wid >> 1) * 32;

    const int la_r = tid >> 1;
    const int la_c = (tid & 1) * 16;
    const int r_glob = bm + la_r;
    const int pos_row = r_glob + 49152 * ((r_glob >> 14) + 1);  // pos[:, -1] remap
    const float* a_ptr  = A  + (size_t)r_glob * K + la_c;
    const float* a2_ptr = A2 + (size_t)pos_row * K + la_c;

    const int nk = K / 32;

    auto ldgA = [&](int i, uint32_t v[8]) {
        const int k0 = i * 32;
        #pragma unroll
        for (int j = 0; j < 4; ++j) {
            float4 a = *(const float4*)(a_ptr + k0 + j * 4);
            const float4 b = *(const float4*)(a2_ptr + k0 + j * 4);
            a.x += b.x; a.y += b.y; a.z += b.z; a.w += b.w;
            v[2 * j]     = packbf(a.x, a.y);
            v[2 * j + 1] = packbf(a.z, a.w);
        }
    };
    auto stsA = [&](int s, const uint32_t v[8]) {
        uint32_t* p = (uint32_t*)&As[s][la_r * BPAD + la_c];
        *(uint4*)p       = make_uint4(v[0], v[1], v[2], v[3]);
        *(uint4*)(p + 4) = make_uint4(v[4], v[5], v[6], v[7]);
    };
    auto cpB = [&](int s, int i) {
        const int k0 = i * 32;
        #pragma unroll
        for (int j = 0; j < 2; ++j) {
            const int ch = j * 256 + tid;
            const int r  = ch >> 2;
            const int cc = (ch & 3) * 8;
            cp_async16(&Bs[s][r * BPAD + cc], Bt + (size_t)(bn + r) * K + k0 + cc);
        }
    };

    float acc[4][4][4] = {};
    uint32_t rA[8];

    ldgA(0, rA); stsA(0, rA); cpB(0, 0); cp_commit();
    ldgA(1, rA);

    for (int i = 0; i < nk; ++i) {
        cp_wait<0>();
        __syncthreads();
        if (i + 1 < nk) { stsA((i + 1) & 1, rA); cpB((i + 1) & 1, i + 1); cp_commit(); }
        if (i + 2 < nk) ldgA(i + 2, rA);
        gemm_compute_stage<BPAD, 32>(As[i & 1], Bs[i & 1], acc, wm, wn, g, t);
        __syncthreads();
    }

    const bool is_attn = (bn >= 256);
    float* C = is_attn ? Cattn : Coff;
    const int stride = is_attn ? 128 : 256;
    const int cbase  = is_attn ? bn - 256 : bn;
    #pragma unroll
    for (int nt = 0; nt < 4; ++nt) {
        const int nn = wn + nt * 8 + t * 2;
        const float bx = bias[bn + nn], by = bias[bn + nn + 1];
        #pragma unroll
        for (int mt = 0; mt < 4; ++mt) {
            const int m = bm + wm + mt * 16 + g;
            *(float2*)&C[(size_t)m * stride + cbase + nn] =
                make_float2(acc[mt][nt][0] + bx, acc[mt][nt][1] + by);
            *(float2*)&C[(size_t)(m + 8) * stride + cbase + nn] =
                make_float2(acc[mt][nt][2] + bx, acc[mt][nt][3] + by);
        }
    }
}

// ================= GEMM 3: bf16 A, BK=64 2-stage (out-proj / FFN) ===========
template <bool RELU, bool BF16_OUT>
__global__ __launch_bounds__(256)
void bgemm_b16a(const __nv_bfloat16* __restrict__ A,
                const __nv_bfloat16* __restrict__ Bt, const float* __restrict__ bias,
                float* __restrict__ C, __nv_bfloat16* __restrict__ Cb,
                int M, int N, int K)
{
    __shared__ __align__(16) __nv_bfloat16 As[2][128 * BPAD64];
    __shared__ __align__(16) __nv_bfloat16 Bs[2][128 * BPAD64];

    const int tid  = threadIdx.x;
    const int wid  = tid >> 5;
    const int lane = tid & 31;
    const int g    = lane >> 2;
    const int t    = lane & 3;
    const int bm = blockIdx.y * 128;
    const int bn = blockIdx.x * 128;
    const int wm = (wid & 1) * 64;
    const int wn = (wid >> 1) * 32;

    const int nk = K / 64;

    auto load_stage = [&](int s, int i) {
        const int k0 = i * 64;
        #pragma unroll
        for (int j = 0; j < 4; ++j) {
            const int ch = j * 256 + tid;          // 1024 chunks of 16B (A+B each)
            const int r  = ch >> 3;                // 0..127
            const int cc = (ch & 7) * 8;           // 0..56
            cp_async16(&As[s][r * BPAD64 + cc], A  + (size_t)(bm + r) * K + k0 + cc);
            cp_async16(&Bs[s][r * BPAD64 + cc], Bt + (size_t)(bn + r) * K + k0 + cc);
        }
    };

    float acc[4][4][4] = {};

    load_stage(0, 0); cp_commit();

    for (int i = 0; i < nk; ++i) {
        if (i + 1 < nk) {
            load_stage((i + 1) & 1, i + 1);
            cp_commit();
            cp_wait<1>();
        } else {
            cp_wait<0>();
        }
        __syncthreads();
        gemm_compute_stage<BPAD64, 64>(As[i & 1], Bs[i & 1], acc, wm, wn, g, t);
        __syncthreads();
    }

    #pragma unroll
    for (int nt = 0; nt < 4; ++nt) {
        const int n = bn + wn + nt * 8 + t * 2;
        const float bx = bias[n], by = bias[n + 1];
        #pragma unroll
        for (int mt = 0; mt < 4; ++mt) {
            const int m = bm + wm + mt * 16 + g;
            float2 v0 = { acc[mt][nt][0] + bx, acc[mt][nt][1] + by };
            float2 v1 = { acc[mt][nt][2] + bx, acc[mt][nt][3] + by };
            if (RELU) {
                v0.x = fmaxf(v0.x, 0.f); v0.y = fmaxf(v0.y, 0.f);
                v1.x = fmaxf(v1.x, 0.f); v1.y = fmaxf(v1.y, 0.f);
            }
            if (BF16_OUT) {
                *(uint32_t*)&Cb[(size_t)m * N + n]       = packbf(v0.x, v0.y);
                *(uint32_t*)&Cb[(size_t)(m + 8) * N + n] = packbf(v1.x, v1.y);
            } else {
                *(float2*)&C[(size_t)m * N + n]       = v0;
                *(float2*)&C[(size_t)(m + 8) * N + n] = v1;
            }
        }
    }
}

// ================= single prep kernel: all transposes + bias concat =========
__device__ __forceinline__ void do_transpose_tile(
    const float* W, __nv_bfloat16* Wt, int K, int N, int tilesX, int local)
{
    __shared__ float tt[32][33];
    const int bx = (local % tilesX) * 32;   // n
    const int by = (local / tilesX) * 32;   // k
    const int x = threadIdx.x, y = threadIdx.y;
    #pragma unroll
    for (int j = 0; j < 32; j += 8)
        tt[y + j][x] = W[(size_t)(by + y + j) * N + bx + x];
    __syncthreads();
    #pragma unroll
    for (int j = 0; j < 32; j += 8)
        Wt[(size_t)(bx + y + j) * K + by + x] = __float2bfloat16_rn(tt[x][y + j]);
}

__global__ void prep_kernel(
    const float* __restrict__ W_val, const float* __restrict__ W_off,
    const float* __restrict__ W_attn, const float* __restrict__ W_out,
    const float* __restrict__ W1, const float* __restrict__ W2,
    const float* __restrict__ b_off, const float* __restrict__ b_attn,
    __nv_bfloat16* __restrict__ wvalT, __nv_bfloat16* __restrict__ wqT,
    __nv_bfloat16* __restrict__ woutT, __nv_bfloat16* __restrict__ w1T,
    __nv_bfloat16* __restrict__ w2T, float* __restrict__ bq)
{
    const int b = blockIdx.x;
    if      (b < 64)  do_transpose_tile(W_val,  wvalT,           256, 256,  8,  b);
    else if (b < 128) do_transpose_tile(W_off,  wqT,             256, 256,  8,  b - 64);
    else if (b < 160) do_transpose_tile(W_attn, wqT + 256 * 256, 256, 128,  4,  b - 128);
    else if (b < 224) do_transpose_tile(W_out,  woutT,           256, 256,  8,  b - 160);
    else if (b < 480) do_transpose_tile(W1,     w1T,             256, 1024, 32, b - 224);
    else if (b < 736) do_transpose_tile(W2,     w2T,            1024, 256,  8,  b - 480);
    else {
        const int t = threadIdx.y * 32 + threadIdx.x;   // 0..255
        bq[t] = b_off[t];
        if (t < 128) bq[256 + t] = b_attn[t];
    }
}

// ---------------- fused softmax + deformable bilinear sampling --------------
// Half-warp per (n, q, h). Lane l owns point l's scalars; gathers are paired
// LDG.64 over adjacent x-corner pixels (lane groups 0-7/8-15 own slot 0/1);
// slot weights algebraically absorb clamping + validity. One xor-8 merge.
__global__ __launch_bounds__(256)
void sample_kernel(const float* __restrict__ off, const float* __restrict__ attn,
                   const float* __restrict__ ref,
                   const __nv_bfloat16* __restrict__ value,
                   __nv_bfloat16* __restrict__ out)
{
    const int tw  = blockIdx.x * 16 + (threadIdx.x >> 4);
    const int l16 = threadIdx.x & 15;
    const int h = tw & 7;
    const int q = (tw >> 3) & (LQ - 1);
    const int n = tw >> 17;
    const size_t row = (size_t)n * LQ + q;

    // ---- lane-parallel point setup: lane l16 owns point p = l16 ----
    const int p  = l16;
    const int lv = p >> 2;

    // softmax over 16 points (width-16 butterflies)
    const float logit = attn[row * 128 + h * 16 + p];
    float mx = logit;
    #pragma unroll
    for (int o = 8; o; o >>= 1) mx = fmaxf(mx, __shfl_xor_sync(0xffffffffu, mx, o, 16));
    const float e = __expf(logit - mx);
    float ssum = e;
    #pragma unroll
    for (int o = 8; o; o >>= 1) ssum += __shfl_xor_sync(0xffffffffu, ssum, o, 16);
    const float aw = e * (1.f / ssum);

    // coordinates & weights for point p
    const float2 o2 = *(const float2*)&off[row * 256 + h * 32 + 2 * p];
    const float rx = ref[row * 8 + lv * 2];
    const float ry = ref[row * 8 + lv * 2 + 1];
    const float x = fmaf(rx, 128.f, o2.x - 0.5f);
    const float y = fmaf(ry, 128.f, o2.y - 0.5f);
    const float x0f = floorf(x), y0f = floorf(y);
    const float wx = x - x0f, wy = y - y0f;
    const int x0 = (int)x0f, y0 = (int)y0f;

    // x: corner weights + slot assignment under clamped pair base b in [0,126]
    const float sA = (x0 >= 0 && x0 < HW) ? (1.f - wx) : 0.f;      // corner x0
    const float sB = (x0 >= -1 && x0 < HW - 1) ? wx : 0.f;          // corner x0+1
    const int   b  = min(max(x0, 0), HW - 2);
    float s0, s1;
    if (x0 >= 0) { s0 = sA; s1 = sB; } else { s0 = sB; s1 = 0.f; }
    if (x0 >= HW - 1) { s0 = 0.f; s1 = sA; }

    // y: row weights + clamped rows
    const float r0 = (y0 >= 0 && y0 < HW) ? (1.f - wy) : 0.f;
    const float r1 = (y0 >= -1 && y0 < HW - 1) ? wy : 0.f;
    const int y0c = min(max(y0, 0), HW - 1);
    const int y1c = min(max(y0 + 1, 0), HW - 1);

    const float q00 = aw * r0 * s0, q01 = aw * r0 * s1;
    const float q10 = aw * r1 * s0, q11 = aw * r1 * s1;
    // packed index: word offset of pix(b) in row y0c | dy flag at bit 28
    const int ipack = ((lv * LQ + y0c * HW + b) * 16) | ((y1c - y0c) << 28);

    const uint32_t* vbw =
        (const uint32_t*)value + ((size_t)(n * 8 + h) * LIN) * 16;
    const int lw = 2 * l16;     // lane's word pair offset within the 128B pair

    float a0 = 0.f, a1 = 0.f, a2 = 0.f, a3 = 0.f;
    #pragma unroll
    for (int pp = 0; pp < 16; ++pp) {
        const int   ip  = __shfl_sync(0xffffffffu, ipack, pp, 16);
        const float b00 = __shfl_sync(0xffffffffu, q00, pp, 16);
        const float b01 = __shfl_sync(0xffffffffu, q01, pp, 16);
        const float b10 = __shfl_sync(0xffffffffu, q10, pp, 16);
        const float b11 = __shfl_sync(0xffffffffu, q11, pp, 16);
        const int ib = ip & 0x0FFFFFFF;
        const int dy = (ip >> 28) << 11;           // 0 or 2048 words
        const float wtop = (l16 < 8) ? b00 : b01;
        const float wbot = (l16 < 8) ? b10 : b11;
        const uint2 v0 = *(const uint2*)(vbw + ib + lw);
        const uint2 v1 = *(const uint2*)(vbw + ib + dy + lw);
        a0 = fmaf(bflo(v0.x), wtop, a0); a1 = fmaf(bfhi(v0.x), wtop, a1);
        a2 = fmaf(bflo(v0.y), wtop, a2); a3 = fmaf(bfhi(v0.y), wtop, a3);
        a0 = fmaf(bflo(v1.x), wbot, a0); a1 = fmaf(bfhi(v1.x), wbot, a1);
        a2 = fmaf(bflo(v1.y), wbot, a2); a3 = fmaf(bfhi(v1.y), wbot, a3);
    }
    // merge the two pixel-slot halves: channels 4j..4j+3 = lane j + lane j+8
    a0 += __shfl_xor_sync(0xffffffffu, a0, 8, 16);
    a1 += __shfl_xor_sync(0xffffffffu, a1, 8, 16);
    a2 += __shfl_xor_sync(0xffffffffu, a2, 8, 16);
    a3 += __shfl_xor_sync(0xffffffffu, a3, 8, 16);

    if (l16 < 8) {
        uint2 w = { packbf(a0, a1), packbf(a2, a3) };
        *((uint2*)(out + row * 256 + h * 32) + l16) = w;
    }
}

// ---------------- residual add + layernorm (+ optional bf16 twin) -----------
__global__ __launch_bounds__(256)
void add_ln_kernel(const float* __restrict__ a, const float* __restrict__ b,
                   const float* __restrict__ gamma, const float* __restrict__ beta,
                   float* __restrict__ out, __nv_bfloat16* __restrict__ out_b)
{
    const int row = blockIdx.x;
    const int t = threadIdx.x;
    const size_t idx = (size_t)row * 256 + t;
    const float v = a[idx] + b[idx];

    __shared__ float red[8];
    float s = v;
    #pragma unroll
    for (int o = 16; o; o >>= 1) s += __shfl_xor_sync(0xffffffffu, s, o);
    if ((t & 31) == 0) red[t >> 5] = s;
    __syncthreads();
    float mean = 0.f;
    #pragma unroll
    for (int i = 0; i < 8; ++i) mean += red[i];
    mean *= (1.f / 256.f);
    __syncthreads();

    const float d = v - mean;
    float s2 = d * d;
    #pragma unroll
    for (int o = 16; o; o >>= 1) s2 += __shfl_xor_sync(0xffffffffu, s2, o);
    if ((t & 31) == 0) red[t >> 5] = s2;
    __syncthreads();
    float var = 0.f;
    #pragma unroll
    for (int i = 0; i < 8; ++i) var += red[i];
    var *= (1.f / 256.f);

    const float r = d * rsqrtf(var + 1e-5f) * gamma[t] + beta[t];
    out[idx] = r;
    if (out_b) out_b[idx] = __float2bfloat16_rn(r);
}

// ---------------- launch -----------------------------------------------------
extern "C" void kernel_launch(void* const* d_in, const int* in_sizes, int n_in,
                              void* d_out, int out_size)
{
    (void)in_sizes; (void)n_in; (void)out_size;
    const float* cur_src = (const float*)d_in[0];
    const float* src_all = (const float*)d_in[1];
    const float* pos     = (const float*)d_in[2];
    const float* refpts  = (const float*)d_in[3];
    const float* W_off   = (const float*)d_in[6];
    const float* b_off   = (const float*)d_in[7];
    const float* W_attn  = (const float*)d_in[8];
    const float* b_attn  = (const float*)d_in[9];
    const float* W_val   = (const float*)d_in[10];
    const float* b_val   = (const float*)d_in[11];
    const float* W_out   = (const float*)d_in[12];
    const float* b_out   = (const float*)d_in[13];
    const float* gamma1  = (const float*)d_in[14];
    const float* beta1   = (const float*)d_in[15];
    const float* W1      = (const float*)d_in[16];
    const float* b1      = (const float*)d_in[17];
    const float* W2      = (const float*)d_in[18];
    const float* b2      = (const float*)d_in[19];
    const float* gamma2  = (const float*)d_in[20];
    const float* beta2   = (const float*)d_in[21];
    float* out = (float*)d_out;

    float *g_off, *g_attn, *g_src2, *g_src, *g_ffn2, *g_bq;
    __nv_bfloat16 *g_value, *g_samp, *g_srcb, *g_ffnb;
    __nv_bfloat16 *g_wvalT, *g_wqT, *g_woutT, *g_w1T, *g_w2T;
    cudaGetSymbolAddress((void**)&g_value, sc_value);
    cudaGetSymbolAddress((void**)&g_off,   sc_off);
    cudaGetSymbolAddress((void**)&g_attn,  sc_attn);
    cudaGetSymbolAddress((void**)&g_samp,  sc_samp);
    cudaGetSymbolAddress((void**)&g_src2,  sc_src2);
    cudaGetSymbolAddress((void**)&g_src,   sc_src);
    cudaGetSymbolAddress((void**)&g_srcb,  sc_srcb);
    cudaGetSymbolAddress((void**)&g_ffnb,  sc_ffnb);
    cudaGetSymbolAddress((void**)&g_ffn2,  sc_ffn2);
    cudaGetSymbolAddress((void**)&g_wvalT, sc_wvalT);
    cudaGetSymbolAddress((void**)&g_wqT,   sc_wqT);
    cudaGetSymbolAddress((void**)&g_woutT, sc_woutT);
    cudaGetSymbolAddress((void**)&g_w1T,   sc_w1T);
    cudaGetSymbolAddress((void**)&g_w2T,   sc_w2T);
    cudaGetSymbolAddress((void**)&g_bq,    sc_bq);

    // 0. one prep kernel: all weight transposes + bias concat
    prep_kernel<<<737, dim3(32, 8)>>>(W_val, W_off, W_attn, W_out, W1, W2,
                                      b_off, b_attn,
                                      g_wvalT, g_wqT, g_woutT, g_w1T, g_w2T, g_bq);

    // 1. value = bf16(src_all + pos) @ W_val + b_val -> head-major bf16
    bgemm_value<<<dim3(2, ROWS_V / 128), 256>>>(
        src_all, pos, g_wvalT, b_val, g_value, 256);

    // 2. [off | attn] = (cur_src + pos[:,-1]) @ [W_off|W_attn] + [b_off|b_attn]
    bgemm_qa<<<dim3(3, ROWS_Q / 128), 256>>>(
        cur_src, pos, g_wqT, g_bq, g_off, g_attn);

    // 3. fused softmax + deformable bilinear sampling -> bf16
    sample_kernel<<<(BATCH * LQ * N_HEADS) / 16, 256>>>(
        g_off, g_attn, refpts, g_value, g_samp);

    // 4. src2 = samp @ W_out + b_out
    bgemm_b16a<false, false><<<dim3(2, ROWS_Q / 128), 256>>>(
        g_samp, g_woutT, b_out, g_src2, nullptr, ROWS_Q, 256, 256);

    // 5. src = LN(cur_src + src2), bf16 twin for FFN1
    add_ln_kernel<<<ROWS_Q, 256>>>(cur_src, g_src2, gamma1, beta1, g_src, g_srcb);

    // 6. ffn_h = relu(src @ W1 + b1) -> bf16
    bgemm_b16a<true, true><<<dim3(D_FFN / 128, ROWS_Q / 128), 256>>>(
        g_srcb, g_w1T, b1, nullptr, g_ffnb, ROWS_Q, D_FFN, 256);

    // 7. ffn2 = ffn_h @ W2 + b2
    bgemm_b16a<false, false><<<dim3(2, ROWS_Q / 128), 256>>>(
        g_ffnb, g_w2T, b2, g_ffn2, nullptr, ROWS_Q, 256, 1024);

    // 8. out = LN(src + ffn2)
    add_ln_kernel<<<ROWS_Q, 256>>>(g_src, g_ffn2, gamma2, beta2, out, nullptr);
}

// round 14
// speedup vs baseline: 2.1746x; 1.0485x over previous
#include <cuda_runtime.h>
#include <cuda_bf16.h>
#include <cstdint>

// ---------------- problem constants ----------------
#define D_MODEL   256
#define N_HEADS   8
#define HEAD_DIM  32
#define N_LEVELS  4
#define N_POINTS  4
#define D_FFN     1024
#define HW        128
#define LQ        (HW * HW)            // 16384
#define LIN       (N_LEVELS * LQ)      // 65536
#define BATCH     2
#define ROWS_Q    (BATCH * LQ)         // 32768
#define ROWS_V    (BATCH * LIN)        // 131072

// ---------------- scratch (device globals) ---------------------------------
__device__ __align__(256) __nv_bfloat16 sc_value[ROWS_V * D_MODEL]; // head-major
__device__ __align__(256) float         sc_off  [ROWS_Q * D_MODEL];
__device__ __align__(256) float         sc_attn [ROWS_Q * 128];
__device__ __align__(256) __nv_bfloat16 sc_samp [ROWS_Q * D_MODEL];
__device__ __align__(256) float         sc_src2 [ROWS_Q * D_MODEL];
__device__ __align__(256) float         sc_src  [ROWS_Q * D_MODEL];
__device__ __align__(256) __nv_bfloat16 sc_srcb [ROWS_Q * D_MODEL];
__device__ __align__(256) __nv_bfloat16 sc_ffnb [ROWS_Q * D_FFN];
__device__ __align__(256) float         sc_ffn2 [ROWS_Q * D_MODEL];
// bf16 transposed weights Wt[n][k]
__device__ __align__(256) __nv_bfloat16 sc_wvalT[D_MODEL * D_MODEL];
__device__ __align__(256) __nv_bfloat16 sc_wqT  [384 * D_MODEL];      // off(256)+attn(128)
__device__ __align__(256) __nv_bfloat16 sc_woutT[D_MODEL * D_MODEL];
__device__ __align__(256) __nv_bfloat16 sc_w1T  [D_FFN * D_MODEL];
__device__ __align__(256) __nv_bfloat16 sc_w2T  [D_MODEL * D_FFN];
__device__ __align__(256) float         sc_bq   [384];                // b_off ++ b_attn

// ---------------- helpers --------------------------------------------------
__device__ __forceinline__ void mma_bf16(float c[4], const uint32_t a[4],
                                         const uint32_t b[2]) {
    asm volatile(
        "mma.sync.aligned.m16n8k16.row.col.f32.bf16.bf16.f32 "
        "{%0,%1,%2,%3}, {%4,%5,%6,%7}, {%8,%9}, {%0,%1,%2,%3};"
        : "+f"(c[0]), "+f"(c[1]), "+f"(c[2]), "+f"(c[3])
        : "r"(a[0]), "r"(a[1]), "r"(a[2]), "r"(a[3]), "r"(b[0]), "r"(b[1]));
}
__device__ __forceinline__ void cp_async16(void* smem, const void* gmem) {
    const uint32_t s = (uint32_t)__cvta_generic_to_shared(smem);
    asm volatile("cp.async.ca.shared.global [%0], [%1], 16;\n" :: "r"(s), "l"(gmem));
}
__device__ __forceinline__ void cp_commit() {
    asm volatile("cp.async.commit_group;\n");
}
template <int N>
__device__ __forceinline__ void cp_wait() {
    asm volatile("cp.async.wait_group %0;\n" :: "n"(N));
}
__device__ __forceinline__ uint32_t packbf(float x, float y) {
    __nv_bfloat162 p = __floats2bfloat162_rn(x, y);
    return *(uint32_t*)&p;
}
__device__ __forceinline__ float bflo(uint32_t u) { return __uint_as_float(u << 16); }
__device__ __forceinline__ float bfhi(uint32_t u) { return __uint_as_float(u & 0xffff0000u); }

#define BPAD 40   // bf16 row stride (BK=32 tiles): conflict-free LDSM phases
#define BPAD64 72 // bf16 row stride (BK=64 tiles): conflict-free LDSM phases

// ---- warp-tile compute on one smem stage (ldmatrix fragment loads) ---------
template <int PITCH, int BK>
__device__ __forceinline__ void gemm_compute_stage(
    const __nv_bfloat16* As, const __nv_bfloat16* Bs,
    float acc[4][4][4], int wm, int wn, int lane)
{
    // lane-address bases (bytes): A lanes 0-15 -> rows m0-15 col 0,
    // lanes 16-31 -> rows m0-15 col 8. B lanes 0-7 -> rows n0-7 col 0,
    // lanes 8-15 -> rows n0-7 col 8 (x2 uses lanes 0-15 only).
    const uint32_t aOff = (uint32_t)__cvta_generic_to_shared(As) +
        (uint32_t)(((wm + (lane & 15)) * PITCH + (lane >> 4) * 8) * 2);
    const uint32_t bOff = (uint32_t)__cvta_generic_to_shared(Bs) +
        (uint32_t)(((wn + (lane & 7)) * PITCH + ((lane >> 3) & 1) * 8) * 2);

    #pragma unroll
    for (int ks = 0; ks < BK; ks += 16) {
        uint32_t af[4][4];
        #pragma unroll
        for (int mt = 0; mt < 4; ++mt)
            asm volatile(
                "ldmatrix.sync.aligned.m8n8.x4.shared.b16 {%0,%1,%2,%3}, [%4];"
                : "=r"(af[mt][0]), "=r"(af[mt][1]), "=r"(af[mt][2]), "=r"(af[mt][3])
                : "r"(aOff + (uint32_t)((mt * 16 * PITCH + ks) * 2)));
        uint32_t bf[4][2];
        #pragma unroll
        for (int nt = 0; nt < 4; ++nt)
            asm volatile(
                "ldmatrix.sync.aligned.m8n8.x2.shared.b16 {%0,%1}, [%2];"
                : "=r"(bf[nt][0]), "=r"(bf[nt][1])
                : "r"(bOff + (uint32_t)((nt * 8 * PITCH + ks) * 2)));
        #pragma unroll
        for (int mt = 0; mt < 4; ++mt)
            #pragma unroll
            for (int nt = 0; nt < 4; ++nt)
                mma_bf16(acc[mt][nt], af[mt], bf[nt]);
    }
}

// ================= GEMM 1: value projection =================================
// A fp32 + A2 fp32 (same row), out = bf16 HEAD-MAJOR [n][h][pix][32].
__global__ __launch_bounds__(256)
void bgemm_value(const float* __restrict__ A, const float* __restrict__ A2,
                 const __nv_bfloat16* __restrict__ Bt, const float* __restrict__ bias,
                 __nv_bfloat16* __restrict__ Cb, int K)
{
    __shared__ __align__(16) __nv_bfloat16 As[2][128 * BPAD];
    __shared__ __align__(16) __nv_bfloat16 Bs[2][128 * BPAD];

    const int tid  = threadIdx.x;
    const int wid  = tid >> 5;
    const int lane = tid & 31;
    const int g    = lane >> 2;
    const int t    = lane & 3;
    const int bm = blockIdx.y * 128;
    const int bn = blockIdx.x * 128;
    const int wm = (wid & 1) * 64;
    const int wn = (wid >> 1) * 32;

    const int la_r = tid >> 1;
    const int la_c = (tid & 1) * 16;
    const float* a_ptr  = A  + (size_t)(bm + la_r) * K + la_c;
    const float* a2_ptr = A2 + (size_t)(bm + la_r) * K + la_c;

    const int nk = K / 32;

    auto ldgA = [&](int i, uint32_t v[8]) {
        const int k0 = i * 32;
        #pragma unroll
        for (int j = 0; j < 4; ++j) {
            float4 a = *(const float4*)(a_ptr + k0 + j * 4);
            const float4 b = *(const float4*)(a2_ptr + k0 + j * 4);
            a.x += b.x; a.y += b.y; a.z += b.z; a.w += b.w;
            v[2 * j]     = packbf(a.x, a.y);
            v[2 * j + 1] = packbf(a.z, a.w);
        }
    };
    auto stsA = [&](int s, const uint32_t v[8]) {
        uint32_t* p = (uint32_t*)&As[s][la_r * BPAD + la_c];
        *(uint4*)p       = make_uint4(v[0], v[1], v[2], v[3]);
        *(uint4*)(p + 4) = make_uint4(v[4], v[5], v[6], v[7]);
    };
    auto cpB = [&](int s, int i) {
        const int k0 = i * 32;
        #pragma unroll
        for (int j = 0; j < 2; ++j) {
            const int ch = j * 256 + tid;
            const int r  = ch >> 2;
            const int cc = (ch & 3) * 8;
            cp_async16(&Bs[s][r * BPAD + cc], Bt + (size_t)(bn + r) * K + k0 + cc);
        }
    };

    float acc[4][4][4] = {};
    uint32_t rA[8];

    ldgA(0, rA); stsA(0, rA); cpB(0, 0); cp_commit();
    ldgA(1, rA);

    for (int i = 0; i < nk; ++i) {
        cp_wait<0>();
        __syncthreads();
        if (i + 1 < nk) { stsA((i + 1) & 1, rA); cpB((i + 1) & 1, i + 1); cp_commit(); }
        if (i + 2 < nk) ldgA(i + 2, rA);
        gemm_compute_stage<BPAD, 32>(As[i & 1], Bs[i & 1], acc, wm, wn, lane);
        __syncthreads();
    }

    // epilogue: head-major store
    const int nb  = bm / LIN;              // batch (tile never straddles LIN)
    const int pix0 = bm & (LIN - 1);
    #pragma unroll
    for (int nt = 0; nt < 4; ++nt) {
        const int n = bn + wn + nt * 8 + t * 2;
        const int h = n >> 5, c = n & 31;
        const float bx = bias[n], by = bias[n + 1];
        __nv_bfloat16* hb = Cb + ((size_t)(nb * 8 + h) * LIN) * 32 + c;
        #pragma unroll
        for (int mt = 0; mt < 4; ++mt) {
            const int pix = pix0 + wm + mt * 16 + g;
            *(uint32_t*)&hb[(size_t)pix * 32] =
                packbf(acc[mt][nt][0] + bx, acc[mt][nt][1] + by);
            *(uint32_t*)&hb[(size_t)(pix + 8) * 32] =
                packbf(acc[mt][nt][2] + bx, acc[mt][nt][3] + by);
        }
    }
}

// ================= GEMM 2: fused q-add + off/attn split =====================
__global__ __launch_bounds__(256)
void bgemm_qa(const float* __restrict__ A, const float* __restrict__ A2,
              const __nv_bfloat16* __restrict__ Bt, const float* __restrict__ bias,
              float* __restrict__ Coff, float* __restrict__ Cattn)
{
    const int K = 256;
    __shared__ __align__(16) __nv_bfloat16 As[2][128 * BPAD];
    __shared__ __align__(16) __nv_bfloat16 Bs[2][128 * BPAD];

    const int tid  = threadIdx.x;
    const int wid  = tid >> 5;
    const int lane = tid & 31;
    const int g    = lane >> 2;
    const int t    = lane & 3;
    const int bm = blockIdx.y * 128;
    const int bn = blockIdx.x * 128;
    const int wm = (wid & 1) * 64;
    const int wn = (wid >> 1) * 32;

    const int la_r = tid >> 1;
    const int la_c = (tid & 1) * 16;
    const int r_glob = bm + la_r;
    const int pos_row = r_glob + 49152 * ((r_glob >> 14) + 1);  // pos[:, -1] remap
    const float* a_ptr  = A  + (size_t)r_glob * K + la_c;
    const float* a2_ptr = A2 + (size_t)pos_row * K + la_c;

    const int nk = K / 32;

    auto ldgA = [&](int i, uint32_t v[8]) {
        const int k0 = i * 32;
        #pragma unroll
        for (int j = 0; j < 4; ++j) {
            float4 a = *(const float4*)(a_ptr + k0 + j * 4);
            const float4 b = *(const float4*)(a2_ptr + k0 + j * 4);
            a.x += b.x; a.y += b.y; a.z += b.z; a.w += b.w;
            v[2 * j]     = packbf(a.x, a.y);
            v[2 * j + 1] = packbf(a.z, a.w);
        }
    };
    auto stsA = [&](int s, const uint32_t v[8]) {
        uint32_t* p = (uint32_t*)&As[s][la_r * BPAD + la_c];
        *(uint4*)p       = make_uint4(v[0], v[1], v[2], v[3]);
        *(uint4*)(p + 4) = make_uint4(v[4], v[5], v[6], v[7]);
    };
    auto cpB = [&](int s, int i) {
        const int k0 = i * 32;
        #pragma unroll
        for (int j = 0; j < 2; ++j) {
            const int ch = j * 256 + tid;
            const int r  = ch >> 2;
            const int cc = (ch & 3) * 8;
            cp_async16(&Bs[s][r * BPAD + cc], Bt + (size_t)(bn + r) * K + k0 + cc);
        }
    };

    float acc[4][4][4] = {};
    uint32_t rA[8];

    ldgA(0, rA); stsA(0, rA); cpB(0, 0); cp_commit();
    ldgA(1, rA);

    for (int i = 0; i < nk; ++i) {
        cp_wait<0>();
        __syncthreads();
        if (i + 1 < nk) { stsA((i + 1) & 1, rA); cpB((i + 1) & 1, i + 1); cp_commit(); }
        if (i + 2 < nk) ldgA(i + 2, rA);
        gemm_compute_stage<BPAD, 32>(As[i & 1], Bs[i & 1], acc, wm, wn, lane);
        __syncthreads();
    }

    const bool is_attn = (bn >= 256);
    float* C = is_attn ? Cattn : Coff;
    const int stride = is_attn ? 128 : 256;
    const int cbase  = is_attn ? bn - 256 : bn;
    #pragma unroll
    for (int nt = 0; nt < 4; ++nt) {
        const int nn = wn + nt * 8 + t * 2;
        const float bx = bias[bn + nn], by = bias[bn + nn + 1];
        #pragma unroll
        for (int mt = 0; mt < 4; ++mt) {
            const int m = bm + wm + mt * 16 + g;
            *(float2*)&C[(size_t)m * stride + cbase + nn] =
                make_float2(acc[mt][nt][0] + bx, acc[mt][nt][1] + by);
            *(float2*)&C[(size_t)(m + 8) * stride + cbase + nn] =
                make_float2(acc[mt][nt][2] + bx, acc[mt][nt][3] + by);
        }
    }
}

// ================= GEMM 3: bf16 A, BK=64 2-stage (out-proj / FFN) ===========
template <bool RELU, bool BF16_OUT>
__global__ __launch_bounds__(256)
void bgemm_b16a(const __nv_bfloat16* __restrict__ A,
                const __nv_bfloat16* __restrict__ Bt, const float* __restrict__ bias,
                float* __restrict__ C, __nv_bfloat16* __restrict__ Cb,
                int M, int N, int K)
{
    __shared__ __align__(16) __nv_bfloat16 As[2][128 * BPAD64];
    __shared__ __align__(16) __nv_bfloat16 Bs[2][128 * BPAD64];

    const int tid  = threadIdx.x;
    const int wid  = tid >> 5;
    const int lane = tid & 31;
    const int g    = lane >> 2;
    const int t    = lane & 3;
    const int bm = blockIdx.y * 128;
    const int bn = blockIdx.x * 128;
    const int wm = (wid & 1) * 64;
    const int wn = (wid >> 1) * 32;

    const int nk = K / 64;

    auto load_stage = [&](int s, int i) {
        const int k0 = i * 64;
        #pragma unroll
        for (int j = 0; j < 4; ++j) {
            const int ch = j * 256 + tid;          // 1024 chunks of 16B (A+B each)
            const int r  = ch >> 3;                // 0..127
            const int cc = (ch & 7) * 8;           // 0..56
            cp_async16(&As[s][r * BPAD64 + cc], A  + (size_t)(bm + r) * K + k0 + cc);
            cp_async16(&Bs[s][r * BPAD64 + cc], Bt + (size_t)(bn + r) * K + k0 + cc);
        }
    };

    float acc[4][4][4] = {};

    load_stage(0, 0); cp_commit();

    for (int i = 0; i < nk; ++i) {
        if (i + 1 < nk) {
            load_stage((i + 1) & 1, i + 1);
            cp_commit();
            cp_wait<1>();
        } else {
            cp_wait<0>();
        }
        __syncthreads();
        gemm_compute_stage<BPAD64, 64>(As[i & 1], Bs[i & 1], acc, wm, wn, lane);
        __syncthreads();
    }

    #pragma unroll
    for (int nt = 0; nt < 4; ++nt) {
        const int n = bn + wn + nt * 8 + t * 2;
        const float bx = bias[n], by = bias[n + 1];
        #pragma unroll
        for (int mt = 0; mt < 4; ++mt) {
            const int m = bm + wm + mt * 16 + g;
            float2 v0 = { acc[mt][nt][0] + bx, acc[mt][nt][1] + by };
            float2 v1 = { acc[mt][nt][2] + bx, acc[mt][nt][3] + by };
            if (RELU) {
                v0.x = fmaxf(v0.x, 0.f); v0.y = fmaxf(v0.y, 0.f);
                v1.x = fmaxf(v1.x, 0.f); v1.y = fmaxf(v1.y, 0.f);
            }
            if (BF16_OUT) {
                *(uint32_t*)&Cb[(size_t)m * N + n]       = packbf(v0.x, v0.y);
                *(uint32_t*)&Cb[(size_t)(m + 8) * N + n] = packbf(v1.x, v1.y);
            } else {
                *(float2*)&C[(size_t)m * N + n]       = v0;
                *(float2*)&C[(size_t)(m + 8) * N + n] = v1;
            }
        }
    }
}

// ================= single prep kernel: all transposes + bias concat =========
__device__ __forceinline__ void do_transpose_tile(
    const float* W, __nv_bfloat16* Wt, int K, int N, int tilesX, int local)
{
    __shared__ float tt[32][33];
    const int bx = (local % tilesX) * 32;   // n
    const int by = (local / tilesX) * 32;   // k
    const int x = threadIdx.x, y = threadIdx.y;
    #pragma unroll
    for (int j = 0; j < 32; j += 8)
        tt[y + j][x] = W[(size_t)(by + y + j) * N + bx + x];
    __syncthreads();
    #pragma unroll
    for (int j = 0; j < 32; j += 8)
        Wt[(size_t)(bx + y + j) * K + by + x] = __float2bfloat16_rn(tt[x][y + j]);
}

__global__ void prep_kernel(
    const float* __restrict__ W_val, const float* __restrict__ W_off,
    const float* __restrict__ W_attn, const float* __restrict__ W_out,
    const float* __restrict__ W1, const float* __restrict__ W2,
    const float* __restrict__ b_off, const float* __restrict__ b_attn,
    __nv_bfloat16* __restrict__ wvalT, __nv_bfloat16* __restrict__ wqT,
    __nv_bfloat16* __restrict__ woutT, __nv_bfloat16* __restrict__ w1T,
    __nv_bfloat16* __restrict__ w2T, float* __restrict__ bq)
{
    const int b = blockIdx.x;
    if      (b < 64)  do_transpose_tile(W_val,  wvalT,           256, 256,  8,  b);
    else if (b < 128) do_transpose_tile(W_off,  wqT,             256, 256,  8,  b - 64);
    else if (b < 160) do_transpose_tile(W_attn, wqT + 256 * 256, 256, 128,  4,  b - 128);
    else if (b < 224) do_transpose_tile(W_out,  woutT,           256, 256,  8,  b - 160);
    else if (b < 480) do_transpose_tile(W1,     w1T,             256, 1024, 32, b - 224);
    else if (b < 736) do_transpose_tile(W2,     w2T,            1024, 256,  8,  b - 480);
    else {
        const int t = threadIdx.y * 32 + threadIdx.x;   // 0..255
        bq[t] = b_off[t];
        if (t < 128) bq[256 + t] = b_attn[t];
    }
}

// ---------------- fused softmax + deformable bilinear sampling --------------
// Half-warp per (n, q, h). Lane l owns point l's scalars; gathers are paired
// LDG.64 over adjacent x-corner pixels (lane groups 0-7/8-15 own slot 0/1);
// slot weights algebraically absorb clamping + validity. One xor-8 merge.
__global__ __launch_bounds__(256)
void sample_kernel(const float* __restrict__ off, const float* __restrict__ attn,
                   const float* __restrict__ ref,
                   const __nv_bfloat16* __restrict__ value,
                   __nv_bfloat16* __restrict__ out)
{
    const int tw  = blockIdx.x * 16 + (threadIdx.x >> 4);
    const int l16 = threadIdx.x & 15;
    const int h = tw & 7;
    const int q = (tw >> 3) & (LQ - 1);
    const int n = tw >> 17;
    const size_t row = (size_t)n * LQ + q;

    // ---- lane-parallel point setup: lane l16 owns point p = l16 ----
    const int p  = l16;
    const int lv = p >> 2;

    // softmax over 16 points (width-16 butterflies)
    const float logit = attn[row * 128 + h * 16 + p];
    float mx = logit;
    #pragma unroll
    for (int o = 8; o; o >>= 1) mx = fmaxf(mx, __shfl_xor_sync(0xffffffffu, mx, o, 16));
    const float e = __expf(logit - mx);
    float ssum = e;
    #pragma unroll
    for (int o = 8; o; o >>= 1) ssum += __shfl_xor_sync(0xffffffffu, ssum, o, 16);
    const float aw = e * (1.f / ssum);

    // coordinates & weights for point p
    const float2 o2 = *(const float2*)&off[row * 256 + h * 32 + 2 * p];
    const float rx = ref[row * 8 + lv * 2];
    const float ry = ref[row * 8 + lv * 2 + 1];
    const float x = fmaf(rx, 128.f, o2.x - 0.5f);
    const float y = fmaf(ry, 128.f, o2.y - 0.5f);
    const float x0f = floorf(x), y0f = floorf(y);
    const float wx = x - x0f, wy = y - y0f;
    const int x0 = (int)x0f, y0 = (int)y0f;

    // x: corner weights + slot assignment under clamped pair base b in [0,126]
    const float sA = (x0 >= 0 && x0 < HW) ? (1.f - wx) : 0.f;      // corner x0
    const float sB = (x0 >= -1 && x0 < HW - 1) ? wx : 0.f;          // corner x0+1
    const int   b  = min(max(x0, 0), HW - 2);
    float s0, s1;
    if (x0 >= 0) { s0 = sA; s1 = sB; } else { s0 = sB; s1 = 0.f; }
    if (x0 >= HW - 1) { s0 = 0.f; s1 = sA; }

    // y: row weights + clamped rows
    const float r0 = (y0 >= 0 && y0 < HW) ? (1.f - wy) : 0.f;
    const float r1 = (y0 >= -1 && y0 < HW - 1) ? wy : 0.f;
    const int y0c = min(max(y0, 0), HW - 1);
    const int y1c = min(max(y0 + 1, 0), HW - 1);

    const float q00 = aw * r0 * s0, q01 = aw * r0 * s1;
    const float q10 = aw * r1 * s0, q11 = aw * r1 * s1;
    // packed index: word offset of pix(b) in row y0c | dy flag at bit 28
    const int ipack = ((lv * LQ + y0c * HW + b) * 16) | ((y1c - y0c) << 28);

    const uint32_t* vbw =
        (const uint32_t*)value + ((size_t)(n * 8 + h) * LIN) * 16;
    const int lw = 2 * l16;     // lane's word pair offset within the 128B pair

    float a0 = 0.f, a1 = 0.f, a2 = 0.f, a3 = 0.f;
    #pragma unroll
    for (int pp = 0; pp < 16; ++pp) {
        const int   ip  = __shfl_sync(0xffffffffu, ipack, pp, 16);
        const float b00 = __shfl_sync(0xffffffffu, q00, pp, 16);
        const float b01 = __shfl_sync(0xffffffffu, q01, pp, 16);
        const float b10 = __shfl_sync(0xffffffffu, q10, pp, 16);
        const float b11 = __shfl_sync(0xffffffffu, q11, pp, 16);
        const int ib = ip & 0x0FFFFFFF;
        const int dy = (ip >> 28) << 11;           // 0 or 2048 words
        const float wtop = (l16 < 8) ? b00 : b01;
        const float wbot = (l16 < 8) ? b10 : b11;
        const uint2 v0 = *(const uint2*)(vbw + ib + lw);
        const uint2 v1 = *(const uint2*)(vbw + ib + dy + lw);
        a0 = fmaf(bflo(v0.x), wtop, a0); a1 = fmaf(bfhi(v0.x), wtop, a1);
        a2 = fmaf(bflo(v0.y), wtop, a2); a3 = fmaf(bfhi(v0.y), wtop, a3);
        a0 = fmaf(bflo(v1.x), wbot, a0); a1 = fmaf(bfhi(v1.x), wbot, a1);
        a2 = fmaf(bflo(v1.y), wbot, a2); a3 = fmaf(bfhi(v1.y), wbot, a3);
    }
    // merge the two pixel-slot halves: channels 4j..4j+3 = lane j + lane j+8
    a0 += __shfl_xor_sync(0xffffffffu, a0, 8, 16);
    a1 += __shfl_xor_sync(0xffffffffu, a1, 8, 16);
    a2 += __shfl_xor_sync(0xffffffffu, a2, 8, 16);
    a3 += __shfl_xor_sync(0xffffffffu, a3, 8, 16);

    if (l16 < 8) {
        uint2 w = { packbf(a0, a1), packbf(a2, a3) };
        *((uint2*)(out + row * 256 + h * 32) + l16) = w;
    }
}

// ---------------- residual add + layernorm (+ optional bf16 twin) -----------
__global__ __launch_bounds__(256)
void add_ln_kernel(const float* __restrict__ a, const float* __restrict__ b,
                   const float* __restrict__ gamma, const float* __restrict__ beta,
                   float* __restrict__ out, __nv_bfloat16* __restrict__ out_b)
{
    const int row = blockIdx.x;
    const int t = threadIdx.x;
    const size_t idx = (size_t)row * 256 + t;
    const float v = a[idx] + b[idx];

    __shared__ float red[8];
    float s = v;
    #pragma unroll
    for (int o = 16; o; o >>= 1) s += __shfl_xor_sync(0xffffffffu, s, o);
    if ((t & 31) == 0) red[t >> 5] = s;
    __syncthreads();
    float mean = 0.f;
    #pragma unroll
    for (int i = 0; i < 8; ++i) mean += red[i];
    mean *= (1.f / 256.f);
    __syncthreads();

    const float d = v - mean;
    float s2 = d * d;
    #pragma unroll
    for (int o = 16; o; o >>= 1) s2 += __shfl_xor_sync(0xffffffffu, s2, o);
    if ((t & 31) == 0) red[t >> 5] = s2;
    __syncthreads();
    float var = 0.f;
    #pragma unroll
    for (int i = 0; i < 8; ++i) var += red[i];
    var *= (1.f / 256.f);

    const float r = d * rsqrtf(var + 1e-5f) * gamma[t] + beta[t];
    out[idx] = r;
    if (out_b) out_b[idx] = __float2bfloat16_rn(r);
}

// ---------------- launch -----------------------------------------------------
extern "C" void kernel_launch(void* const* d_in, const int* in_sizes, int n_in,
                              void* d_out, int out_size)
{
    (void)in_sizes; (void)n_in; (void)out_size;
    const float* cur_src = (const float*)d_in[0];
    const float* src_all = (const float*)d_in[1];
    const float* pos     = (const float*)d_in[2];
    const float* refpts  = (const float*)d_in[3];
    const float* W_off   = (const float*)d_in[6];
    const float* b_off   = (const float*)d_in[7];
    const float* W_attn  = (const float*)d_in[8];
    const float* b_attn  = (const float*)d_in[9];
    const float* W_val   = (const float*)d_in[10];
    const float* b_val   = (const float*)d_in[11];
    const float* W_out   = (const float*)d_in[12];
    const float* b_out   = (const float*)d_in[13];
    const float* gamma1  = (const float*)d_in[14];
    const float* beta1   = (const float*)d_in[15];
    const float* W1      = (const float*)d_in[16];
    const float* b1      = (const float*)d_in[17];
    const float* W2      = (const float*)d_in[18];
    const float* b2      = (const float*)d_in[19];
    const float* gamma2  = (const float*)d_in[20];
    const float* beta2   = (const float*)d_in[21];
    float* out = (float*)d_out;

    float *g_off, *g_attn, *g_src2, *g_src, *g_ffn2, *g_bq;
    __nv_bfloat16 *g_value, *g_samp, *g_srcb, *g_ffnb;
    __nv_bfloat16 *g_wvalT, *g_wqT, *g_woutT, *g_w1T, *g_w2T;
    cudaGetSymbolAddress((void**)&g_value, sc_value);
    cudaGetSymbolAddress((void**)&g_off,   sc_off);
    cudaGetSymbolAddress((void**)&g_attn,  sc_attn);
    cudaGetSymbolAddress((void**)&g_samp,  sc_samp);
    cudaGetSymbolAddress((void**)&g_src2,  sc_src2);
    cudaGetSymbolAddress((void**)&g_src,   sc_src);
    cudaGetSymbolAddress((void**)&g_srcb,  sc_srcb);
    cudaGetSymbolAddress((void**)&g_ffnb,  sc_ffnb);
    cudaGetSymbolAddress((void**)&g_ffn2,  sc_ffn2);
    cudaGetSymbolAddress((void**)&g_wvalT, sc_wvalT);
    cudaGetSymbolAddress((void**)&g_wqT,   sc_wqT);
    cudaGetSymbolAddress((void**)&g_woutT, sc_woutT);
    cudaGetSymbolAddress((void**)&g_w1T,   sc_w1T);
    cudaGetSymbolAddress((void**)&g_w2T,   sc_w2T);
    cudaGetSymbolAddress((void**)&g_bq,    sc_bq);

    // 0. one prep kernel: all weight transposes + bias concat
    prep_kernel<<<737, dim3(32, 8)>>>(W_val, W_off, W_attn, W_out, W1, W2,
                                      b_off, b_attn,
                                      g_wvalT, g_wqT, g_woutT, g_w1T, g_w2T, g_bq);

    // 1. value = bf16(src_all + pos) @ W_val + b_val -> head-major bf16
    bgemm_value<<<dim3(2, ROWS_V / 128), 256>>>(
        src_all, pos, g_wvalT, b_val, g_value, 256);

    // 2. [off | attn] = (cur_src + pos[:,-1]) @ [W_off|W_attn] + [b_off|b_attn]
    bgemm_qa<<<dim3(3, ROWS_Q / 128), 256>>>(
        cur_src, pos, g_wqT, g_bq, g_off, g_attn);

    // 3. fused softmax + deformable bilinear sampling -> bf16
    sample_kernel<<<(BATCH * LQ * N_HEADS) / 16, 256>>>(
        g_off, g_attn, refpts, g_value, g_samp);

    // 4. src2 = samp @ W_out + b_out
    bgemm_b16a<false, false><<<dim3(2, ROWS_Q / 128), 256>>>(
        g_samp, g_woutT, b_out, g_src2, nullptr, ROWS_Q, 256, 256);

    // 5. src = LN(cur_src + src2), bf16 twin for FFN1
    add_ln_kernel<<<ROWS_Q, 256>>>(cur_src, g_src2, gamma1, beta1, g_src, g_srcb);

    // 6. ffn_h = relu(src @ W1 + b1) -> bf16
    bgemm_b16a<true, true><<<dim3(D_FFN / 128, ROWS_Q / 128), 256>>>(
        g_srcb, g_w1T, b1, nullptr, g_ffnb, ROWS_Q, D_FFN, 256);

    // 7. ffn2 = ffn_h @ W2 + b2
    bgemm_b16a<false, false><<<dim3(2, ROWS_Q / 128), 256>>>(
        g_ffnb, g_w2T, b2, g_ffn2, nullptr, ROWS_Q, 256, 1024);

    // 8. out = LN(src + ffn2)
    add_ln_kernel<<<ROWS_Q, 256>>>(g_src, g_ffn2, gamma2, beta2, out, nullptr);
}

// round 15
// speedup vs baseline: 2.2734x; 1.0454x over previous
#include <cuda_runtime.h>
#include <cuda_bf16.h>
#include <cstdint>

// ---------------- problem constants ----------------
#define D_MODEL   256
#define N_HEADS   8
#define HEAD_DIM  32
#define N_LEVELS  4
#define N_POINTS  4
#define D_FFN     1024
#define HW        128
#define LQ        (HW * HW)            // 16384
#define LIN       (N_LEVELS * LQ)      // 65536
#define BATCH     2
#define ROWS_Q    (BATCH * LQ)         // 32768
#define ROWS_V    (BATCH * LIN)        // 131072

// ---------------- scratch (device globals) ---------------------------------
__device__ __align__(256) __nv_bfloat16 sc_value[ROWS_V * D_MODEL]; // head-major
__device__ __align__(256) float         sc_off  [ROWS_Q * D_MODEL];
__device__ __align__(256) float         sc_attn [ROWS_Q * 128];
__device__ __align__(256) __nv_bfloat16 sc_samp [ROWS_Q * D_MODEL];
__device__ __align__(256) float         sc_src2 [ROWS_Q * D_MODEL];
__device__ __align__(256) float         sc_src  [ROWS_Q * D_MODEL];
__device__ __align__(256) __nv_bfloat16 sc_srcb [ROWS_Q * D_MODEL];
__device__ __align__(256) __nv_bfloat16 sc_ffnb [ROWS_Q * D_FFN];
__device__ __align__(256) float         sc_ffn2 [ROWS_Q * D_MODEL];
// bf16 transposed weights Wt[n][k]
__device__ __align__(256) __nv_bfloat16 sc_wvalT[D_MODEL * D_MODEL];
__device__ __align__(256) __nv_bfloat16 sc_wqT  [384 * D_MODEL];      // off(256)+attn(128)
__device__ __align__(256) __nv_bfloat16 sc_woutT[D_MODEL * D_MODEL];
__device__ __align__(256) __nv_bfloat16 sc_w1T  [D_FFN * D_MODEL];
__device__ __align__(256) __nv_bfloat16 sc_w2T  [D_MODEL * D_FFN];
__device__ __align__(256) float         sc_bq   [384];                // b_off ++ b_attn

// ---------------- helpers --------------------------------------------------
__device__ __forceinline__ void mma_bf16(float c[4], const uint32_t a[4],
                                         const uint32_t b[2]) {
    asm volatile(
        "mma.sync.aligned.m16n8k16.row.col.f32.bf16.bf16.f32 "
        "{%0,%1,%2,%3}, {%4,%5,%6,%7}, {%8,%9}, {%0,%1,%2,%3};"
        : "+f"(c[0]), "+f"(c[1]), "+f"(c[2]), "+f"(c[3])
        : "r"(a[0]), "r"(a[1]), "r"(a[2]), "r"(a[3]), "r"(b[0]), "r"(b[1]));
}
__device__ __forceinline__ void cp_async16(void* smem, const void* gmem) {
    const uint32_t s = (uint32_t)__cvta_generic_to_shared(smem);
    asm volatile("cp.async.ca.shared.global [%0], [%1], 16;\n" :: "r"(s), "l"(gmem));
}
__device__ __forceinline__ void cp_commit() {
    asm volatile("cp.async.commit_group;\n");
}
template <int N>
__device__ __forceinline__ void cp_wait() {
    asm volatile("cp.async.wait_group %0;\n" :: "n"(N));
}
__device__ __forceinline__ uint32_t packbf(float x, float y) {
    __nv_bfloat162 p = __floats2bfloat162_rn(x, y);
    return *(uint32_t*)&p;
}
__device__ __forceinline__ float bflo(uint32_t u) { return __uint_as_float(u << 16); }
__device__ __forceinline__ float bfhi(uint32_t u) { return __uint_as_float(u & 0xffff0000u); }

#define BPAD 40   // bf16 row stride (BK=32 tiles): conflict-free LDSM phases
#define BPAD64 72 // bf16 row stride (BK=64 tiles): conflict-free LDSM phases

// ---- warp-tile compute on one smem stage (ldmatrix fragment loads) ---------
// A: x4 per m16 tile. B: x4 per nt-PAIR (mats = {nt k0, nt k8, nt+1 k0, nt+1 k8}).
template <int PITCH, int BK>
__device__ __forceinline__ void gemm_compute_stage(
    const __nv_bfloat16* As, const __nv_bfloat16* Bs,
    float acc[4][4][4], int wm, int wn, int lane)
{
    const uint32_t aOff = (uint32_t)__cvta_generic_to_shared(As) +
        (uint32_t)(((wm + (lane & 15)) * PITCH + (lane >> 4) * 8) * 2);
    const uint32_t bOff = (uint32_t)__cvta_generic_to_shared(Bs) +
        (uint32_t)(((wn + (lane & 7) + (lane >> 4) * 8) * PITCH
                    + ((lane >> 3) & 1) * 8) * 2);

    #pragma unroll
    for (int ks = 0; ks < BK; ks += 16) {
        uint32_t af[4][4];
        #pragma unroll
        for (int mt = 0; mt < 4; ++mt)
            asm volatile(
                "ldmatrix.sync.aligned.m8n8.x4.shared.b16 {%0,%1,%2,%3}, [%4];"
                : "=r"(af[mt][0]), "=r"(af[mt][1]), "=r"(af[mt][2]), "=r"(af[mt][3])
                : "r"(aOff + (uint32_t)((mt * 16 * PITCH + ks) * 2)));
        uint32_t bf[4][2];
        #pragma unroll
        for (int np = 0; np < 2; ++np)
            asm volatile(
                "ldmatrix.sync.aligned.m8n8.x4.shared.b16 {%0,%1,%2,%3}, [%4];"
                : "=r"(bf[2*np][0]), "=r"(bf[2*np][1]),
                  "=r"(bf[2*np+1][0]), "=r"(bf[2*np+1][1])
                : "r"(bOff + (uint32_t)((np * 16 * PITCH + ks) * 2)));
        #pragma unroll
        for (int mt = 0; mt < 4; ++mt)
            #pragma unroll
            for (int nt = 0; nt < 4; ++nt)
                mma_bf16(acc[mt][nt], af[mt], bf[nt]);
    }
}

// ================= GEMM 1: value projection =================================
// A fp32 + A2 fp32 (same row), out = bf16 HEAD-MAJOR [n][h][pix][32].
// Single barrier per K-iter: async loads issued AFTER the barrier.
__global__ __launch_bounds__(256)
void bgemm_value(const float* __restrict__ A, const float* __restrict__ A2,
                 const __nv_bfloat16* __restrict__ Bt, const float* __restrict__ bias,
                 __nv_bfloat16* __restrict__ Cb, int K)
{
    __shared__ __align__(16) __nv_bfloat16 As[2][128 * BPAD];
    __shared__ __align__(16) __nv_bfloat16 Bs[2][128 * BPAD];

    const int tid  = threadIdx.x;
    const int wid  = tid >> 5;
    const int lane = tid & 31;
    const int g    = lane >> 2;
    const int t    = lane & 3;
    const int bm = blockIdx.y * 128;
    const int bn = blockIdx.x * 128;
    const int wm = (wid & 1) * 64;
    const int wn = (wid >> 1) * 32;

    const int la_r = tid >> 1;
    const int la_c = (tid & 1) * 16;
    const float* a_ptr  = A  + (size_t)(bm + la_r) * K + la_c;
    const float* a2_ptr = A2 + (size_t)(bm + la_r) * K + la_c;

    const int nk = K / 32;

    auto ldgA = [&](int i, uint32_t v[8]) {
        const int k0 = i * 32;
        #pragma unroll
        for (int j = 0; j < 4; ++j) {
            float4 a = *(const float4*)(a_ptr + k0 + j * 4);
            const float4 b = *(const float4*)(a2_ptr + k0 + j * 4);
            a.x += b.x; a.y += b.y; a.z += b.z; a.w += b.w;
            v[2 * j]     = packbf(a.x, a.y);
            v[2 * j + 1] = packbf(a.z, a.w);
        }
    };
    auto stsA = [&](int s, const uint32_t v[8]) {
        uint32_t* p = (uint32_t*)&As[s][la_r * BPAD + la_c];
        *(uint4*)p       = make_uint4(v[0], v[1], v[2], v[3]);
        *(uint4*)(p + 4) = make_uint4(v[4], v[5], v[6], v[7]);
    };
    auto cpB = [&](int s, int i) {
        const int k0 = i * 32;
        #pragma unroll
        for (int j = 0; j < 2; ++j) {
            const int ch = j * 256 + tid;
            const int r  = ch >> 2;
            const int cc = (ch & 3) * 8;
            cp_async16(&Bs[s][r * BPAD + cc], Bt + (size_t)(bn + r) * K + k0 + cc);
        }
    };

    float acc[4][4][4] = {};
    uint32_t rA[8];

    ldgA(0, rA); stsA(0, rA); cpB(0, 0); cp_commit();
    ldgA(1, rA);

    for (int i = 0; i < nk; ++i) {
        cp_wait<0>();
        __syncthreads();
        if (i + 1 < nk) { stsA((i + 1) & 1, rA); cpB((i + 1) & 1, i + 1); cp_commit(); }
        if (i + 2 < nk) ldgA(i + 2, rA);
        gemm_compute_stage<BPAD, 32>(As[i & 1], Bs[i & 1], acc, wm, wn, lane);
    }

    // epilogue: head-major store
    const int nb  = bm / LIN;              // batch (tile never straddles LIN)
    const int pix0 = bm & (LIN - 1);
    #pragma unroll
    for (int nt = 0; nt < 4; ++nt) {
        const int n = bn + wn + nt * 8 + t * 2;
        const int h = n >> 5, c = n & 31;
        const float bx = bias[n], by = bias[n + 1];
        __nv_bfloat16* hb = Cb + ((size_t)(nb * 8 + h) * LIN) * 32 + c;
        #pragma unroll
        for (int mt = 0; mt < 4; ++mt) {
            const int pix = pix0 + wm + mt * 16 + g;
            *(uint32_t*)&hb[(size_t)pix * 32] =
                packbf(acc[mt][nt][0] + bx, acc[mt][nt][1] + by);
            *(uint32_t*)&hb[(size_t)(pix + 8) * 32] =
                packbf(acc[mt][nt][2] + bx, acc[mt][nt][3] + by);
        }
    }
}

// ================= GEMM 2: fused q-add + off/attn split =====================
__global__ __launch_bounds__(256)
void bgemm_qa(const float* __restrict__ A, const float* __restrict__ A2,
              const __nv_bfloat16* __restrict__ Bt, const float* __restrict__ bias,
              float* __restrict__ Coff, float* __restrict__ Cattn)
{
    const int K = 256;
    __shared__ __align__(16) __nv_bfloat16 As[2][128 * BPAD];
    __shared__ __align__(16) __nv_bfloat16 Bs[2][128 * BPAD];

    const int tid  = threadIdx.x;
    const int wid  = tid >> 5;
    const int lane = tid & 31;
    const int g    = lane >> 2;
    const int t    = lane & 3;
    const int bm = blockIdx.y * 128;
    const int bn = blockIdx.x * 128;
    const int wm = (wid & 1) * 64;
    const int wn = (wid >> 1) * 32;

    const int la_r = tid >> 1;
    const int la_c = (tid & 1) * 16;
    const int r_glob = bm + la_r;
    const int pos_row = r_glob + 49152 * ((r_glob >> 14) + 1);  // pos[:, -1] remap
    const float* a_ptr  = A  + (size_t)r_glob * K + la_c;
    const float* a2_ptr = A2 + (size_t)pos_row * K + la_c;

    const int nk = K / 32;

    auto ldgA = [&](int i, uint32_t v[8]) {
        const int k0 = i * 32;
        #pragma unroll
        for (int j = 0; j < 4; ++j) {
            float4 a = *(const float4*)(a_ptr + k0 + j * 4);
            const float4 b = *(const float4*)(a2_ptr + k0 + j * 4);
            a.x += b.x; a.y += b.y; a.z += b.z; a.w += b.w;
            v[2 * j]     = packbf(a.x, a.y);
            v[2 * j + 1] = packbf(a.z, a.w);
        }
    };
    auto stsA = [&](int s, const uint32_t v[8]) {
        uint32_t* p = (uint32_t*)&As[s][la_r * BPAD + la_c];
        *(uint4*)p       = make_uint4(v[0], v[1], v[2], v[3]);
        *(uint4*)(p + 4) = make_uint4(v[4], v[5], v[6], v[7]);
    };
    auto cpB = [&](int s, int i) {
        const int k0 = i * 32;
        #pragma unroll
        for (int j = 0; j < 2; ++j) {
            const int ch = j * 256 + tid;
            const int r  = ch >> 2;
            const int cc = (ch & 3) * 8;
            cp_async16(&Bs[s][r * BPAD + cc], Bt + (size_t)(bn + r) * K + k0 + cc);
        }
    };

    float acc[4][4][4] = {};
    uint32_t rA[8];

    ldgA(0, rA); stsA(0, rA); cpB(0, 0); cp_commit();
    ldgA(1, rA);

    for (int i = 0; i < nk; ++i) {
        cp_wait<0>();
        __syncthreads();
        if (i + 1 < nk) { stsA((i + 1) & 1, rA); cpB((i + 1) & 1, i + 1); cp_commit(); }
        if (i + 2 < nk) ldgA(i + 2, rA);
        gemm_compute_stage<BPAD, 32>(As[i & 1], Bs[i & 1], acc, wm, wn, lane);
    }

    const bool is_attn = (bn >= 256);
    float* C = is_attn ? Cattn : Coff;
    const int stride = is_attn ? 128 : 256;
    const int cbase  = is_attn ? bn - 256 : bn;
    #pragma unroll
    for (int nt = 0; nt < 4; ++nt) {
        const int nn = wn + nt * 8 + t * 2;
        const float bx = bias[bn + nn], by = bias[bn + nn + 1];
        #pragma unroll
        for (int mt = 0; mt < 4; ++mt) {
            const int m = bm + wm + mt * 16 + g;
            *(float2*)&C[(size_t)m * stride + cbase + nn] =
                make_float2(acc[mt][nt][0] + bx, acc[mt][nt][1] + by);
            *(float2*)&C[(size_t)(m + 8) * stride + cbase + nn] =
                make_float2(acc[mt][nt][2] + bx, acc[mt][nt][3] + by);
        }
    }
}

// ================= GEMM 3: bf16 A, BK=64 2-stage (out-proj / FFN) ===========
// Single barrier per iter: next-stage loads issued after the barrier.
template <bool RELU, bool BF16_OUT>
__global__ __launch_bounds__(256)
void bgemm_b16a(const __nv_bfloat16* __restrict__ A,
                const __nv_bfloat16* __restrict__ Bt, const float* __restrict__ bias,
                float* __restrict__ C, __nv_bfloat16* __restrict__ Cb,
                int M, int N, int K)
{
    __shared__ __align__(16) __nv_bfloat16 As[2][128 * BPAD64];
    __shared__ __align__(16) __nv_bfloat16 Bs[2][128 * BPAD64];

    const int tid  = threadIdx.x;
    const int wid  = tid >> 5;
    const int lane = tid & 31;
    const int g    = lane >> 2;
    const int t    = lane & 3;
    const int bm = blockIdx.y * 128;
    const int bn = blockIdx.x * 128;
    const int wm = (wid & 1) * 64;
    const int wn = (wid >> 1) * 32;

    const int nk = K / 64;

    auto load_stage = [&](int s, int i) {
        const int k0 = i * 64;
        #pragma unroll
        for (int j = 0; j < 4; ++j) {
            const int ch = j * 256 + tid;          // 1024 chunks of 16B (A+B each)
            const int r  = ch >> 3;                // 0..127
            const int cc = (ch & 7) * 8;           // 0..56
            cp_async16(&As[s][r * BPAD64 + cc], A  + (size_t)(bm + r) * K + k0 + cc);
            cp_async16(&Bs[s][r * BPAD64 + cc], Bt + (size_t)(bn + r) * K + k0 + cc);
        }
    };

    float acc[4][4][4] = {};

    load_stage(0, 0); cp_commit();

    for (int i = 0; i < nk; ++i) {
        cp_wait<0>();
        __syncthreads();
        if (i + 1 < nk) { load_stage((i + 1) & 1, i + 1); cp_commit(); }
        gemm_compute_stage<BPAD64, 64>(As[i & 1], Bs[i & 1], acc, wm, wn, lane);
    }

    #pragma unroll
    for (int nt = 0; nt < 4; ++nt) {
        const int n = bn + wn + nt * 8 + t * 2;
        const float bx = bias[n], by = bias[n + 1];
        #pragma unroll
        for (int mt = 0; mt < 4; ++mt) {
            const int m = bm + wm + mt * 16 + g;
            float2 v0 = { acc[mt][nt][0] + bx, acc[mt][nt][1] + by };
            float2 v1 = { acc[mt][nt][2] + bx, acc[mt][nt][3] + by };
            if (RELU) {
                v0.x = fmaxf(v0.x, 0.f); v0.y = fmaxf(v0.y, 0.f);
                v1.x = fmaxf(v1.x, 0.f); v1.y = fmaxf(v1.y, 0.f);
            }
            if (BF16_OUT) {
                *(uint32_t*)&Cb[(size_t)m * N + n]       = packbf(v0.x, v0.y);
                *(uint32_t*)&Cb[(size_t)(m + 8) * N + n] = packbf(v1.x, v1.y);
            } else {
                *(float2*)&C[(size_t)m * N + n]       = v0;
                *(float2*)&C[(size_t)(m + 8) * N + n] = v1;
            }
        }
    }
}

// ================= single prep kernel: all transposes + bias concat =========
__device__ __forceinline__ void do_transpose_tile(
    const float* W, __nv_bfloat16* Wt, int K, int N, int tilesX, int local)
{
    __shared__ float tt[32][33];
    const int bx = (local % tilesX) * 32;   // n
    const int by = (local / tilesX) * 32;   // k
    const int x = threadIdx.x, y = threadIdx.y;
    #pragma unroll
    for (int j = 0; j < 32; j += 8)
        tt[y + j][x] = W[(size_t)(by + y + j) * N + bx + x];
    __syncthreads();
    #pragma unroll
    for (int j = 0; j < 32; j += 8)
        Wt[(size_t)(bx + y + j) * K + by + x] = __float2bfloat16_rn(tt[x][y + j]);
}

__global__ void prep_kernel(
    const float* __restrict__ W_val, const float* __restrict__ W_off,
    const float* __restrict__ W_attn, const float* __restrict__ W_out,
    const float* __restrict__ W1, const float* __restrict__ W2,
    const float* __restrict__ b_off, const float* __restrict__ b_attn,
    __nv_bfloat16* __restrict__ wvalT, __nv_bfloat16* __restrict__ wqT,
    __nv_bfloat16* __restrict__ woutT, __nv_bfloat16* __restrict__ w1T,
    __nv_bfloat16* __restrict__ w2T, float* __restrict__ bq)
{
    const int b = blockIdx.x;
    if      (b < 64)  do_transpose_tile(W_val,  wvalT,           256, 256,  8,  b);
    else if (b < 128) do_transpose_tile(W_off,  wqT,             256, 256,  8,  b - 64);
    else if (b < 160) do_transpose_tile(W_attn, wqT + 256 * 256, 256, 128,  4,  b - 128);
    else if (b < 224) do_transpose_tile(W_out,  woutT,           256, 256,  8,  b - 160);
    else if (b < 480) do_transpose_tile(W1,     w1T,             256, 1024, 32, b - 224);
    else if (b < 736) do_transpose_tile(W2,     w2T,            1024, 256,  8,  b - 480);
    else {
        const int t = threadIdx.y * 32 + threadIdx.x;   // 0..255
        bq[t] = b_off[t];
        if (t < 128) bq[256 + t] = b_attn[t];
    }
}

// ---------------- fused softmax + deformable bilinear sampling --------------
// Half-warp per (n, q, h). Lane l owns point l's scalars; gathers are paired
// LDG.64 over adjacent x-corner pixels (lane groups 0-7/8-15 own slot 0/1);
// slot weights algebraically absorb clamping + validity. One xor-8 merge.
__global__ __launch_bounds__(256)
void sample_kernel(const float* __restrict__ off, const float* __restrict__ attn,
                   const float* __restrict__ ref,
                   const __nv_bfloat16* __restrict__ value,
                   __nv_bfloat16* __restrict__ out)
{
    const int tw  = blockIdx.x * 16 + (threadIdx.x >> 4);
    const int l16 = threadIdx.x & 15;
    const int h = tw & 7;
    const int q = (tw >> 3) & (LQ - 1);
    const int n = tw >> 17;
    const size_t row = (size_t)n * LQ + q;

    // ---- lane-parallel point setup: lane l16 owns point p = l16 ----
    const int p  = l16;
    const int lv = p >> 2;

    // softmax over 16 points (width-16 butterflies)
    const float logit = attn[row * 128 + h * 16 + p];
    float mx = logit;
    #pragma unroll
    for (int o = 8; o; o >>= 1) mx = fmaxf(mx, __shfl_xor_sync(0xffffffffu, mx, o, 16));
    const float e = __expf(logit - mx);
    float ssum = e;
    #pragma unroll
    for (int o = 8; o; o >>= 1) ssum += __shfl_xor_sync(0xffffffffu, ssum, o, 16);
    const float aw = e * (1.f / ssum);

    // coordinates & weights for point p
    const float2 o2 = *(const float2*)&off[row * 256 + h * 32 + 2 * p];
    const float rx = ref[row * 8 + lv * 2];
    const float ry = ref[row * 8 + lv * 2 + 1];
    const float x = fmaf(rx, 128.f, o2.x - 0.5f);
    const float y = fmaf(ry, 128.f, o2.y - 0.5f);
    const float x0f = floorf(x), y0f = floorf(y);
    const float wx = x - x0f, wy = y - y0f;
    const int x0 = (int)x0f, y0 = (int)y0f;

    // x: corner weights + slot assignment under clamped pair base b in [0,126]
    const float sA = (x0 >= 0 && x0 < HW) ? (1.f - wx) : 0.f;      // corner x0
    const float sB = (x0 >= -1 && x0 < HW - 1) ? wx : 0.f;          // corner x0+1
    const int   b  = min(max(x0, 0), HW - 2);
    float s0, s1;
    if (x0 >= 0) { s0 = sA; s1 = sB; } else { s0 = sB; s1 = 0.f; }
    if (x0 >= HW - 1) { s0 = 0.f; s1 = sA; }

    // y: row weights + clamped rows
    const float r0 = (y0 >= 0 && y0 < HW) ? (1.f - wy) : 0.f;
    const float r1 = (y0 >= -1 && y0 < HW - 1) ? wy : 0.f;
    const int y0c = min(max(y0, 0), HW - 1);
    const int y1c = min(max(y0 + 1, 0), HW - 1);

    const float q00 = aw * r0 * s0, q01 = aw * r0 * s1;
    const float q10 = aw * r1 * s0, q11 = aw * r1 * s1;
    // packed index: word offset of pix(b) in row y0c | dy flag at bit 28
    const int ipack = ((lv * LQ + y0c * HW + b) * 16) | ((y1c - y0c) << 28);

    const uint32_t* vbw =
        (const uint32_t*)value + ((size_t)(n * 8 + h) * LIN) * 16;
    const int lw = 2 * l16;     // lane's word pair offset within the 128B pair

    float a0 = 0.f, a1 = 0.f, a2 = 0.f, a3 = 0.f;
    #pragma unroll
    for (int pp = 0; pp < 16; ++pp) {
        const int   ip  = __shfl_sync(0xffffffffu, ipack, pp, 16);
        const float b00 = __shfl_sync(0xffffffffu, q00, pp, 16);
        const float b01 = __shfl_sync(0xffffffffu, q01, pp, 16);
        const float b10 = __shfl_sync(0xffffffffu, q10, pp, 16);
        const float b11 = __shfl_sync(0xffffffffu, q11, pp, 16);
        const int ib = ip & 0x0FFFFFFF;
        const int dy = (ip >> 28) << 11;           // 0 or 2048 words
        const float wtop = (l16 < 8) ? b00 : b01;
        const float wbot = (l16 < 8) ? b10 : b11;
        const uint2 v0 = *(const uint2*)(vbw + ib + lw);
        const uint2 v1 = *(const uint2*)(vbw + ib + dy + lw);
        a0 = fmaf(bflo(v0.x), wtop, a0); a1 = fmaf(bfhi(v0.x), wtop, a1);
        a2 = fmaf(bflo(v0.y), wtop, a2); a3 = fmaf(bfhi(v0.y), wtop, a3);
        a0 = fmaf(bflo(v1.x), wbot, a0); a1 = fmaf(bfhi(v1.x), wbot, a1);
        a2 = fmaf(bflo(v1.y), wbot, a2); a3 = fmaf(bfhi(v1.y), wbot, a3);
    }
    // merge the two pixel-slot halves: channels 4j..4j+3 = lane j + lane j+8
    a0 += __shfl_xor_sync(0xffffffffu, a0, 8, 16);
    a1 += __shfl_xor_sync(0xffffffffu, a1, 8, 16);
    a2 += __shfl_xor_sync(0xffffffffu, a2, 8, 16);
    a3 += __shfl_xor_sync(0xffffffffu, a3, 8, 16);

    if (l16 < 8) {
        uint2 w = { packbf(a0, a1), packbf(a2, a3) };
        *((uint2*)(out + row * 256 + h * 32) + l16) = w;
    }
}

// ---------------- residual add + layernorm (+ optional bf16 twin) -----------
__global__ __launch_bounds__(256)
void add_ln_kernel(const float* __restrict__ a, const float* __restrict__ b,
                   const float* __restrict__ gamma, const float* __restrict__ beta,
                   float* __restrict__ out, __nv_bfloat16* __restrict__ out_b)
{
    const int row = blockIdx.x;
    const int t = threadIdx.x;
    const size_t idx = (size_t)row * 256 + t;
    const float v = a[idx] + b[idx];

    __shared__ float red[8];
    float s = v;
    #pragma unroll
    for (int o = 16; o; o >>= 1) s += __shfl_xor_sync(0xffffffffu, s, o);
    if ((t & 31) == 0) red[t >> 5] = s;
    __syncthreads();
    float mean = 0.f;
    #pragma unroll
    for (int i = 0; i < 8; ++i) mean += red[i];
    mean *= (1.f / 256.f);
    __syncthreads();

    const float d = v - mean;
    float s2 = d * d;
    #pragma unroll
    for (int o = 16; o; o >>= 1) s2 += __shfl_xor_sync(0xffffffffu, s2, o);
    if ((t & 31) == 0) red[t >> 5] = s2;
    __syncthreads();
    float var = 0.f;
    #pragma unroll
    for (int i = 0; i < 8; ++i) var += red[i];
    var *= (1.f / 256.f);

    const float r = d * rsqrtf(var + 1e-5f) * gamma[t] + beta[t];
    out[idx] = r;
    if (out_b) out_b[idx] = __float2bfloat16_rn(r);
}

// ---------------- launch -----------------------------------------------------
extern "C" void kernel_launch(void* const* d_in, const int* in_sizes, int n_in,
                              void* d_out, int out_size)
{
    (void)in_sizes; (void)n_in; (void)out_size;
    const float* cur_src = (const float*)d_in[0];
    const float* src_all = (const float*)d_in[1];
    const float* pos     = (const float*)d_in[2];
    const float* refpts  = (const float*)d_in[3];
    const float* W_off   = (const float*)d_in[6];
    const float* b_off   = (const float*)d_in[7];
    const float* W_attn  = (const float*)d_in[8];
    const float* b_attn  = (const float*)d_in[9];
    const float* W_val   = (const float*)d_in[10];
    const float* b_val   = (const float*)d_in[11];
    const float* W_out   = (const float*)d_in[12];
    const float* b_out   = (const float*)d_in[13];
    const float* gamma1  = (const float*)d_in[14];
    const float* beta1   = (const float*)d_in[15];
    const float* W1      = (const float*)d_in[16];
    const float* b1      = (const float*)d_in[17];
    const float* W2      = (const float*)d_in[18];
    const float* b2      = (const float*)d_in[19];
    const float* gamma2  = (const float*)d_in[20];
    const float* beta2   = (const float*)d_in[21];
    float* out = (float*)d_out;

    float *g_off, *g_attn, *g_src2, *g_src, *g_ffn2, *g_bq;
    __nv_bfloat16 *g_value, *g_samp, *g_srcb, *g_ffnb;
    __nv_bfloat16 *g_wvalT, *g_wqT, *g_woutT, *g_w1T, *g_w2T;
    cudaGetSymbolAddress((void**)&g_value, sc_value);
    cudaGetSymbolAddress((void**)&g_off,   sc_off);
    cudaGetSymbolAddress((void**)&g_attn,  sc_attn);
    cudaGetSymbolAddress((void**)&g_samp,  sc_samp);
    cudaGetSymbolAddress((void**)&g_src2,  sc_src2);
    cudaGetSymbolAddress((void**)&g_src,   sc_src);
    cudaGetSymbolAddress((void**)&g_srcb,  sc_srcb);
    cudaGetSymbolAddress((void**)&g_ffnb,  sc_ffnb);
    cudaGetSymbolAddress((void**)&g_ffn2,  sc_ffn2);
    cudaGetSymbolAddress((void**)&g_wvalT, sc_wvalT);
    cudaGetSymbolAddress((void**)&g_wqT,   sc_wqT);
    cudaGetSymbolAddress((void**)&g_woutT, sc_woutT);
    cudaGetSymbolAddress((void**)&g_w1T,   sc_w1T);
    cudaGetSymbolAddress((void**)&g_w2T,   sc_w2T);
    cudaGetSymbolAddress((void**)&g_bq,    sc_bq);

    // 0. one prep kernel: all weight transposes + bias concat
    prep_kernel<<<737, dim3(32, 8)>>>(W_val, W_off, W_attn, W_out, W1, W2,
                                      b_off, b_attn,
                                      g_wvalT, g_wqT, g_woutT, g_w1T, g_w2T, g_bq);

    // 1. value = bf16(src_all + pos) @ W_val + b_val -> head-major bf16
    bgemm_value<<<dim3(2, ROWS_V / 128), 256>>>(
        src_all, pos, g_wvalT, b_val, g_value, 256);

    // 2. [off | attn] = (cur_src + pos[:,-1]) @ [W_off|W_attn] + [b_off|b_attn]
    bgemm_qa<<<dim3(3, ROWS_Q / 128), 256>>>(
        cur_src, pos, g_wqT, g_bq, g_off, g_attn);

    // 3. fused softmax + deformable bilinear sampling -> bf16
    sample_kernel<<<(BATCH * LQ * N_HEADS) / 16, 256>>>(
        g_off, g_attn, refpts, g_value, g_samp);

    // 4. src2 = samp @ W_out + b_out
    bgemm_b16a<false, false><<<dim3(2, ROWS_Q / 128), 256>>>(
        g_samp, g_woutT, b_out, g_src2, nullptr, ROWS_Q, 256, 256);

    // 5. src = LN(cur_src + src2), bf16 twin for FFN1
    add_ln_kernel<<<ROWS_Q, 256>>>(cur_src, g_src2, gamma1, beta1, g_src, g_srcb);

    // 6. ffn_h = relu(src @ W1 + b1) -> bf16
    bgemm_b16a<true, true><<<dim3(D_FFN / 128, ROWS_Q / 128), 256>>>(
        g_srcb, g_w1T, b1, nullptr, g_ffnb, ROWS_Q, D_FFN, 256);

    // 7. ffn2 = ffn_h @ W2 + b2
    bgemm_b16a<false, false><<<dim3(2, ROWS_Q / 128), 256>>>(
        g_ffnb, g_w2T, b2, g_ffn2, nullptr, ROWS_Q, 256, 1024);

    // 8. out = LN(src + ffn2)
    add_ln_kernel<<<ROWS_Q, 256>>>(g_src, g_ffn2, gamma2, beta2, out, nullptr);
}

// round 16
// speedup vs baseline: 2.2922x; 1.0083x over previous
#include <cuda_runtime.h>
#include <cuda_bf16.h>
#include <cstdint>

// ---------------- problem constants ----------------
#define D_MODEL   256
#define N_HEADS   8
#define HEAD_DIM  32
#define N_LEVELS  4
#define N_POINTS  4
#define D_FFN     1024
#define HW        128
#define LQ        (HW * HW)            // 16384
#define LIN       (N_LEVELS * LQ)      // 65536
#define BATCH     2
#define ROWS_Q    (BATCH * LQ)         // 32768
#define ROWS_V    (BATCH * LIN)        // 131072

// ---------------- scratch (device globals) ---------------------------------
__device__ __align__(256) __nv_bfloat16 sc_value[ROWS_V * D_MODEL]; // head-major
__device__ __align__(256) float         sc_off  [ROWS_Q * D_MODEL];
__device__ __align__(256) float         sc_attn [ROWS_Q * 128];
__device__ __align__(256) __nv_bfloat16 sc_samp [ROWS_Q * D_MODEL];
__device__ __align__(256) float         sc_src2 [ROWS_Q * D_MODEL];
__device__ __align__(256) float         sc_src  [ROWS_Q * D_MODEL];
__device__ __align__(256) __nv_bfloat16 sc_srcb [ROWS_Q * D_MODEL];
__device__ __align__(256) __nv_bfloat16 sc_ffnb [ROWS_Q * D_FFN];
__device__ __align__(256) float         sc_ffn2 [ROWS_Q * D_MODEL];
// bf16 transposed weights Wt[n][k]
__device__ __align__(256) __nv_bfloat16 sc_wvalT[D_MODEL * D_MODEL];
__device__ __align__(256) __nv_bfloat16 sc_wqT  [384 * D_MODEL];      // off(256)+attn(128)
__device__ __align__(256) __nv_bfloat16 sc_woutT[D_MODEL * D_MODEL];
__device__ __align__(256) __nv_bfloat16 sc_w1T  [D_FFN * D_MODEL];
__device__ __align__(256) __nv_bfloat16 sc_w2T  [D_MODEL * D_FFN];
__device__ __align__(256) float         sc_bq   [384];                // b_off ++ b_attn

// ---------------- helpers --------------------------------------------------
__device__ __forceinline__ void mma_bf16(float c[4], const uint32_t a[4],
                                         const uint32_t b[2]) {
    asm volatile(
        "mma.sync.aligned.m16n8k16.row.col.f32.bf16.bf16.f32 "
        "{%0,%1,%2,%3}, {%4,%5,%6,%7}, {%8,%9}, {%0,%1,%2,%3};"
        : "+f"(c[0]), "+f"(c[1]), "+f"(c[2]), "+f"(c[3])
        : "r"(a[0]), "r"(a[1]), "r"(a[2]), "r"(a[3]), "r"(b[0]), "r"(b[1]));
}
__device__ __forceinline__ void cp_async16(void* smem, const void* gmem) {
    const uint32_t s = (uint32_t)__cvta_generic_to_shared(smem);
    asm volatile("cp.async.ca.shared.global [%0], [%1], 16;\n" :: "r"(s), "l"(gmem));
}
__device__ __forceinline__ void cp_commit() {
    asm volatile("cp.async.commit_group;\n");
}
template <int N>
__device__ __forceinline__ void cp_wait() {
    asm volatile("cp.async.wait_group %0;\n" :: "n"(N));
}
__device__ __forceinline__ uint32_t packbf(float x, float y) {
    __nv_bfloat162 p = __floats2bfloat162_rn(x, y);
    return *(uint32_t*)&p;
}
// bf16x2 word -> packed f32x2 (channels c, c+1)
__device__ __forceinline__ uint64_t bf2f32x2(uint32_t u) {
    const uint32_t lo = u << 16, hi = u & 0xffff0000u;
    uint64_t d;
    asm("mov.b64 %0, {%1,%2};" : "=l"(d) : "r"(lo), "r"(hi));
    return d;
}
__device__ __forceinline__ uint64_t bcastf2(float a) {
    uint64_t d;
    asm("mov.b64 %0, {%1,%1};" : "=l"(d) : "f"(a));
    return d;
}
__device__ __forceinline__ void fma2(uint64_t& acc, uint64_t v, uint64_t w) {
    asm("fma.rn.f32x2 %0, %1, %2, %0;" : "+l"(acc) : "l"(v), "l"(w));
}

#define BPAD 40   // bf16 row stride (BK=32 tiles): conflict-free LDSM phases
#define BPAD64 72 // bf16 row stride (BK=64 tiles): conflict-free LDSM phases

// ---- warp-tile compute on one smem stage (ldmatrix fragment loads) ---------
template <int PITCH, int BK>
__device__ __forceinline__ void gemm_compute_stage(
    const __nv_bfloat16* As, const __nv_bfloat16* Bs,
    float acc[4][4][4], int wm, int wn, int lane)
{
    const uint32_t aOff = (uint32_t)__cvta_generic_to_shared(As) +
        (uint32_t)(((wm + (lane & 15)) * PITCH + (lane >> 4) * 8) * 2);
    const uint32_t bOff = (uint32_t)__cvta_generic_to_shared(Bs) +
        (uint32_t)(((wn + (lane & 7) + (lane >> 4) * 8) * PITCH
                    + ((lane >> 3) & 1) * 8) * 2);

    #pragma unroll
    for (int ks = 0; ks < BK; ks += 16) {
        uint32_t af[4][4];
        #pragma unroll
        for (int mt = 0; mt < 4; ++mt)
            asm volatile(
                "ldmatrix.sync.aligned.m8n8.x4.shared.b16 {%0,%1,%2,%3}, [%4];"
                : "=r"(af[mt][0]), "=r"(af[mt][1]), "=r"(af[mt][2]), "=r"(af[mt][3])
                : "r"(aOff + (uint32_t)((mt * 16 * PITCH + ks) * 2)));
        uint32_t bf[4][2];
        #pragma unroll
        for (int np = 0; np < 2; ++np)
            asm volatile(
                "ldmatrix.sync.aligned.m8n8.x4.shared.b16 {%0,%1,%2,%3}, [%4];"
                : "=r"(bf[2*np][0]), "=r"(bf[2*np][1]),
                  "=r"(bf[2*np+1][0]), "=r"(bf[2*np+1][1])
                : "r"(bOff + (uint32_t)((np * 16 * PITCH + ks) * 2)));
        #pragma unroll
        for (int mt = 0; mt < 4; ++mt)
            #pragma unroll
            for (int nt = 0; nt < 4; ++nt)
                mma_bf16(acc[mt][nt], af[mt], bf[nt]);
    }
}

// ================= GEMM 1: value projection =================================
// A fp32 + A2 fp32 (same row), out = bf16 HEAD-MAJOR [n][h][pix][32].
__global__ __launch_bounds__(256)
void bgemm_value(const float* __restrict__ A, const float* __restrict__ A2,
                 const __nv_bfloat16* __restrict__ Bt, const float* __restrict__ bias,
                 __nv_bfloat16* __restrict__ Cb, int K)
{
    __shared__ __align__(16) __nv_bfloat16 As[2][128 * BPAD];
    __shared__ __align__(16) __nv_bfloat16 Bs[2][128 * BPAD];

    const int tid  = threadIdx.x;
    const int wid  = tid >> 5;
    const int lane = tid & 31;
    const int g    = lane >> 2;
    const int t    = lane & 3;
    const int bm = blockIdx.y * 128;
    const int bn = blockIdx.x * 128;
    const int wm = (wid & 1) * 64;
    const int wn = (wid >> 1) * 32;

    const int la_r = tid >> 1;
    const int la_c = (tid & 1) * 16;
    const float* a_ptr  = A  + (size_t)(bm + la_r) * K + la_c;
    const float* a2_ptr = A2 + (size_t)(bm + la_r) * K + la_c;

    const int nk = K / 32;

    auto ldgA = [&](int i, uint32_t v[8]) {
        const int k0 = i * 32;
        #pragma unroll
        for (int j = 0; j < 4; ++j) {
            float4 a = *(const float4*)(a_ptr + k0 + j * 4);
            const float4 b = *(const float4*)(a2_ptr + k0 + j * 4);
            a.x += b.x; a.y += b.y; a.z += b.z; a.w += b.w;
            v[2 * j]     = packbf(a.x, a.y);
            v[2 * j + 1] = packbf(a.z, a.w);
        }
    };
    auto stsA = [&](int s, const uint32_t v[8]) {
        uint32_t* p = (uint32_t*)&As[s][la_r * BPAD + la_c];
        *(uint4*)p       = make_uint4(v[0], v[1], v[2], v[3]);
        *(uint4*)(p + 4) = make_uint4(v[4], v[5], v[6], v[7]);
    };
    auto cpB = [&](int s, int i) {
        const int k0 = i * 32;
        #pragma unroll
        for (int j = 0; j < 2; ++j) {
            const int ch = j * 256 + tid;
            const int r  = ch >> 2;
            const int cc = (ch & 3) * 8;
            cp_async16(&Bs[s][r * BPAD + cc], Bt + (size_t)(bn + r) * K + k0 + cc);
        }
    };

    float acc[4][4][4] = {};
    uint32_t rA[8];

    ldgA(0, rA); stsA(0, rA); cpB(0, 0); cp_commit();
    ldgA(1, rA);

    for (int i = 0; i < nk; ++i) {
        cp_wait<0>();
        __syncthreads();
        if (i + 1 < nk) { stsA((i + 1) & 1, rA); cpB((i + 1) & 1, i + 1); cp_commit(); }
        if (i + 2 < nk) ldgA(i + 2, rA);
        gemm_compute_stage<BPAD, 32>(As[i & 1], Bs[i & 1], acc, wm, wn, lane);
    }

    // epilogue: head-major store
    const int nb  = bm / LIN;              // batch (tile never straddles LIN)
    const int pix0 = bm & (LIN - 1);
    #pragma unroll
    for (int nt = 0; nt < 4; ++nt) {
        const int n = bn + wn + nt * 8 + t * 2;
        const int h = n >> 5, c = n & 31;
        const float bx = bias[n], by = bias[n + 1];
        __nv_bfloat16* hb = Cb + ((size_t)(nb * 8 + h) * LIN) * 32 + c;
        #pragma unroll
        for (int mt = 0; mt < 4; ++mt) {
            const int pix = pix0 + wm + mt * 16 + g;
            *(uint32_t*)&hb[(size_t)pix * 32] =
                packbf(acc[mt][nt][0] + bx, acc[mt][nt][1] + by);
            *(uint32_t*)&hb[(size_t)(pix + 8) * 32] =
                packbf(acc[mt][nt][2] + bx, acc[mt][nt][3] + by);
        }
    }
}

// ================= GEMM 2: fused q-add + off/attn split =====================
__global__ __launch_bounds__(256)
void bgemm_qa(const float* __restrict__ A, const float* __restrict__ A2,
              const __nv_bfloat16* __restrict__ Bt, const float* __restrict__ bias,
              float* __restrict__ Coff, float* __restrict__ Cattn)
{
    const int K = 256;
    __shared__ __align__(16) __nv_bfloat16 As[2][128 * BPAD];
    __shared__ __align__(16) __nv_bfloat16 Bs[2][128 * BPAD];

    const int tid  = threadIdx.x;
    const int wid  = tid >> 5;
    const int lane = tid & 31;
    const int g    = lane >> 2;
    const int t    = lane & 3;
    const int bm = blockIdx.y * 128;
    const int bn = blockIdx.x * 128;
    const int wm = (wid & 1) * 64;
    const int wn = (wid >> 1) * 32;

    const int la_r = tid >> 1;
    const int la_c = (tid & 1) * 16;
    const int r_glob = bm + la_r;
    const int pos_row = r_glob + 49152 * ((r_glob >> 14) + 1);  // pos[:, -1] remap
    const float* a_ptr  = A  + (size_t)r_glob * K + la_c;
    const float* a2_ptr = A2 + (size_t)pos_row * K + la_c;

    const int nk = K / 32;

    auto ldgA = [&](int i, uint32_t v[8]) {
        const int k0 = i * 32;
        #pragma unroll
        for (int j = 0; j < 4; ++j) {
            float4 a = *(const float4*)(a_ptr + k0 + j * 4);
            const float4 b = *(const float4*)(a2_ptr + k0 + j * 4);
            a.x += b.x; a.y += b.y; a.z += b.z; a.w += b.w;
            v[2 * j]     = packbf(a.x, a.y);
            v[2 * j + 1] = packbf(a.z, a.w);
        }
    };
    auto stsA = [&](int s, const uint32_t v[8]) {
        uint32_t* p = (uint32_t*)&As[s][la_r * BPAD + la_c];
        *(uint4*)p       = make_uint4(v[0], v[1], v[2], v[3]);
        *(uint4*)(p + 4) = make_uint4(v[4], v[5], v[6], v[7]);
    };
    auto cpB = [&](int s, int i) {
        const int k0 = i * 32;
        #pragma unroll
        for (int j = 0; j < 2; ++j) {
            const int ch = j * 256 + tid;
            const int r  = ch >> 2;
            const int cc = (ch & 3) * 8;
            cp_async16(&Bs[s][r * BPAD + cc], Bt + (size_t)(bn + r) * K + k0 + cc);
        }
    };

    float acc[4][4][4] = {};
    uint32_t rA[8];

    ldgA(0, rA); stsA(0, rA); cpB(0, 0); cp_commit();
    ldgA(1, rA);

    for (int i = 0; i < nk; ++i) {
        cp_wait<0>();
        __syncthreads();
        if (i + 1 < nk) { stsA((i + 1) & 1, rA); cpB((i + 1) & 1, i + 1); cp_commit(); }
        if (i + 2 < nk) ldgA(i + 2, rA);
        gemm_compute_stage<BPAD, 32>(As[i & 1], Bs[i & 1], acc, wm, wn, lane);
    }

    const bool is_attn = (bn >= 256);
    float* C = is_attn ? Cattn : Coff;
    const int stride = is_attn ? 128 : 256;
    const int cbase  = is_attn ? bn - 256 : bn;
    #pragma unroll
    for (int nt = 0; nt < 4; ++nt) {
        const int nn = wn + nt * 8 + t * 2;
        const float bx = bias[bn + nn], by = bias[bn + nn + 1];
        #pragma unroll
        for (int mt = 0; mt < 4; ++mt) {
            const int m = bm + wm + mt * 16 + g;
            *(float2*)&C[(size_t)m * stride + cbase + nn] =
                make_float2(acc[mt][nt][0] + bx, acc[mt][nt][1] + by);
            *(float2*)&C[(size_t)(m + 8) * stride + cbase + nn] =
                make_float2(acc[mt][nt][2] + bx, acc[mt][nt][3] + by);
        }
    }
}

// ================= GEMM 3: bf16 A, BK=64 2-stage (out-proj / FFN) ===========
// Optional fused residual add (Res, same layout as C).
template <bool RELU, bool BF16_OUT, bool RESID>
__global__ __launch_bounds__(256)
void bgemm_b16a(const __nv_bfloat16* __restrict__ A,
                const __nv_bfloat16* __restrict__ Bt, const float* __restrict__ bias,
                const float* __restrict__ Res,
                float* __restrict__ C, __nv_bfloat16* __restrict__ Cb,
                int M, int N, int K)
{
    __shared__ __align__(16) __nv_bfloat16 As[2][128 * BPAD64];
    __shared__ __align__(16) __nv_bfloat16 Bs[2][128 * BPAD64];

    const int tid  = threadIdx.x;
    const int wid  = tid >> 5;
    const int lane = tid & 31;
    const int g    = lane >> 2;
    const int t    = lane & 3;
    const int bm = blockIdx.y * 128;
    const int bn = blockIdx.x * 128;
    const int wm = (wid & 1) * 64;
    const int wn = (wid >> 1) * 32;

    const int nk = K / 64;

    auto load_stage = [&](int s, int i) {
        const int k0 = i * 64;
        #pragma unroll
        for (int j = 0; j < 4; ++j) {
            const int ch = j * 256 + tid;
            const int r  = ch >> 3;
            const int cc = (ch & 7) * 8;
            cp_async16(&As[s][r * BPAD64 + cc], A  + (size_t)(bm + r) * K + k0 + cc);
            cp_async16(&Bs[s][r * BPAD64 + cc], Bt + (size_t)(bn + r) * K + k0 + cc);
        }
    };

    float acc[4][4][4] = {};

    load_stage(0, 0); cp_commit();

    for (int i = 0; i < nk; ++i) {
        cp_wait<0>();
        __syncthreads();
        if (i + 1 < nk) { load_stage((i + 1) & 1, i + 1); cp_commit(); }
        gemm_compute_stage<BPAD64, 64>(As[i & 1], Bs[i & 1], acc, wm, wn, lane);
    }

    #pragma unroll
    for (int nt = 0; nt < 4; ++nt) {
        const int n = bn + wn + nt * 8 + t * 2;
        const float bx = bias[n], by = bias[n + 1];
        #pragma unroll
        for (int mt = 0; mt < 4; ++mt) {
            const int m = bm + wm + mt * 16 + g;
            float2 v0 = { acc[mt][nt][0] + bx, acc[mt][nt][1] + by };
            float2 v1 = { acc[mt][nt][2] + bx, acc[mt][nt][3] + by };
            if (RESID) {
                const float2 r0 = *(const float2*)&Res[(size_t)m * N + n];
                const float2 r1 = *(const float2*)&Res[(size_t)(m + 8) * N + n];
                v0.x += r0.x; v0.y += r0.y;
                v1.x += r1.x; v1.y += r1.y;
            }
            if (RELU) {
                v0.x = fmaxf(v0.x, 0.f); v0.y = fmaxf(v0.y, 0.f);
                v1.x = fmaxf(v1.x, 0.f); v1.y = fmaxf(v1.y, 0.f);
            }
            if (BF16_OUT) {
                *(uint32_t*)&Cb[(size_t)m * N + n]       = packbf(v0.x, v0.y);
                *(uint32_t*)&Cb[(size_t)(m + 8) * N + n] = packbf(v1.x, v1.y);
            } else {
                *(float2*)&C[(size_t)m * N + n]       = v0;
                *(float2*)&C[(size_t)(m + 8) * N + n] = v1;
            }
        }
    }
}

// ================= single prep kernel: all transposes + bias concat =========
__device__ __forceinline__ void do_transpose_tile(
    const float* W, __nv_bfloat16* Wt, int K, int N, int tilesX, int local)
{
    __shared__ float tt[32][33];
    const int bx = (local % tilesX) * 32;   // n
    const int by = (local / tilesX) * 32;   // k
    const int x = threadIdx.x, y = threadIdx.y;
    #pragma unroll
    for (int j = 0; j < 32; j += 8)
        tt[y + j][x] = W[(size_t)(by + y + j) * N + bx + x];
    __syncthreads();
    #pragma unroll
    for (int j = 0; j < 32; j += 8)
        Wt[(size_t)(bx + y + j) * K + by + x] = __float2bfloat16_rn(tt[x][y + j]);
}

__global__ void prep_kernel(
    const float* __restrict__ W_val, const float* __restrict__ W_off,
    const float* __restrict__ W_attn, const float* __restrict__ W_out,
    const float* __restrict__ W1, const float* __restrict__ W2,
    const float* __restrict__ b_off, const float* __restrict__ b_attn,
    __nv_bfloat16* __restrict__ wvalT, __nv_bfloat16* __restrict__ wqT,
    __nv_bfloat16* __restrict__ woutT, __nv_bfloat16* __restrict__ w1T,
    __nv_bfloat16* __restrict__ w2T, float* __restrict__ bq)
{
    const int b = blockIdx.x;
    if      (b < 64)  do_transpose_tile(W_val,  wvalT,           256, 256,  8,  b);
    else if (b < 128) do_transpose_tile(W_off,  wqT,             256, 256,  8,  b - 64);
    else if (b < 160) do_transpose_tile(W_attn, wqT + 256 * 256, 256, 128,  4,  b - 128);
    else if (b < 224) do_transpose_tile(W_out,  woutT,           256, 256,  8,  b - 160);
    else if (b < 480) do_transpose_tile(W1,     w1T,             256, 1024, 32, b - 224);
    else if (b < 736) do_transpose_tile(W2,     w2T,            1024, 256,  8,  b - 480);
    else {
        const int t = threadIdx.y * 32 + threadIdx.x;   // 0..255
        bq[t] = b_off[t];
        if (t < 128) bq[256 + t] = b_attn[t];
    }
}

// ---------------- fused softmax + deformable bilinear sampling --------------
// Half-warp per (n, q, h); packed f32x2 FMA accumulation.
__global__ __launch_bounds__(256)
void sample_kernel(const float* __restrict__ off, const float* __restrict__ attn,
                   const float* __restrict__ ref,
                   const __nv_bfloat16* __restrict__ value,
                   __nv_bfloat16* __restrict__ out)
{
    const int tw  = blockIdx.x * 16 + (threadIdx.x >> 4);
    const int l16 = threadIdx.x & 15;
    const int h = tw & 7;
    const int q = (tw >> 3) & (LQ - 1);
    const int n = tw >> 17;
    const size_t row = (size_t)n * LQ + q;

    // ---- lane-parallel point setup: lane l16 owns point p = l16 ----
    const int p  = l16;
    const int lv = p >> 2;

    // softmax over 16 points (width-16 butterflies)
    const float logit = attn[row * 128 + h * 16 + p];
    float mx = logit;
    #pragma unroll
    for (int o = 8; o; o >>= 1) mx = fmaxf(mx, __shfl_xor_sync(0xffffffffu, mx, o, 16));
    const float e = __expf(logit - mx);
    float ssum = e;
    #pragma unroll
    for (int o = 8; o; o >>= 1) ssum += __shfl_xor_sync(0xffffffffu, ssum, o, 16);
    const float aw = e * (1.f / ssum);

    // coordinates & weights for point p
    const float2 o2 = *(const float2*)&off[row * 256 + h * 32 + 2 * p];
    const float rx = ref[row * 8 + lv * 2];
    const float ry = ref[row * 8 + lv * 2 + 1];
    const float x = fmaf(rx, 128.f, o2.x - 0.5f);
    const float y = fmaf(ry, 128.f, o2.y - 0.5f);
    const float x0f = floorf(x), y0f = floorf(y);
    const float wx = x - x0f, wy = y - y0f;
    const int x0 = (int)x0f, y0 = (int)y0f;

    // x: corner weights + slot assignment under clamped pair base b in [0,126]
    const float sA = (x0 >= 0 && x0 < HW) ? (1.f - wx) : 0.f;
    const float sB = (x0 >= -1 && x0 < HW - 1) ? wx : 0.f;
    const int   b  = min(max(x0, 0), HW - 2);
    float s0, s1;
    if (x0 >= 0) { s0 = sA; s1 = sB; } else { s0 = sB; s1 = 0.f; }
    if (x0 >= HW - 1) { s0 = 0.f; s1 = sA; }

    // y: row weights + clamped rows
    const float r0 = (y0 >= 0 && y0 < HW) ? (1.f - wy) : 0.f;
    const float r1 = (y0 >= -1 && y0 < HW - 1) ? wy : 0.f;
    const int y0c = min(max(y0, 0), HW - 1);
    const int y1c = min(max(y0 + 1, 0), HW - 1);

    const float q00 = aw * r0 * s0, q01 = aw * r0 * s1;
    const float q10 = aw * r1 * s0, q11 = aw * r1 * s1;
    const int ipack = ((lv * LQ + y0c * HW + b) * 16) | ((y1c - y0c) << 28);

    const uint32_t* vbw =
        (const uint32_t*)value + ((size_t)(n * 8 + h) * LIN) * 16;
    const int lw = 2 * l16;

    uint64_t acc01 = 0, acc23 = 0;       // packed f32x2 accumulators
    #pragma unroll
    for (int pp = 0; pp < 16; ++pp) {
        const int   ip  = __shfl_sync(0xffffffffu, ipack, pp, 16);
        const float b00 = __shfl_sync(0xffffffffu, q00, pp, 16);
        const float b01 = __shfl_sync(0xffffffffu, q01, pp, 16);
        const float b10 = __shfl_sync(0xffffffffu, q10, pp, 16);
        const float b11 = __shfl_sync(0xffffffffu, q11, pp, 16);
        const int ib = ip & 0x0FFFFFFF;
        const int dy = (ip >> 28) << 11;
        const uint64_t wt2 = bcastf2((l16 < 8) ? b00 : b01);
        const uint64_t wb2 = bcastf2((l16 < 8) ? b10 : b11);
        const uint2 v0 = *(const uint2*)(vbw + ib + lw);
        const uint2 v1 = *(const uint2*)(vbw + ib + dy + lw);
        fma2(acc01, bf2f32x2(v0.x), wt2);
        fma2(acc23, bf2f32x2(v0.y), wt2);
        fma2(acc01, bf2f32x2(v1.x), wb2);
        fma2(acc23, bf2f32x2(v1.y), wb2);
    }
    float a0, a1, a2, a3;
    asm("mov.b64 {%0,%1}, %2;" : "=f"(a0), "=f"(a1) : "l"(acc01));
    asm("mov.b64 {%0,%1}, %2;" : "=f"(a2), "=f"(a3) : "l"(acc23));

    a0 += __shfl_xor_sync(0xffffffffu, a0, 8, 16);
    a1 += __shfl_xor_sync(0xffffffffu, a1, 8, 16);
    a2 += __shfl_xor_sync(0xffffffffu, a2, 8, 16);
    a3 += __shfl_xor_sync(0xffffffffu, a3, 8, 16);

    if (l16 < 8) {
        uint2 w = { packbf(a0, a1), packbf(a2, a3) };
        *((uint2*)(out + row * 256 + h * 32) + l16) = w;
    }
}

// ---------------- pure layernorm (input already has residual) ---------------
__global__ __launch_bounds__(256)
void ln_kernel(const float* __restrict__ a,
               const float* __restrict__ gamma, const float* __restrict__ beta,
               float* __restrict__ out, __nv_bfloat16* __restrict__ out_b)
{
    const int row = blockIdx.x;
    const int t = threadIdx.x;
    const size_t idx = (size_t)row * 256 + t;
    const float v = a[idx];

    __shared__ float red[8];
    float s = v;
    #pragma unroll
    for (int o = 16; o; o >>= 1) s += __shfl_xor_sync(0xffffffffu, s, o);
    if ((t & 31) == 0) red[t >> 5] = s;
    __syncthreads();
    float mean = 0.f;
    #pragma unroll
    for (int i = 0; i < 8; ++i) mean += red[i];
    mean *= (1.f / 256.f);
    __syncthreads();

    const float d = v - mean;
    float s2 = d * d;
    #pragma unroll
    for (int o = 16; o; o >>= 1) s2 += __shfl_xor_sync(0xffffffffu, s2, o);
    if ((t & 31) == 0) red[t >> 5] = s2;
    __syncthreads();
    float var = 0.f;
    #pragma unroll
    for (int i = 0; i < 8; ++i) var += red[i];
    var *= (1.f / 256.f);

    const float r = d * rsqrtf(var + 1e-5f) * gamma[t] + beta[t];
    out[idx] = r;
    if (out_b) out_b[idx] = __float2bfloat16_rn(r);
}

// ---------------- launch -----------------------------------------------------
extern "C" void kernel_launch(void* const* d_in, const int* in_sizes, int n_in,
                              void* d_out, int out_size)
{
    (void)in_sizes; (void)n_in; (void)out_size;
    const float* cur_src = (const float*)d_in[0];
    const float* src_all = (const float*)d_in[1];
    const float* pos     = (const float*)d_in[2];
    const float* refpts  = (const float*)d_in[3];
    const float* W_off   = (const float*)d_in[6];
    const float* b_off   = (const float*)d_in[7];
    const float* W_attn  = (const float*)d_in[8];
    const float* b_attn  = (const float*)d_in[9];
    const float* W_val   = (const float*)d_in[10];
    const float* b_val   = (const float*)d_in[11];
    const float* W_out   = (const float*)d_in[12];
    const float* b_out   = (const float*)d_in[13];
    const float* gamma1  = (const float*)d_in[14];
    const float* beta1   = (const float*)d_in[15];
    const float* W1      = (const float*)d_in[16];
    const float* b1      = (const float*)d_in[17];
    const float* W2      = (const float*)d_in[18];
    const float* b2      = (const float*)d_in[19];
    const float* gamma2  = (const float*)d_in[20];
    const float* beta2   = (const float*)d_in[21];
    float* out = (float*)d_out;

    float *g_off, *g_attn, *g_src2, *g_src, *g_ffn2, *g_bq;
    __nv_bfloat16 *g_value, *g_samp, *g_srcb, *g_ffnb;
    __nv_bfloat16 *g_wvalT, *g_wqT, *g_woutT, *g_w1T, *g_w2T;
    cudaGetSymbolAddress((void**)&g_value, sc_value);
    cudaGetSymbolAddress((void**)&g_off,   sc_off);
    cudaGetSymbolAddress((void**)&g_attn,  sc_attn);
    cudaGetSymbolAddress((void**)&g_samp,  sc_samp);
    cudaGetSymbolAddress((void**)&g_src2,  sc_src2);
    cudaGetSymbolAddress((void**)&g_src,   sc_src);
    cudaGetSymbolAddress((void**)&g_srcb,  sc_srcb);
    cudaGetSymbolAddress((void**)&g_ffnb,  sc_ffnb);
    cudaGetSymbolAddress((void**)&g_ffn2,  sc_ffn2);
    cudaGetSymbolAddress((void**)&g_wvalT, sc_wvalT);
    cudaGetSymbolAddress((void**)&g_wqT,   sc_wqT);
    cudaGetSymbolAddress((void**)&g_woutT, sc_woutT);
    cudaGetSymbolAddress((void**)&g_w1T,   sc_w1T);
    cudaGetSymbolAddress((void**)&g_w2T,   sc_w2T);
    cudaGetSymbolAddress((void**)&g_bq,    sc_bq);

    // 0. one prep kernel: all weight transposes + bias concat
    prep_kernel<<<737, dim3(32, 8)>>>(W_val, W_off, W_attn, W_out, W1, W2,
                                      b_off, b_attn,
                                      g_wvalT, g_wqT, g_woutT, g_w1T, g_w2T, g_bq);

    // 1. value = bf16(src_all + pos) @ W_val + b_val -> head-major bf16
    bgemm_value<<<dim3(2, ROWS_V / 128), 256>>>(
        src_all, pos, g_wvalT, b_val, g_value, 256);

    // 2. [off | attn] = (cur_src + pos[:,-1]) @ [W_off|W_attn] + [b_off|b_attn]
    bgemm_qa<<<dim3(3, ROWS_Q / 128), 256>>>(
        cur_src, pos, g_wqT, g_bq, g_off, g_attn);

    // 3. fused softmax + deformable bilinear sampling -> bf16
    sample_kernel<<<(BATCH * LQ * N_HEADS) / 16, 256>>>(
        g_off, g_attn, refpts, g_value, g_samp);

    // 4. src2sum = samp @ W_out + b_out + cur_src  (residual fused)
    bgemm_b16a<false, false, true><<<dim3(2, ROWS_Q / 128), 256>>>(
        g_samp, g_woutT, b_out, cur_src, g_src2, nullptr, ROWS_Q, 256, 256);

    // 5. src = LN(src2sum), bf16 twin for FFN1
    ln_kernel<<<ROWS_Q, 256>>>(g_src2, gamma1, beta1, g_src, g_srcb);

    // 6. ffn_h = relu(src @ W1 + b1) -> bf16
    bgemm_b16a<true, true, false><<<dim3(D_FFN / 128, ROWS_Q / 128), 256>>>(
        g_srcb, g_w1T, b1, nullptr, nullptr, g_ffnb, ROWS_Q, D_FFN, 256);

    // 7. ffn2sum = ffn_h @ W2 + b2 + src  (residual fused)
    bgemm_b16a<false, false, true><<<dim3(2, ROWS_Q / 128), 256>>>(
        g_ffnb, g_w2T, b2, g_src, g_ffn2, nullptr, ROWS_Q, 256, 1024);

    // 8. out = LN(ffn2sum)
    ln_kernel<<<ROWS_Q, 256>>>(g_ffn2, gamma2, beta2, out, nullptr);
}